// round 1
// baseline (speedup 1.0000x reference)
#include <cuda_runtime.h>
#include <math.h>

#define Bb 4
#define Ss 1024
#define Dd 1024
#define Hh 16
#define DKk 64
#define BHh (Bb*Hh)   /* 64 */
#define Mm (Bb*Ss)    /* 4096 */

// Scratch (device globals: allocation-free per harness rules)
__device__ float g_Wc[3][Dd*Dd];        // folded weights (12 MB)
__device__ float g_bc[3][Dd];           // folded biases
__device__ float g_QKV[3][BHh*Ss*DKk];  // per-head Q,K,V after relu (48 MB)

// ---------------------------------------------------------------------------
// Fold: Wc[t][(h*64+o)*1024 + j] = sum_i Wf[o,i] * Wbig[h*64+i, j]
// grid (16 j-tiles, 16 heads, 3 tensors), 256 threads
// ---------------------------------------------------------------------------
__global__ void fold_kernel(const float* __restrict__ Wq, const float* __restrict__ Wqf,
                            const float* __restrict__ Wk, const float* __restrict__ Wkf,
                            const float* __restrict__ Wv, const float* __restrict__ Wvf) {
    int t = blockIdx.z, h = blockIdx.y, j0 = blockIdx.x * 64;
    const float* Wbig = (t == 0) ? Wq : (t == 1) ? Wk : Wv;
    const float* Wf   = (t == 0) ? Wqf : (t == 1) ? Wkf : Wvf;

    __shared__ float fs[64][65];  // Wf[o][i]
    __shared__ float bs[64][65];  // Wbig[i][j]

    int tid = threadIdx.x;
    for (int idx = tid; idx < 64 * 16; idx += 256) {
        int r = idx >> 4, c4 = (idx & 15) * 4;
        float4 fv = *(const float4*)(Wf + r * 64 + c4);
        fs[r][c4] = fv.x; fs[r][c4 + 1] = fv.y; fs[r][c4 + 2] = fv.z; fs[r][c4 + 3] = fv.w;
        float4 bv = *(const float4*)(Wbig + (h * 64 + r) * Dd + j0 + c4);
        bs[r][c4] = bv.x; bs[r][c4 + 1] = bv.y; bs[r][c4 + 2] = bv.z; bs[r][c4 + 3] = bv.w;
    }
    __syncthreads();

    int ty = tid >> 4, tx = tid & 15;
    float acc[4][4] = {};
#pragma unroll 8
    for (int i = 0; i < 64; i++) {
        float a[4], b[4];
#pragma unroll
        for (int u = 0; u < 4; u++) { a[u] = fs[ty * 4 + u][i]; b[u] = bs[i][tx * 4 + u]; }
#pragma unroll
        for (int u = 0; u < 4; u++)
#pragma unroll
            for (int w = 0; w < 4; w++) acc[u][w] += a[u] * b[w];
    }
    float* dst = g_Wc[t];
#pragma unroll
    for (int u = 0; u < 4; u++)
#pragma unroll
        for (int w = 0; w < 4; w++)
            dst[(h * 64 + ty * 4 + u) * Dd + j0 + tx * 4 + w] = acc[u][w];
}

// bc[t][h*64+o] = sum_i Wf[o,i]*b1[h*64+i] + b2[o]
__global__ void bfold_kernel(const float* __restrict__ bq, const float* __restrict__ bqf,
                             const float* __restrict__ bk, const float* __restrict__ bkf,
                             const float* __restrict__ bv, const float* __restrict__ bvf,
                             const float* __restrict__ Wqf, const float* __restrict__ Wkf,
                             const float* __restrict__ Wvf) {
    int t = blockIdx.x, n = threadIdx.x;
    const float* b1 = (t == 0) ? bq : (t == 1) ? bk : bv;
    const float* b2 = (t == 0) ? bqf : (t == 1) ? bkf : bvf;
    const float* Wf = (t == 0) ? Wqf : (t == 1) ? Wkf : Wvf;
    int h = n >> 6, o = n & 63;
    float s = b2[o];
    for (int i = 0; i < 64; i++) s += Wf[o * 64 + i] * b1[h * 64 + i];
    g_bc[t][n] = s;
}

// ---------------------------------------------------------------------------
// Y = relu(X @ Wc^T + bc), written in per-head layout g_QKV[t][bh][s][dk]
// BM=128, BN=64 (one head per block x), BK=16. 256 threads, 8x4 per thread.
// grid (16, 32, 3)
// ---------------------------------------------------------------------------
__global__ void gemm_relu_kernel(const float* __restrict__ q, const float* __restrict__ k,
                                 const float* __restrict__ v) {
    int t = blockIdx.z;
    const float* X = (t == 0) ? q : (t == 1) ? k : v;
    const float* W = g_Wc[t];
    const float* bias = g_bc[t];
    float* Y = g_QKV[t];
    int bx = blockIdx.x;   // head index (N tile of 64)
    int by = blockIdx.y;   // M tile of 128

    __shared__ float Xs[16][128 + 4];
    __shared__ float Ws[16][64 + 4];

    int tid = threadIdx.x;
    int mg = tid >> 4, ng = tid & 15;
    float acc[8][4] = {};

    for (int k0 = 0; k0 < Dd; k0 += 16) {
#pragma unroll
        for (int it = 0; it < 2; it++) {
            int idx = tid + it * 256;           // 0..511
            int r = idx >> 2, c4 = (idx & 3) * 4;
            float4 xv = *(const float4*)(X + (by * 128 + r) * Dd + k0 + c4);
            Xs[c4][r] = xv.x; Xs[c4 + 1][r] = xv.y; Xs[c4 + 2][r] = xv.z; Xs[c4 + 3][r] = xv.w;
        }
        {
            int r = tid >> 2, c4 = (tid & 3) * 4;
            float4 wv = *(const float4*)(W + (bx * 64 + r) * Dd + k0 + c4);
            Ws[c4][r] = wv.x; Ws[c4 + 1][r] = wv.y; Ws[c4 + 2][r] = wv.z; Ws[c4 + 3][r] = wv.w;
        }
        __syncthreads();
#pragma unroll
        for (int kk = 0; kk < 16; kk++) {
            const float4* xp = (const float4*)&Xs[kk][mg * 8];
            float4 a0 = xp[0], a1 = xp[1];
            const float4* wp = (const float4*)&Ws[kk][ng * 4];
            float4 b4 = wp[0];
            float a[8] = {a0.x, a0.y, a0.z, a0.w, a1.x, a1.y, a1.z, a1.w};
            float b[4] = {b4.x, b4.y, b4.z, b4.w};
#pragma unroll
            for (int i = 0; i < 8; i++)
#pragma unroll
                for (int j = 0; j < 4; j++) acc[i][j] += a[i] * b[j];
        }
        __syncthreads();
    }

#pragma unroll
    for (int i = 0; i < 8; i++) {
        int m = by * 128 + mg * 8 + i;
        int b_ = m >> 10, s = m & 1023;
        float* dst = Y + (((size_t)(b_ * Hh + bx)) * Ss + s) * DKk + ng * 4;
        float4 o4;
        o4.x = fmaxf(acc[i][0] + bias[bx * 64 + ng * 4 + 0], 0.f);
        o4.y = fmaxf(acc[i][1] + bias[bx * 64 + ng * 4 + 1], 0.f);
        o4.z = fmaxf(acc[i][2] + bias[bx * 64 + ng * 4 + 2], 0.f);
        o4.w = fmaxf(acc[i][3] + bias[bx * 64 + ng * 4 + 3], 0.f);
        *(float4*)dst = o4;
    }
}

// ---------------------------------------------------------------------------
// Flash attention + fused per-head output projection (Wo, bo) + transpose-out.
// grid (16 q-tiles, 64 batch-heads), 256 threads (16x16, 4x4 micro-tile)
// dynamic smem: Qs,Ks,Vs,Ps each [64][65]
// ---------------------------------------------------------------------------
__global__ void attn_kernel(const int* __restrict__ mask, const float* __restrict__ Wo,
                            const float* __restrict__ bo, float* __restrict__ out) {
    extern __shared__ float sm[];
    float (*Qs)[65] = (float(*)[65])sm;
    float (*Ks)[65] = Qs + 64;
    float (*Vs)[65] = Ks + 64;
    float (*Ps)[65] = Vs + 64;
    __shared__ int ms[64];

    int bh = blockIdx.y;
    int q0 = blockIdx.x * 64;
    const float* Q = g_QKV[0] + ((size_t)bh * Ss + q0) * DKk;
    const float* K = g_QKV[1] + (size_t)bh * Ss * DKk;
    const float* V = g_QKV[2] + (size_t)bh * Ss * DKk;

    int tid = threadIdx.x, ty = tid >> 4, tx = tid & 15;

    // Load Q tile
    for (int idx = tid; idx < 64 * 16; idx += 256) {
        int r = idx >> 4, c4 = (idx & 15) * 4;
        float4 qv = *(const float4*)(Q + r * DKk + c4);
        Qs[r][c4] = qv.x; Qs[r][c4 + 1] = qv.y; Qs[r][c4 + 2] = qv.z; Qs[r][c4 + 3] = qv.w;
    }

    float m_i[4], l_i[4], acc[4][4];
#pragma unroll
    for (int i = 0; i < 4; i++) {
        m_i[i] = -1e30f; l_i[i] = 0.f;
#pragma unroll
        for (int j = 0; j < 4; j++) acc[i][j] = 0.f;
    }

    const float scale = 0.125f;  // 1/sqrt(64)

    for (int kt = 0; kt < 16; kt++) {
        __syncthreads();  // Q ready (first iter) / prev PV done before overwrite
        for (int idx = tid; idx < 64 * 16; idx += 256) {
            int r = idx >> 4, c4 = (idx & 15) * 4;
            float4 kv = *(const float4*)(K + (kt * 64 + r) * DKk + c4);
            Ks[r][c4] = kv.x; Ks[r][c4 + 1] = kv.y; Ks[r][c4 + 2] = kv.z; Ks[r][c4 + 3] = kv.w;
            float4 vv = *(const float4*)(V + (kt * 64 + r) * DKk + c4);
            Vs[r][c4] = vv.x; Vs[r][c4 + 1] = vv.y; Vs[r][c4 + 2] = vv.z; Vs[r][c4 + 3] = vv.w;
        }
        if (tid < 64) ms[tid] = mask[bh * Ss + kt * 64 + tid];
        __syncthreads();

        // scores: s[i][j] = (Q[r] . K[c]) * scale, masked
        float s[4][4] = {};
#pragma unroll 8
        for (int d = 0; d < 64; d++) {
            float a[4], b[4];
#pragma unroll
            for (int i = 0; i < 4; i++) a[i] = Qs[ty * 4 + i][d];
#pragma unroll
            for (int j = 0; j < 4; j++) b[j] = Ks[tx * 4 + j][d];
#pragma unroll
            for (int i = 0; i < 4; i++)
#pragma unroll
                for (int j = 0; j < 4; j++) s[i][j] += a[i] * b[j];
        }
#pragma unroll
        for (int j = 0; j < 4; j++) {
            bool msk = (ms[tx * 4 + j] == 0);
#pragma unroll
            for (int i = 0; i < 4; i++) {
                s[i][j] *= scale;
                if (msk) s[i][j] = -10000.0f;
            }
        }

        // online softmax per row (rows owned by ty-group; reduce over tx lanes)
        float p[4][4], rsum[4];
#pragma unroll
        for (int i = 0; i < 4; i++) {
            float rm = fmaxf(fmaxf(s[i][0], s[i][1]), fmaxf(s[i][2], s[i][3]));
#pragma unroll
            for (int off = 1; off < 16; off <<= 1)
                rm = fmaxf(rm, __shfl_xor_sync(0xffffffffu, rm, off));
            float mn = fmaxf(m_i[i], rm);
            float sc = __expf(m_i[i] - mn);
            m_i[i] = mn;
            float rs = 0.f;
#pragma unroll
            for (int j = 0; j < 4; j++) { p[i][j] = __expf(s[i][j] - mn); rs += p[i][j]; }
#pragma unroll
            for (int off = 1; off < 16; off <<= 1)
                rs += __shfl_xor_sync(0xffffffffu, rs, off);
            rsum[i] = rs;
            l_i[i] = l_i[i] * sc + rs;
#pragma unroll
            for (int j = 0; j < 4; j++) acc[i][j] *= sc;
        }
        (void)rsum;

        // publish P
#pragma unroll
        for (int i = 0; i < 4; i++)
#pragma unroll
            for (int j = 0; j < 4; j++) Ps[ty * 4 + i][tx * 4 + j] = p[i][j];
        __syncthreads();

        // O += P @ V   (rows r=ty*4+i, d-cols = tx*4+j)
#pragma unroll 8
        for (int kk = 0; kk < 64; kk++) {
            float a[4], b[4];
#pragma unroll
            for (int i = 0; i < 4; i++) a[i] = Ps[ty * 4 + i][kk];
#pragma unroll
            for (int j = 0; j < 4; j++) b[j] = Vs[kk][tx * 4 + j];
#pragma unroll
            for (int i = 0; i < 4; i++)
#pragma unroll
                for (int j = 0; j < 4; j++) acc[i][j] += a[i] * b[j];
        }
    }

    __syncthreads();
    // normalize and stage O into Ps
#pragma unroll
    for (int i = 0; i < 4; i++) {
        float inv = 1.0f / l_i[i];
#pragma unroll
        for (int j = 0; j < 4; j++) Ps[ty * 4 + i][tx * 4 + j] = acc[i][j] * inv;
    }
    // stage Wo into Ks: Ks[o][i] = Wo[o*64+i]
    for (int idx = tid; idx < 64 * 16; idx += 256) {
        int r = idx >> 4, c4 = (idx & 15) * 4;
        float4 wv = *(const float4*)(Wo + r * 64 + c4);
        Ks[r][c4] = wv.x; Ks[r][c4 + 1] = wv.y; Ks[r][c4 + 2] = wv.z; Ks[r][c4 + 3] = wv.w;
    }
    __syncthreads();

    // out2[r][o] = sum_d O[r][d] * Wo[o][d] + bo[o]
    float o2[4][4];
#pragma unroll
    for (int i = 0; i < 4; i++)
#pragma unroll
        for (int j = 0; j < 4; j++) o2[i][j] = bo[tx * 4 + j];
#pragma unroll 8
    for (int d = 0; d < 64; d++) {
        float a[4], b[4];
#pragma unroll
        for (int i = 0; i < 4; i++) a[i] = Ps[ty * 4 + i][d];
#pragma unroll
        for (int j = 0; j < 4; j++) b[j] = Ks[tx * 4 + j][d];
#pragma unroll
        for (int i = 0; i < 4; i++)
#pragma unroll
            for (int j = 0; j < 4; j++) o2[i][j] += a[i] * b[j];
    }

    // write out[b][s][h*64+o]
    int b_ = bh / Hh, h = bh % Hh;
#pragma unroll
    for (int i = 0; i < 4; i++) {
        int s = q0 + ty * 4 + i;
        float* dst = out + ((size_t)(b_ * Ss + s)) * Dd + h * 64 + tx * 4;
        float4 w4 = {o2[i][0], o2[i][1], o2[i][2], o2[i][3]};
        *(float4*)dst = w4;
    }
}

// ---------------------------------------------------------------------------
extern "C" void kernel_launch(void* const* d_in, const int* in_sizes, int n_in,
                              void* d_out, int out_size) {
    const float* q   = (const float*)d_in[0];
    const float* k   = (const float*)d_in[1];
    const float* v   = (const float*)d_in[2];
    const int*   msk = (const int*)d_in[3];
    const float* Wq  = (const float*)d_in[4];
    const float* bq  = (const float*)d_in[5];
    const float* Wk  = (const float*)d_in[6];
    const float* bk  = (const float*)d_in[7];
    const float* Wv  = (const float*)d_in[8];
    const float* bv  = (const float*)d_in[9];
    const float* Wqf = (const float*)d_in[10];
    const float* bqf = (const float*)d_in[11];
    const float* Wkf = (const float*)d_in[12];
    const float* bkf = (const float*)d_in[13];
    const float* Wvf = (const float*)d_in[14];
    const float* bvf = (const float*)d_in[15];
    const float* Wo  = (const float*)d_in[16];
    const float* bo  = (const float*)d_in[17];
    float* out = (float*)d_out;

    fold_kernel<<<dim3(16, 16, 3), 256>>>(Wq, Wqf, Wk, Wkf, Wv, Wvf);
    bfold_kernel<<<3, 1024>>>(bq, bqf, bk, bkf, bv, bvf, Wqf, Wkf, Wvf);
    gemm_relu_kernel<<<dim3(16, 32, 3), 256>>>(q, k, v);

    int smem = 4 * 64 * 65 * sizeof(float);
    static int attn_cfg = 0;
    if (!attn_cfg) {  // attribute set is idempotent & not a stream op
        cudaFuncSetAttribute(attn_kernel, cudaFuncAttributeMaxDynamicSharedMemorySize, smem);
        attn_cfg = 1;
    }
    attn_kernel<<<dim3(16, 64), 256, smem>>>(msk, Wo, bo, out);
}

// round 2
// speedup vs baseline: 2.8107x; 2.8107x over previous
#include <cuda_runtime.h>
#include <math.h>
#include <stdint.h>

#define Bb 4
#define Ss 1024
#define Dd 1024
#define Hh 16
#define DKk 64

// Scratch (device globals: allocation-free per harness rules)
__device__ float g_Wc[3][Dd*Dd];        // folded weights
__device__ float g_bc[3][Dd];           // folded biases
__device__ float g_QKV[3][64*Ss*DKk];   // per-head Q,K,V after relu (tf32-rounded fp32)

// ---------------------------------------------------------------------------
// helpers
// ---------------------------------------------------------------------------
__device__ __forceinline__ uint32_t tf32r(float x) {
    uint32_t u; asm("cvt.rna.tf32.f32 %0, %1;" : "=r"(u) : "f"(x)); return u;
}
__device__ __forceinline__ void mma8(float (&d)[4], uint32_t a0, uint32_t a1, uint32_t a2,
                                     uint32_t a3, uint32_t b0, uint32_t b1) {
    asm volatile(
        "mma.sync.aligned.m16n8k8.row.col.f32.tf32.tf32.f32 "
        "{%0,%1,%2,%3},{%4,%5,%6,%7},{%8,%9},{%0,%1,%2,%3};"
        : "+f"(d[0]), "+f"(d[1]), "+f"(d[2]), "+f"(d[3])
        : "r"(a0), "r"(a1), "r"(a2), "r"(a3), "r"(b0), "r"(b1));
}
__device__ __forceinline__ void cp16(void* s, const void* g) {
    uint32_t sa = (uint32_t)__cvta_generic_to_shared(s);
    asm volatile("cp.async.cg.shared.global [%0], [%1], 16;" :: "r"(sa), "l"(g));
}

// ---------------------------------------------------------------------------
// Fold: Wc[t][(h*64+o)*1024 + j] = sum_i Wf[o,i] * Wbig[h*64+i, j]
// ---------------------------------------------------------------------------
__global__ void fold_kernel(const float* __restrict__ Wq, const float* __restrict__ Wqf,
                            const float* __restrict__ Wk, const float* __restrict__ Wkf,
                            const float* __restrict__ Wv, const float* __restrict__ Wvf) {
    int t = blockIdx.z, h = blockIdx.y, j0 = blockIdx.x * 64;
    const float* Wbig = (t == 0) ? Wq : (t == 1) ? Wk : Wv;
    const float* Wf   = (t == 0) ? Wqf : (t == 1) ? Wkf : Wvf;

    __shared__ float fs[64][65];
    __shared__ float bs[64][65];

    int tid = threadIdx.x;
    for (int idx = tid; idx < 64 * 16; idx += 256) {
        int r = idx >> 4, c4 = (idx & 15) * 4;
        float4 fv = *(const float4*)(Wf + r * 64 + c4);
        fs[r][c4] = fv.x; fs[r][c4 + 1] = fv.y; fs[r][c4 + 2] = fv.z; fs[r][c4 + 3] = fv.w;
        float4 bv = *(const float4*)(Wbig + (h * 64 + r) * Dd + j0 + c4);
        bs[r][c4] = bv.x; bs[r][c4 + 1] = bv.y; bs[r][c4 + 2] = bv.z; bs[r][c4 + 3] = bv.w;
    }
    __syncthreads();

    int ty = tid >> 4, tx = tid & 15;
    float acc[4][4] = {};
#pragma unroll 8
    for (int i = 0; i < 64; i++) {
        float a[4], b[4];
#pragma unroll
        for (int u = 0; u < 4; u++) { a[u] = fs[ty * 4 + u][i]; b[u] = bs[i][tx * 4 + u]; }
#pragma unroll
        for (int u = 0; u < 4; u++)
#pragma unroll
            for (int w = 0; w < 4; w++) acc[u][w] += a[u] * b[w];
    }
    float* dst = g_Wc[t];
#pragma unroll
    for (int u = 0; u < 4; u++)
#pragma unroll
        for (int w = 0; w < 4; w++)
            dst[(h * 64 + ty * 4 + u) * Dd + j0 + tx * 4 + w] = acc[u][w];
}

__global__ void bfold_kernel(const float* __restrict__ bq, const float* __restrict__ bqf,
                             const float* __restrict__ bk, const float* __restrict__ bkf,
                             const float* __restrict__ bv, const float* __restrict__ bvf,
                             const float* __restrict__ Wqf, const float* __restrict__ Wkf,
                             const float* __restrict__ Wvf) {
    int t = blockIdx.x, n = threadIdx.x;
    const float* b1 = (t == 0) ? bq : (t == 1) ? bk : bv;
    const float* b2 = (t == 0) ? bqf : (t == 1) ? bkf : bvf;
    const float* Wf = (t == 0) ? Wqf : (t == 1) ? Wkf : Wvf;
    int h = n >> 6, o = n & 63;
    float s = b2[o];
    for (int i = 0; i < 64; i++) s += Wf[o * 64 + i] * b1[h * 64 + i];
    g_bc[t][n] = s;
}

// ---------------------------------------------------------------------------
// Projection GEMM via tf32 mma: Y = relu(X @ Wc^T + bc), per-head layout out.
// BM=128, BN=64(head), BK=32. 256 thr = 8 warps (4 M x 2 N), warp tile 32x32.
// cp.async double buffered. smem: Xs[2][128][36] + Ws[2][64][36] = 55296 B
// ---------------------------------------------------------------------------
#define GST 36
__global__ __launch_bounds__(256) void gemm_tc(const float* __restrict__ q,
                                               const float* __restrict__ k,
                                               const float* __restrict__ v) {
    extern __shared__ float sm[];
    float* Xs = sm;                  // [2][128][GST]
    float* Ws = sm + 2 * 128 * GST;  // [2][64][GST]

    int t = blockIdx.z;
    const float* X = (t == 0) ? q : (t == 1) ? k : v;
    const float* W = g_Wc[t];
    const float* bias = g_bc[t];
    float* Y = g_QKV[t];
    int head = blockIdx.x, m0 = blockIdx.y * 128;

    int tid = threadIdx.x;
    int w = tid >> 5, lane = tid & 31, g = lane >> 2, tg = lane & 3;
    int wm = w & 3, wn = w >> 2;

    float acc[2][4][4] = {};

#define LOAD_TILE(I, BUF)                                                              \
    do {                                                                               \
        int k0_ = (I) * 32;                                                            \
        _Pragma("unroll")                                                              \
        for (int j = 0; j < 4; j++) {                                                  \
            int idx = tid + j * 256; int r = idx >> 3, c = (idx & 7) * 4;              \
            cp16(&Xs[((BUF) * 128 + r) * GST + c],                                     \
                 X + (size_t)(m0 + r) * Dd + k0_ + c);                                 \
        }                                                                              \
        _Pragma("unroll")                                                              \
        for (int j = 0; j < 2; j++) {                                                  \
            int idx = tid + j * 256; int r = idx >> 3, c = (idx & 7) * 4;              \
            cp16(&Ws[((BUF) * 64 + r) * GST + c],                                      \
                 W + (size_t)(head * 64 + r) * Dd + k0_ + c);                          \
        }                                                                              \
        asm volatile("cp.async.commit_group;");                                       \
    } while (0)

    LOAD_TILE(0, 0);
    for (int i = 0; i < 32; i++) {
        int buf = i & 1;
        if (i < 31) {
            LOAD_TILE(i + 1, buf ^ 1);
            asm volatile("cp.async.wait_group 1;");
        } else {
            asm volatile("cp.async.wait_group 0;");
        }
        __syncthreads();
        float* Xb = &Xs[buf * 128 * GST];
        float* Wb = &Ws[buf * 64 * GST];
#pragma unroll
        for (int ks = 0; ks < 4; ks++) {
            int kk = ks * 8;
            uint32_t a[2][4];
#pragma unroll
            for (int fm = 0; fm < 2; fm++) {
                int r = wm * 32 + fm * 16 + g;
                a[fm][0] = tf32r(Xb[r * GST + kk + tg]);
                a[fm][1] = tf32r(Xb[(r + 8) * GST + kk + tg]);
                a[fm][2] = tf32r(Xb[r * GST + kk + tg + 4]);
                a[fm][3] = tf32r(Xb[(r + 8) * GST + kk + tg + 4]);
            }
#pragma unroll
            for (int fn = 0; fn < 4; fn++) {
                int n = wn * 32 + fn * 8 + g;
                uint32_t b0 = tf32r(Wb[n * GST + kk + tg]);
                uint32_t b1 = tf32r(Wb[n * GST + kk + tg + 4]);
                mma8(acc[0][fn], a[0][0], a[0][1], a[0][2], a[0][3], b0, b1);
                mma8(acc[1][fn], a[1][0], a[1][1], a[1][2], a[1][3], b0, b1);
            }
        }
        __syncthreads();
    }
#undef LOAD_TILE

    // epilogue: bias + relu + tf32 round + per-head layout store
#pragma unroll
    for (int fm = 0; fm < 2; fm++) {
#pragma unroll
        for (int fn = 0; fn < 4; fn++) {
            int col = wn * 32 + fn * 8 + 2 * tg;
            float b0 = bias[head * 64 + col], b1 = bias[head * 64 + col + 1];
            int r0 = m0 + wm * 32 + fm * 16 + g;
            int r1 = r0 + 8;
            float2 v0, v1;
            v0.x = __uint_as_float(tf32r(fmaxf(acc[fm][fn][0] + b0, 0.f)));
            v0.y = __uint_as_float(tf32r(fmaxf(acc[fm][fn][1] + b1, 0.f)));
            v1.x = __uint_as_float(tf32r(fmaxf(acc[fm][fn][2] + b0, 0.f)));
            v1.y = __uint_as_float(tf32r(fmaxf(acc[fm][fn][3] + b1, 0.f)));
            {
                int b_ = r0 >> 10, s = r0 & 1023;
                *(float2*)(Y + (((size_t)(b_ * Hh + head)) * Ss + s) * DKk + col) = v0;
            }
            {
                int b_ = r1 >> 10, s = r1 & 1023;
                *(float2*)(Y + (((size_t)(b_ * Hh + head)) * Ss + s) * DKk + col) = v1;
            }
        }
    }
}

// ---------------------------------------------------------------------------
// Flash attention via tf32 mma + fused Wo/bo epilogue.
// grid (16 q-tiles, 64 bh), 128 threads = 4 warps; warp owns 16 q-rows.
// smem: Qs[64][68] Ks[64][68] Vs[64][72] Ps[4][16][72] + ms[64] = 71936 B
// ---------------------------------------------------------------------------
__global__ __launch_bounds__(128) void attn_tc(const int* __restrict__ mask,
                                               const float* __restrict__ Wo,
                                               const float* __restrict__ bo,
                                               float* __restrict__ out) {
    extern __shared__ float sm[];
    float* Qs = sm;                    // [64][68]
    float* Ks = Qs + 64 * 68;          // [64][68]
    float* Vs = Ks + 64 * 68;          // [64][72]
    float* Ps = Vs + 64 * 72;          // [4][16][72]
    int*   ms = (int*)(Ps + 4 * 16 * 72);

    int bh = blockIdx.y, q0 = blockIdx.x * 64;
    const float* Q = g_QKV[0] + ((size_t)bh * Ss + q0) * DKk;
    const float* K = g_QKV[1] + (size_t)bh * Ss * DKk;
    const float* V = g_QKV[2] + (size_t)bh * Ss * DKk;

    int tid = threadIdx.x, w = tid >> 5, lane = tid & 31, g = lane >> 2, tg = lane & 3;

    // load Q tile (values already tf32-rounded at projection epilogue)
#pragma unroll
    for (int j = 0; j < 8; j++) {
        int idx = tid + j * 128; int r = idx >> 4, c = (idx & 15) * 4;
        *(float4*)&Qs[r * 68 + c] = *(const float4*)(Q + (size_t)r * DKk + c);
    }
    __syncthreads();

    // cache Q A-fragments in registers
    uint32_t qa[8][4];
#pragma unroll
    for (int ks = 0; ks < 8; ks++) {
        int r = w * 16 + g;
        qa[ks][0] = __float_as_uint(Qs[r * 68 + ks * 8 + tg]);
        qa[ks][1] = __float_as_uint(Qs[(r + 8) * 68 + ks * 8 + tg]);
        qa[ks][2] = __float_as_uint(Qs[r * 68 + ks * 8 + tg + 4]);
        qa[ks][3] = __float_as_uint(Qs[(r + 8) * 68 + ks * 8 + tg + 4]);
    }

    float oacc[8][4] = {};
    float mrow[2] = {-1e30f, -1e30f};
    float lrow[2] = {0.f, 0.f};
    const float scale = 0.125f;
    float* Pw = Ps + w * 16 * 72;

    for (int kt = 0; kt < 16; kt++) {
        __syncthreads();  // prior tile fully consumed before overwrite
#pragma unroll
        for (int j = 0; j < 8; j++) {
            int idx = tid + j * 128; int r = idx >> 4, c = (idx & 15) * 4;
            *(float4*)&Ks[r * 68 + c] = *(const float4*)(K + (size_t)(kt * 64 + r) * DKk + c);
            *(float4*)&Vs[r * 72 + c] = *(const float4*)(V + (size_t)(kt * 64 + r) * DKk + c);
        }
        if (tid < 64) ms[tid] = mask[(size_t)bh * Ss + kt * 64 + tid];
        __syncthreads();

        // S = Q @ K^T
        float sacc[8][4] = {};
#pragma unroll
        for (int ks = 0; ks < 8; ks++) {
#pragma unroll
            for (int fn = 0; fn < 8; fn++) {
                int n = fn * 8 + g;
                uint32_t b0 = __float_as_uint(Ks[n * 68 + ks * 8 + tg]);
                uint32_t b1 = __float_as_uint(Ks[n * 68 + ks * 8 + tg + 4]);
                mma8(sacc[fn], qa[ks][0], qa[ks][1], qa[ks][2], qa[ks][3], b0, b1);
            }
        }
        // scale + mask
#pragma unroll
        for (int fn = 0; fn < 8; fn++) {
            int c0 = fn * 8 + 2 * tg;
            bool k0m = (ms[c0] == 0), k1m = (ms[c0 + 1] == 0);
            sacc[fn][0] = k0m ? -10000.f : sacc[fn][0] * scale;
            sacc[fn][1] = k1m ? -10000.f : sacc[fn][1] * scale;
            sacc[fn][2] = k0m ? -10000.f : sacc[fn][2] * scale;
            sacc[fn][3] = k1m ? -10000.f : sacc[fn][3] * scale;
        }
        // online softmax: rows (w*16+g) and (+8), cols split over tg quad
        float mxA = -1e30f, mxB = -1e30f;
#pragma unroll
        for (int fn = 0; fn < 8; fn++) {
            mxA = fmaxf(mxA, fmaxf(sacc[fn][0], sacc[fn][1]));
            mxB = fmaxf(mxB, fmaxf(sacc[fn][2], sacc[fn][3]));
        }
        mxA = fmaxf(mxA, __shfl_xor_sync(~0u, mxA, 1));
        mxA = fmaxf(mxA, __shfl_xor_sync(~0u, mxA, 2));
        mxB = fmaxf(mxB, __shfl_xor_sync(~0u, mxB, 1));
        mxB = fmaxf(mxB, __shfl_xor_sync(~0u, mxB, 2));
        float mAn = fmaxf(mrow[0], mxA), mBn = fmaxf(mrow[1], mxB);
        float aA = __expf(mrow[0] - mAn), aB = __expf(mrow[1] - mBn);
        mrow[0] = mAn; mrow[1] = mBn;
        float sA = 0.f, sB = 0.f;
#pragma unroll
        for (int fn = 0; fn < 8; fn++) {
            sacc[fn][0] = __expf(sacc[fn][0] - mAn);
            sacc[fn][1] = __expf(sacc[fn][1] - mAn);
            sacc[fn][2] = __expf(sacc[fn][2] - mBn);
            sacc[fn][3] = __expf(sacc[fn][3] - mBn);
            sA += sacc[fn][0] + sacc[fn][1];
            sB += sacc[fn][2] + sacc[fn][3];
        }
        sA += __shfl_xor_sync(~0u, sA, 1); sA += __shfl_xor_sync(~0u, sA, 2);
        sB += __shfl_xor_sync(~0u, sB, 1); sB += __shfl_xor_sync(~0u, sB, 2);
        lrow[0] = lrow[0] * aA + sA;
        lrow[1] = lrow[1] * aB + sB;
#pragma unroll
        for (int fn = 0; fn < 8; fn++) {
            oacc[fn][0] *= aA; oacc[fn][1] *= aA; oacc[fn][2] *= aB; oacc[fn][3] *= aB;
        }
        // stage P (tf32-rounded) in per-warp smem
#pragma unroll
        for (int fn = 0; fn < 8; fn++) {
            int c0 = fn * 8 + 2 * tg;
            Pw[g * 72 + c0]           = __uint_as_float(tf32r(sacc[fn][0]));
            Pw[g * 72 + c0 + 1]       = __uint_as_float(tf32r(sacc[fn][1]));
            Pw[(g + 8) * 72 + c0]     = __uint_as_float(tf32r(sacc[fn][2]));
            Pw[(g + 8) * 72 + c0 + 1] = __uint_as_float(tf32r(sacc[fn][3]));
        }
        __syncwarp();
        // O += P @ V
#pragma unroll
        for (int ks = 0; ks < 8; ks++) {
            uint32_t a0 = __float_as_uint(Pw[g * 72 + ks * 8 + tg]);
            uint32_t a1 = __float_as_uint(Pw[(g + 8) * 72 + ks * 8 + tg]);
            uint32_t a2 = __float_as_uint(Pw[g * 72 + ks * 8 + tg + 4]);
            uint32_t a3 = __float_as_uint(Pw[(g + 8) * 72 + ks * 8 + tg + 4]);
#pragma unroll
            for (int fn = 0; fn < 8; fn++) {
                int n = fn * 8 + g;
                uint32_t b0 = __float_as_uint(Vs[(ks * 8 + tg) * 72 + n]);
                uint32_t b1 = __float_as_uint(Vs[(ks * 8 + tg + 4) * 72 + n]);
                mma8(oacc[fn], a0, a1, a2, a3, b0, b1);
            }
        }
    }
    __syncthreads();

    // normalize O -> Ps ; Wo -> Ks (both tf32-rounded)
    float invA = 1.f / lrow[0], invB = 1.f / lrow[1];
#pragma unroll
    for (int fn = 0; fn < 8; fn++) {
        int c0 = fn * 8 + 2 * tg;
        Pw[g * 72 + c0]           = __uint_as_float(tf32r(oacc[fn][0] * invA));
        Pw[g * 72 + c0 + 1]       = __uint_as_float(tf32r(oacc[fn][1] * invA));
        Pw[(g + 8) * 72 + c0]     = __uint_as_float(tf32r(oacc[fn][2] * invB));
        Pw[(g + 8) * 72 + c0 + 1] = __uint_as_float(tf32r(oacc[fn][3] * invB));
    }
#pragma unroll
    for (int j = 0; j < 8; j++) {
        int idx = tid + j * 128; int r = idx >> 4, c = (idx & 15) * 4;
        float4 wv = *(const float4*)(Wo + r * 64 + c);
        Ks[r * 68 + c]     = __uint_as_float(tf32r(wv.x));
        Ks[r * 68 + c + 1] = __uint_as_float(tf32r(wv.y));
        Ks[r * 68 + c + 2] = __uint_as_float(tf32r(wv.z));
        Ks[r * 68 + c + 3] = __uint_as_float(tf32r(wv.w));
    }
    __syncthreads();

    // O2 = O @ Wo^T + bo
    float o2[8][4];
#pragma unroll
    for (int fn = 0; fn < 8; fn++) {
        int c0 = fn * 8 + 2 * tg;
        float b0v = bo[c0], b1v = bo[c0 + 1];
        o2[fn][0] = b0v; o2[fn][1] = b1v; o2[fn][2] = b0v; o2[fn][3] = b1v;
    }
#pragma unroll
    for (int ks = 0; ks < 8; ks++) {
        uint32_t a0 = __float_as_uint(Pw[g * 72 + ks * 8 + tg]);
        uint32_t a1 = __float_as_uint(Pw[(g + 8) * 72 + ks * 8 + tg]);
        uint32_t a2 = __float_as_uint(Pw[g * 72 + ks * 8 + tg + 4]);
        uint32_t a3 = __float_as_uint(Pw[(g + 8) * 72 + ks * 8 + tg + 4]);
#pragma unroll
        for (int fn = 0; fn < 8; fn++) {
            int n = fn * 8 + g;
            uint32_t b0 = __float_as_uint(Ks[n * 68 + ks * 8 + tg]);
            uint32_t b1 = __float_as_uint(Ks[n * 68 + ks * 8 + tg + 4]);
            mma8(o2[fn], a0, a1, a2, a3, b0, b1);
        }
    }
    // write out[b][s][h*64+o]
    int b_ = bh >> 4, h = bh & 15;
#pragma unroll
    for (int fn = 0; fn < 8; fn++) {
        int col = h * 64 + fn * 8 + 2 * tg;
        int r0 = q0 + w * 16 + g, r1 = r0 + 8;
        *(float2*)(out + ((size_t)(b_ * Ss + r0)) * Dd + col) = make_float2(o2[fn][0], o2[fn][1]);
        *(float2*)(out + ((size_t)(b_ * Ss + r1)) * Dd + col) = make_float2(o2[fn][2], o2[fn][3]);
    }
}

// ---------------------------------------------------------------------------
extern "C" void kernel_launch(void* const* d_in, const int* in_sizes, int n_in,
                              void* d_out, int out_size) {
    const float* q   = (const float*)d_in[0];
    const float* k   = (const float*)d_in[1];
    const float* v   = (const float*)d_in[2];
    const int*   msk = (const int*)d_in[3];
    const float* Wq  = (const float*)d_in[4];
    const float* bq  = (const float*)d_in[5];
    const float* Wk  = (const float*)d_in[6];
    const float* bk  = (const float*)d_in[7];
    const float* Wv  = (const float*)d_in[8];
    const float* bv  = (const float*)d_in[9];
    const float* Wqf = (const float*)d_in[10];
    const float* bqf = (const float*)d_in[11];
    const float* Wkf = (const float*)d_in[12];
    const float* bkf = (const float*)d_in[13];
    const float* Wvf = (const float*)d_in[14];
    const float* bvf = (const float*)d_in[15];
    const float* Wo  = (const float*)d_in[16];
    const float* bo  = (const float*)d_in[17];
    float* out = (float*)d_out;

    const int gemm_smem = (2 * 128 * GST + 2 * 64 * GST) * (int)sizeof(float);      // 55296
    const int attn_smem = (64 * 68 + 64 * 68 + 64 * 72 + 4 * 16 * 72) * 4 + 64 * 4; // 71936

    static int cfg = 0;
    if (!cfg) {  // idempotent attribute set; first call happens before graph capture
        cudaFuncSetAttribute(gemm_tc, cudaFuncAttributeMaxDynamicSharedMemorySize, gemm_smem);
        cudaFuncSetAttribute(attn_tc, cudaFuncAttributeMaxDynamicSharedMemorySize, attn_smem);
        cfg = 1;
    }

    fold_kernel<<<dim3(16, 16, 3), 256>>>(Wq, Wqf, Wk, Wkf, Wv, Wvf);
    bfold_kernel<<<3, 1024>>>(bq, bqf, bk, bkf, bv, bvf, Wqf, Wkf, Wvf);
    gemm_tc<<<dim3(16, 32, 3), 256, gemm_smem>>>(q, k, v);
    attn_tc<<<dim3(16, 64), 128, attn_smem>>>(msk, Wo, bo, out);
}

// round 3
// speedup vs baseline: 3.1853x; 1.1333x over previous
#include <cuda_runtime.h>
#include <cuda_bf16.h>
#include <math.h>
#include <stdint.h>

#define Bb 4
#define Ss 1024
#define Dd 1024
#define Hh 16
#define DKk 64

// ---------------------------------------------------------------------------
// Device scratch (allocation-free)
// ---------------------------------------------------------------------------
__device__ __nv_bfloat16 g_Xb[2][4096 * 1024];   // bf16 q,k inputs
__device__ float         g_Xr[4096 * 1024];      // tf32-rounded v input
__device__ __nv_bfloat16 g_Wcb[2][1024 * 1024];  // folded Wq,Wk (bf16)
__device__ float         g_Wc[1024 * 1024];      // folded Wv (tf32)
__device__ float         g_bc[3][1024];
__device__ __nv_bfloat16 g_Qb[64 * 1024 * 64];   // per-head Q (bf16)
__device__ __nv_bfloat16 g_Kb[64 * 1024 * 64];   // per-head K (bf16)
__device__ float         g_V [64 * 1024 * 64];   // per-head V (f32)
__device__ float         g_Vp[64 * 1024 * 64];   // V' = V @ Wo^T (tf32)

// ---------------------------------------------------------------------------
// helpers
// ---------------------------------------------------------------------------
__device__ __forceinline__ uint32_t tf32r(float x) {
    uint32_t u; asm("cvt.rna.tf32.f32 %0, %1;" : "=r"(u) : "f"(x)); return u;
}
__device__ __forceinline__ float tf32f(float x) { return __uint_as_float(tf32r(x)); }
__device__ __forceinline__ void mma8(float (&d)[4], uint32_t a0, uint32_t a1, uint32_t a2,
                                     uint32_t a3, uint32_t b0, uint32_t b1) {
    asm volatile(
        "mma.sync.aligned.m16n8k8.row.col.f32.tf32.tf32.f32 "
        "{%0,%1,%2,%3},{%4,%5,%6,%7},{%8,%9},{%0,%1,%2,%3};"
        : "+f"(d[0]), "+f"(d[1]), "+f"(d[2]), "+f"(d[3])
        : "r"(a0), "r"(a1), "r"(a2), "r"(a3), "r"(b0), "r"(b1));
}
__device__ __forceinline__ void mma16(float (&d)[4], uint32_t a0, uint32_t a1, uint32_t a2,
                                      uint32_t a3, uint32_t b0, uint32_t b1) {
    asm volatile(
        "mma.sync.aligned.m16n8k16.row.col.f32.bf16.bf16.f32 "
        "{%0,%1,%2,%3},{%4,%5,%6,%7},{%8,%9},{%0,%1,%2,%3};"
        : "+f"(d[0]), "+f"(d[1]), "+f"(d[2]), "+f"(d[3])
        : "r"(a0), "r"(a1), "r"(a2), "r"(a3), "r"(b0), "r"(b1));
}
__device__ __forceinline__ void cp16(void* s, const void* g) {
    uint32_t sa = (uint32_t)__cvta_generic_to_shared(s);
    asm volatile("cp.async.cg.shared.global [%0], [%1], 16;" :: "r"(sa), "l"(g));
}
__device__ __forceinline__ uint32_t pack_bf2(float a, float b) {
    __nv_bfloat162 t = __float22bfloat162_rn(make_float2(a, b));
    return *reinterpret_cast<uint32_t*>(&t);
}

// ---------------------------------------------------------------------------
// preround: q,k -> bf16 ; v -> tf32-rounded f32.  grid 4096 x 256, float4/thr
// ---------------------------------------------------------------------------
__global__ void preround(const float* __restrict__ q, const float* __restrict__ k,
                         const float* __restrict__ v) {
    size_t i = (size_t)blockIdx.x * blockDim.x + threadIdx.x;  // float4 index
    float4 a = ((const float4*)q)[i];
    uint32_t* dq = (uint32_t*)g_Xb[0];
    dq[i * 2] = pack_bf2(a.x, a.y); dq[i * 2 + 1] = pack_bf2(a.z, a.w);
    float4 b = ((const float4*)k)[i];
    uint32_t* dk = (uint32_t*)g_Xb[1];
    dk[i * 2] = pack_bf2(b.x, b.y); dk[i * 2 + 1] = pack_bf2(b.z, b.w);
    float4 c = ((const float4*)v)[i];
    float4 r; r.x = tf32f(c.x); r.y = tf32f(c.y); r.z = tf32f(c.z); r.w = tf32f(c.w);
    ((float4*)g_Xr)[i] = r;
}

// ---------------------------------------------------------------------------
// Fold: Wc[t][(h*64+o)*1024 + j] = sum_i Wf[o,i] * Wbig[h*64+i, j]
// t<2 -> bf16 (g_Wcb), t==2 -> tf32-rounded f32 (g_Wc)
// ---------------------------------------------------------------------------
__global__ void fold_kernel(const float* __restrict__ Wq, const float* __restrict__ Wqf,
                            const float* __restrict__ Wk, const float* __restrict__ Wkf,
                            const float* __restrict__ Wv, const float* __restrict__ Wvf) {
    int t = blockIdx.z, h = blockIdx.y, j0 = blockIdx.x * 64;
    const float* Wbig = (t == 0) ? Wq : (t == 1) ? Wk : Wv;
    const float* Wf   = (t == 0) ? Wqf : (t == 1) ? Wkf : Wvf;

    __shared__ float fs[64][65];
    __shared__ float bs[64][65];

    int tid = threadIdx.x;
    for (int idx = tid; idx < 64 * 16; idx += 256) {
        int r = idx >> 4, c4 = (idx & 15) * 4;
        float4 fv = *(const float4*)(Wf + r * 64 + c4);
        fs[r][c4] = fv.x; fs[r][c4 + 1] = fv.y; fs[r][c4 + 2] = fv.z; fs[r][c4 + 3] = fv.w;
        float4 bv = *(const float4*)(Wbig + (h * 64 + r) * Dd + j0 + c4);
        bs[r][c4] = bv.x; bs[r][c4 + 1] = bv.y; bs[r][c4 + 2] = bv.z; bs[r][c4 + 3] = bv.w;
    }
    __syncthreads();

    int ty = tid >> 4, tx = tid & 15;
    float acc[4][4] = {};
#pragma unroll 8
    for (int i = 0; i < 64; i++) {
        float a[4], b[4];
#pragma unroll
        for (int u = 0; u < 4; u++) { a[u] = fs[ty * 4 + u][i]; b[u] = bs[i][tx * 4 + u]; }
#pragma unroll
        for (int u = 0; u < 4; u++)
#pragma unroll
            for (int w = 0; w < 4; w++) acc[u][w] += a[u] * b[w];
    }
    if (t < 2) {
        uint32_t* dst = (uint32_t*)g_Wcb[t];
#pragma unroll
        for (int u = 0; u < 4; u++) {
            size_t row = (size_t)(h * 64 + ty * 4 + u) * Dd + j0 + tx * 4;
            dst[row / 2]     = pack_bf2(acc[u][0], acc[u][1]);
            dst[row / 2 + 1] = pack_bf2(acc[u][2], acc[u][3]);
        }
    } else {
        float* dst = g_Wc;
#pragma unroll
        for (int u = 0; u < 4; u++)
#pragma unroll
            for (int w = 0; w < 4; w++)
                dst[(size_t)(h * 64 + ty * 4 + u) * Dd + j0 + tx * 4 + w] = tf32f(acc[u][w]);
    }
}

__global__ void bfold_kernel(const float* __restrict__ bq, const float* __restrict__ bqf,
                             const float* __restrict__ bk, const float* __restrict__ bkf,
                             const float* __restrict__ bv, const float* __restrict__ bvf,
                             const float* __restrict__ Wqf, const float* __restrict__ Wkf,
                             const float* __restrict__ Wvf) {
    int t = blockIdx.x, n = threadIdx.x;
    const float* b1 = (t == 0) ? bq : (t == 1) ? bk : bv;
    const float* b2 = (t == 0) ? bqf : (t == 1) ? bkf : bvf;
    const float* Wf = (t == 0) ? Wqf : (t == 1) ? Wkf : Wvf;
    int h = n >> 6, o = n & 63;
    float s = b2[o];
    for (int i = 0; i < 64; i++) s += Wf[o * 64 + i] * b1[h * 64 + i];
    g_bc[t][n] = s;
}

// ---------------------------------------------------------------------------
// bf16 projection GEMM (Q and K): Y = relu(Xb @ Wcb^T + bc) -> bf16 per-head
// BM=128, BN=64(head), BK=32. 8 warps (4m x 2n), warp 32x32, m16n8k16.
// smem: Xs[2][128][40] + Ws[2][64][40] bf16 = 30720 B
// ---------------------------------------------------------------------------
#define BP 40
__global__ __launch_bounds__(256) void gemm_bf() {
    extern __shared__ uint16_t sb[];
    uint16_t* Xs = sb;               // [2][128][BP]
    uint16_t* Ws = sb + 2 * 128 * BP;

    int t = blockIdx.z;
    const __nv_bfloat16* X = g_Xb[t];
    const __nv_bfloat16* W = g_Wcb[t];
    const float* bias = g_bc[t];
    __nv_bfloat16* Y = (t == 0) ? g_Qb : g_Kb;
    int head = blockIdx.x, m0 = blockIdx.y * 128;

    int tid = threadIdx.x;
    int w = tid >> 5, lane = tid & 31, g = lane >> 2, tg = lane & 3;
    int wm = w & 3, wn = w >> 2;

    float acc[2][4][4] = {};

#define BLOAD(I, BUF)                                                                   \
    do {                                                                                \
        int k0_ = (I) * 32;                                                             \
        _Pragma("unroll")                                                               \
        for (int j = 0; j < 2; j++) {                                                   \
            int idx = tid + j * 256; int r = idx >> 2, c = (idx & 3) * 8;               \
            cp16(Xs + ((BUF) * 128 + r) * BP + c,                                       \
                 X + (size_t)(m0 + r) * Dd + k0_ + c);                                  \
        }                                                                               \
        {                                                                               \
            int r = tid >> 2, c = (tid & 3) * 8;                                        \
            cp16(Ws + ((BUF) * 64 + r) * BP + c,                                        \
                 W + (size_t)(head * 64 + r) * Dd + k0_ + c);                           \
        }                                                                               \
        asm volatile("cp.async.commit_group;");                                        \
    } while (0)

    BLOAD(0, 0);
    for (int i = 0; i < 32; i++) {
        int buf = i & 1;
        if (i < 31) {
            BLOAD(i + 1, buf ^ 1);
            asm volatile("cp.async.wait_group 1;");
        } else {
            asm volatile("cp.async.wait_group 0;");
        }
        __syncthreads();
        const uint16_t* Xb_ = Xs + buf * 128 * BP;
        const uint16_t* Wb_ = Ws + buf * 64 * BP;
#pragma unroll
        for (int ks = 0; ks < 2; ks++) {
            uint32_t a[2][4];
#pragma unroll
            for (int fm = 0; fm < 2; fm++) {
                int r = wm * 32 + fm * 16 + g;
                const uint16_t* xp = Xb_ + r * BP + ks * 16 + 2 * tg;
                a[fm][0] = *(const uint32_t*)xp;
                a[fm][1] = *(const uint32_t*)(xp + 8 * BP);
                a[fm][2] = *(const uint32_t*)(xp + 8);
                a[fm][3] = *(const uint32_t*)(xp + 8 * BP + 8);
            }
#pragma unroll
            for (int fn = 0; fn < 4; fn++) {
                int n = wn * 32 + fn * 8 + g;
                const uint16_t* wp = Wb_ + n * BP + ks * 16 + 2 * tg;
                uint32_t b0 = *(const uint32_t*)wp;
                uint32_t b1 = *(const uint32_t*)(wp + 8);
                mma16(acc[0][fn], a[0][0], a[0][1], a[0][2], a[0][3], b0, b1);
                mma16(acc[1][fn], a[1][0], a[1][1], a[1][2], a[1][3], b0, b1);
            }
        }
        __syncthreads();
    }
#undef BLOAD

#pragma unroll
    for (int fm = 0; fm < 2; fm++) {
#pragma unroll
        for (int fn = 0; fn < 4; fn++) {
            int col = wn * 32 + fn * 8 + 2 * tg;
            float b0 = bias[head * 64 + col], b1 = bias[head * 64 + col + 1];
            int r0 = m0 + wm * 32 + fm * 16 + g, r1 = r0 + 8;
            uint32_t v0 = pack_bf2(fmaxf(acc[fm][fn][0] + b0, 0.f),
                                   fmaxf(acc[fm][fn][1] + b1, 0.f));
            uint32_t v1 = pack_bf2(fmaxf(acc[fm][fn][2] + b0, 0.f),
                                   fmaxf(acc[fm][fn][3] + b1, 0.f));
            {
                int b_ = r0 >> 10, s = r0 & 1023;
                *(uint32_t*)((uint16_t*)Y + (((size_t)(b_ * Hh + head)) * Ss + s) * DKk + col) = v0;
            }
            {
                int b_ = r1 >> 10, s = r1 & 1023;
                *(uint32_t*)((uint16_t*)Y + (((size_t)(b_ * Hh + head)) * Ss + s) * DKk + col) = v1;
            }
        }
    }
}

// ---------------------------------------------------------------------------
// tf32 projection GEMM (V only): g_V = relu(g_Xr @ g_Wc^T + bc[2]), f32 out
// ---------------------------------------------------------------------------
#define GST 36
__global__ __launch_bounds__(256) void gemm_tc() {
    extern __shared__ float sm[];
    float* Xs = sm;
    float* Ws = sm + 2 * 128 * GST;

    const float* X = g_Xr;
    const float* W = g_Wc;
    const float* bias = g_bc[2];
    float* Y = g_V;
    int head = blockIdx.x, m0 = blockIdx.y * 128;

    int tid = threadIdx.x;
    int w = tid >> 5, lane = tid & 31, g = lane >> 2, tg = lane & 3;
    int wm = w & 3, wn = w >> 2;

    float acc[2][4][4] = {};

#define VLOAD(I, BUF)                                                                  \
    do {                                                                               \
        int k0_ = (I) * 32;                                                            \
        _Pragma("unroll")                                                              \
        for (int j = 0; j < 4; j++) {                                                  \
            int idx = tid + j * 256; int r = idx >> 3, c = (idx & 7) * 4;              \
            cp16(&Xs[((BUF) * 128 + r) * GST + c],                                     \
                 X + (size_t)(m0 + r) * Dd + k0_ + c);                                 \
        }                                                                              \
        _Pragma("unroll")                                                              \
        for (int j = 0; j < 2; j++) {                                                  \
            int idx = tid + j * 256; int r = idx >> 3, c = (idx & 7) * 4;              \
            cp16(&Ws[((BUF) * 64 + r) * GST + c],                                      \
                 W + (size_t)(head * 64 + r) * Dd + k0_ + c);                          \
        }                                                                              \
        asm volatile("cp.async.commit_group;");                                       \
    } while (0)

    VLOAD(0, 0);
    for (int i = 0; i < 32; i++) {
        int buf = i & 1;
        if (i < 31) {
            VLOAD(i + 1, buf ^ 1);
            asm volatile("cp.async.wait_group 1;");
        } else {
            asm volatile("cp.async.wait_group 0;");
        }
        __syncthreads();
        float* Xb = &Xs[buf * 128 * GST];
        float* Wb = &Ws[buf * 64 * GST];
#pragma unroll
        for (int ks = 0; ks < 4; ks++) {
            int kk = ks * 8;
            uint32_t a[2][4];
#pragma unroll
            for (int fm = 0; fm < 2; fm++) {
                int r = wm * 32 + fm * 16 + g;
                a[fm][0] = __float_as_uint(Xb[r * GST + kk + tg]);
                a[fm][1] = __float_as_uint(Xb[(r + 8) * GST + kk + tg]);
                a[fm][2] = __float_as_uint(Xb[r * GST + kk + tg + 4]);
                a[fm][3] = __float_as_uint(Xb[(r + 8) * GST + kk + tg + 4]);
            }
#pragma unroll
            for (int fn = 0; fn < 4; fn++) {
                int n = wn * 32 + fn * 8 + g;
                uint32_t b0 = __float_as_uint(Wb[n * GST + kk + tg]);
                uint32_t b1 = __float_as_uint(Wb[n * GST + kk + tg + 4]);
                mma8(acc[0][fn], a[0][0], a[0][1], a[0][2], a[0][3], b0, b1);
                mma8(acc[1][fn], a[1][0], a[1][1], a[1][2], a[1][3], b0, b1);
            }
        }
        __syncthreads();
    }
#undef VLOAD

#pragma unroll
    for (int fm = 0; fm < 2; fm++) {
#pragma unroll
        for (int fn = 0; fn < 4; fn++) {
            int col = wn * 32 + fn * 8 + 2 * tg;
            float b0 = bias[head * 64 + col], b1 = bias[head * 64 + col + 1];
            int r0 = m0 + wm * 32 + fm * 16 + g, r1 = r0 + 8;
            float2 v0 = make_float2(fmaxf(acc[fm][fn][0] + b0, 0.f),
                                    fmaxf(acc[fm][fn][1] + b1, 0.f));
            float2 v1 = make_float2(fmaxf(acc[fm][fn][2] + b0, 0.f),
                                    fmaxf(acc[fm][fn][3] + b1, 0.f));
            {
                int b_ = r0 >> 10, s = r0 & 1023;
                *(float2*)(Y + (((size_t)(b_ * Hh + head)) * Ss + s) * DKk + col) = v0;
            }
            {
                int b_ = r1 >> 10, s = r1 & 1023;
                *(float2*)(Y + (((size_t)(b_ * Hh + head)) * Ss + s) * DKk + col) = v1;
            }
        }
    }
}

// ---------------------------------------------------------------------------
// vprime: g_Vp[bh][s][o] = tf32( sum_d g_V[bh][s][d] * Wo[o][d] )
// ---------------------------------------------------------------------------
__global__ void vprime(const float* __restrict__ Wo) {
    int st = blockIdx.x, bh = blockIdx.y;
    __shared__ float vs[64][65], wo[64][65];
    const float* Vt = g_V + ((size_t)bh * Ss + st * 64) * DKk;

    int tid = threadIdx.x;
    for (int idx = tid; idx < 64 * 16; idx += 256) {
        int r = idx >> 4, c4 = (idx & 15) * 4;
        float4 a = *(const float4*)(Vt + (size_t)r * DKk + c4);
        vs[r][c4] = a.x; vs[r][c4 + 1] = a.y; vs[r][c4 + 2] = a.z; vs[r][c4 + 3] = a.w;
        float4 b = *(const float4*)(Wo + r * 64 + c4);
        wo[r][c4] = b.x; wo[r][c4 + 1] = b.y; wo[r][c4 + 2] = b.z; wo[r][c4 + 3] = b.w;
    }
    __syncthreads();

    int ty = tid >> 4, tx = tid & 15;
    float acc[4][4] = {};
#pragma unroll 8
    for (int d = 0; d < 64; d++) {
        float a[4], b[4];
#pragma unroll
        for (int u = 0; u < 4; u++) { a[u] = vs[ty * 4 + u][d]; b[u] = wo[tx * 4 + u][d]; }
#pragma unroll
        for (int u = 0; u < 4; u++)
#pragma unroll
            for (int w = 0; w < 4; w++) acc[u][w] += a[u] * b[w];
    }
    float* dst = g_Vp + ((size_t)bh * Ss + st * 64) * DKk;
#pragma unroll
    for (int u = 0; u < 4; u++)
#pragma unroll
        for (int w = 0; w < 4; w++)
            dst[(size_t)(ty * 4 + u) * DKk + tx * 4 + w] = tf32f(acc[u][w]);
}

// ---------------------------------------------------------------------------
// Flash attention: S in bf16 (m16n8k16), PV in tf32 (m16n8k8), V'=V@Wo^T,
// bo added at write. 128 q-rows/CTA, 8 warps, cp.async double-buffered K/V/mask.
// ---------------------------------------------------------------------------
#define KP 72   // K/Q bf16 pitch (uint16 units)
#define VP 72   // V f32 pitch
#define PP 76   // P f32 pitch
__global__ __launch_bounds__(256) void attn_tc(const int* __restrict__ mask,
                                               const float* __restrict__ bo,
                                               float* __restrict__ out) {
    extern __shared__ char smraw[];
    uint16_t* Kb = (uint16_t*)smraw;                           // [2][64][KP] 18432 B
    float* Vs = (float*)(smraw + 2 * 64 * KP * 2);             // [2][64][VP] 36864 B
    float* Ps = Vs + 2 * 64 * VP;                              // [8][16][PP] 38912 B
    int* ms = (int*)((char*)Ps + 8 * 16 * PP * 4);             // [2][64]       512 B

    int bh = blockIdx.y, q0 = blockIdx.x * 128;
    const __nv_bfloat16* Qg = g_Qb + ((size_t)bh * Ss + q0) * DKk;
    const __nv_bfloat16* Kg = g_Kb + (size_t)bh * Ss * DKk;
    const float* Vg = g_Vp + (size_t)bh * Ss * DKk;

    int tid = threadIdx.x, w = tid >> 5, lane = tid & 31, g = lane >> 2, tg = lane & 3;

    // ---- stage Q (bf16) through Vs region, extract A-fragments -------------
    {
        uint16_t* Qs = (uint16_t*)Vs;  // pitch KP
#pragma unroll
        for (int j = 0; j < 4; j++) {
            int idx = tid + j * 256; int r = idx >> 3, c = (idx & 7) * 8;
            *(uint4*)(Qs + r * KP + c) = *(const uint4*)((const uint16_t*)Qg + (size_t)r * DKk + c);
        }
        __syncthreads();
        // fall through: qa extracted below, then re-sync before fills
    }
    uint32_t qa[4][4];
    {
        const uint16_t* Qs = (const uint16_t*)Vs;
        int r0 = w * 16 + g;
#pragma unroll
        for (int ks = 0; ks < 4; ks++) {
            const uint16_t* qp = Qs + r0 * KP + ks * 16 + 2 * tg;
            qa[ks][0] = *(const uint32_t*)qp;
            qa[ks][1] = *(const uint32_t*)(qp + 8 * KP);
            qa[ks][2] = *(const uint32_t*)(qp + 8);
            qa[ks][3] = *(const uint32_t*)(qp + 8 * KP + 8);
        }
    }
    __syncthreads();

#define AFILL(KT, BUF)                                                                  \
    do {                                                                                \
        const uint16_t* kg = (const uint16_t*)Kg + (size_t)(KT) * 64 * DKk;             \
        const float* vg = Vg + (size_t)(KT) * 64 * DKk;                                 \
        _Pragma("unroll")                                                               \
        for (int j = 0; j < 2; j++) {                                                   \
            int idx = tid + j * 256; int r = idx >> 3, c = (idx & 7) * 8;               \
            cp16(Kb + ((BUF) * 64 + r) * KP + c, kg + (size_t)r * DKk + c);             \
        }                                                                               \
        _Pragma("unroll")                                                               \
        for (int j = 0; j < 4; j++) {                                                   \
            int idx = tid + j * 256; int r = idx >> 4, c = (idx & 15) * 4;              \
            cp16(Vs + ((BUF) * 64 + r) * VP + c, vg + (size_t)r * DKk + c);             \
        }                                                                               \
        if (tid < 16)                                                                   \
            cp16(ms + (BUF) * 64 + tid * 4, mask + (size_t)bh * Ss + (KT) * 64 + tid * 4); \
        asm volatile("cp.async.commit_group;");                                        \
    } while (0)

    float oacc[8][4] = {};
    float mrow[2] = {-1e30f, -1e30f};
    float lrow[2] = {0.f, 0.f};
    const float scale = 0.125f;
    float* Pw = Ps + w * 16 * PP;

    AFILL(0, 0);
    for (int kt = 0; kt < 16; kt++) {
        int buf = kt & 1;
        if (kt < 15) {
            AFILL(kt + 1, buf ^ 1);
            asm volatile("cp.async.wait_group 1;");
        } else {
            asm volatile("cp.async.wait_group 0;");
        }
        __syncthreads();
        const uint16_t* Kt = Kb + buf * 64 * KP;
        const float* Vt = Vs + buf * 64 * VP;
        const int* mt = ms + buf * 64;

        // ---- S = Q @ K^T (bf16) ----
        float sacc[8][4] = {};
#pragma unroll
        for (int ks = 0; ks < 4; ks++) {
#pragma unroll
            for (int fn = 0; fn < 8; fn++) {
                const uint16_t* kp = Kt + (fn * 8 + g) * KP + ks * 16 + 2 * tg;
                uint32_t b0 = *(const uint32_t*)kp;
                uint32_t b1 = *(const uint32_t*)(kp + 8);
                mma16(sacc[fn], qa[ks][0], qa[ks][1], qa[ks][2], qa[ks][3], b0, b1);
            }
        }
        // scale + mask
#pragma unroll
        for (int fn = 0; fn < 8; fn++) {
            int c0 = fn * 8 + 2 * tg;
            bool k0m = (mt[c0] == 0), k1m = (mt[c0 + 1] == 0);
            sacc[fn][0] = k0m ? -10000.f : sacc[fn][0] * scale;
            sacc[fn][1] = k1m ? -10000.f : sacc[fn][1] * scale;
            sacc[fn][2] = k0m ? -10000.f : sacc[fn][2] * scale;
            sacc[fn][3] = k1m ? -10000.f : sacc[fn][3] * scale;
        }
        // online softmax (rows g and g+8)
        float mxA = -1e30f, mxB = -1e30f;
#pragma unroll
        for (int fn = 0; fn < 8; fn++) {
            mxA = fmaxf(mxA, fmaxf(sacc[fn][0], sacc[fn][1]));
            mxB = fmaxf(mxB, fmaxf(sacc[fn][2], sacc[fn][3]));
        }
        mxA = fmaxf(mxA, __shfl_xor_sync(~0u, mxA, 1));
        mxA = fmaxf(mxA, __shfl_xor_sync(~0u, mxA, 2));
        mxB = fmaxf(mxB, __shfl_xor_sync(~0u, mxB, 1));
        mxB = fmaxf(mxB, __shfl_xor_sync(~0u, mxB, 2));
        float mAn = fmaxf(mrow[0], mxA), mBn = fmaxf(mrow[1], mxB);
        float aA = __expf(mrow[0] - mAn), aB = __expf(mrow[1] - mBn);
        mrow[0] = mAn; mrow[1] = mBn;
        float sA = 0.f, sB = 0.f;
#pragma unroll
        for (int fn = 0; fn < 8; fn++) {
            sacc[fn][0] = __expf(sacc[fn][0] - mAn);
            sacc[fn][1] = __expf(sacc[fn][1] - mAn);
            sacc[fn][2] = __expf(sacc[fn][2] - mBn);
            sacc[fn][3] = __expf(sacc[fn][3] - mBn);
            sA += sacc[fn][0] + sacc[fn][1];
            sB += sacc[fn][2] + sacc[fn][3];
        }
        sA += __shfl_xor_sync(~0u, sA, 1); sA += __shfl_xor_sync(~0u, sA, 2);
        sB += __shfl_xor_sync(~0u, sB, 1); sB += __shfl_xor_sync(~0u, sB, 2);
        lrow[0] = lrow[0] * aA + sA;
        lrow[1] = lrow[1] * aB + sB;
#pragma unroll
        for (int fn = 0; fn < 8; fn++) {
            oacc[fn][0] *= aA; oacc[fn][1] *= aA; oacc[fn][2] *= aB; oacc[fn][3] *= aB;
        }
        // stage P (tf32-rounded) in per-warp smem
#pragma unroll
        for (int fn = 0; fn < 8; fn++) {
            int c0 = fn * 8 + 2 * tg;
            *(float2*)(Pw + g * PP + c0)       = make_float2(tf32f(sacc[fn][0]), tf32f(sacc[fn][1]));
            *(float2*)(Pw + (g + 8) * PP + c0) = make_float2(tf32f(sacc[fn][2]), tf32f(sacc[fn][3]));
        }
        __syncwarp();
        // ---- O += P @ V' (tf32) ----
#pragma unroll
        for (int ks = 0; ks < 8; ks++) {
            uint32_t a0 = __float_as_uint(Pw[g * PP + ks * 8 + tg]);
            uint32_t a1 = __float_as_uint(Pw[(g + 8) * PP + ks * 8 + tg]);
            uint32_t a2 = __float_as_uint(Pw[g * PP + ks * 8 + tg + 4]);
            uint32_t a3 = __float_as_uint(Pw[(g + 8) * PP + ks * 8 + tg + 4]);
#pragma unroll
            for (int fn = 0; fn < 8; fn++) {
                int n = fn * 8 + g;
                uint32_t b0 = __float_as_uint(Vt[(ks * 8 + tg) * VP + n]);
                uint32_t b1 = __float_as_uint(Vt[(ks * 8 + tg + 4) * VP + n]);
                mma8(oacc[fn], a0, a1, a2, a3, b0, b1);
            }
        }
        __syncthreads();
    }
#undef AFILL

    // ---- epilogue: normalize, +bo, transpose-out write ---------------------
    float invA = 1.f / lrow[0], invB = 1.f / lrow[1];
    int b_ = bh >> 4, h = bh & 15;
#pragma unroll
    for (int fn = 0; fn < 8; fn++) {
        int col = fn * 8 + 2 * tg;
        float b0v = bo[col], b1v = bo[col + 1];
        int r0 = q0 + w * 16 + g, r1 = r0 + 8;
        *(float2*)(out + ((size_t)(b_ * Ss + r0)) * Dd + h * 64 + col) =
            make_float2(oacc[fn][0] * invA + b0v, oacc[fn][1] * invA + b1v);
        *(float2*)(out + ((size_t)(b_ * Ss + r1)) * Dd + h * 64 + col) =
            make_float2(oacc[fn][2] * invB + b0v, oacc[fn][3] * invB + b1v);
    }
}

// ---------------------------------------------------------------------------
extern "C" void kernel_launch(void* const* d_in, const int* in_sizes, int n_in,
                              void* d_out, int out_size) {
    const float* q   = (const float*)d_in[0];
    const float* k   = (const float*)d_in[1];
    const float* v   = (const float*)d_in[2];
    const int*   msk = (const int*)d_in[3];
    const float* Wq  = (const float*)d_in[4];
    const float* bq  = (const float*)d_in[5];
    const float* Wk  = (const float*)d_in[6];
    const float* bk  = (const float*)d_in[7];
    const float* Wv  = (const float*)d_in[8];
    const float* bv  = (const float*)d_in[9];
    const float* Wqf = (const float*)d_in[10];
    const float* bqf = (const float*)d_in[11];
    const float* Wkf = (const float*)d_in[12];
    const float* bkf = (const float*)d_in[13];
    const float* Wvf = (const float*)d_in[14];
    const float* bvf = (const float*)d_in[15];
    const float* Wo  = (const float*)d_in[16];
    const float* bo  = (const float*)d_in[17];
    float* out = (float*)d_out;

    const int bf_smem   = (2 * 128 * BP + 2 * 64 * BP) * 2;                               // 30720
    const int gemm_smem = (2 * 128 * GST + 2 * 64 * GST) * (int)sizeof(float);            // 55296
    const int attn_smem = 2 * 64 * KP * 2 + 2 * 64 * VP * 4 + 8 * 16 * PP * 4 + 2 * 64 * 4; // 94720

    static int cfg = 0;
    if (!cfg) {
        cudaFuncSetAttribute(gemm_bf, cudaFuncAttributeMaxDynamicSharedMemorySize, bf_smem);
        cudaFuncSetAttribute(gemm_tc, cudaFuncAttributeMaxDynamicSharedMemorySize, gemm_smem);
        cudaFuncSetAttribute(attn_tc, cudaFuncAttributeMaxDynamicSharedMemorySize, attn_smem);
        cfg = 1;
    }

    preround<<<4096, 256>>>(q, k, v);
    fold_kernel<<<dim3(16, 16, 3), 256>>>(Wq, Wqf, Wk, Wkf, Wv, Wvf);
    bfold_kernel<<<3, 1024>>>(bq, bqf, bk, bkf, bv, bvf, Wqf, Wkf, Wvf);
    gemm_bf<<<dim3(16, 32, 2), 256, bf_smem>>>();
    gemm_tc<<<dim3(16, 32), 256, gemm_smem>>>();
    vprime<<<dim3(16, 64), 256>>>(Wo);
    attn_tc<<<dim3(8, 64), 256, attn_smem>>>(msk, bo, out);
}

// round 5
// speedup vs baseline: 3.5369x; 1.1104x over previous
#include <cuda_runtime.h>
#include <cuda_bf16.h>
#include <math.h>
#include <stdint.h>

#define Bb 4
#define Ss 1024
#define Dd 1024
#define Hh 16
#define DKk 64

// Q pre-scale: 1/sqrt(64) * log2(e)  (softmax done in exp2 domain)
#define QSCALE 0.18033688011112042f
#define MASKVAL -14426.950408889634f

// ---------------------------------------------------------------------------
// Device scratch (allocation-free)
// ---------------------------------------------------------------------------
__device__ __nv_bfloat16 g_Xb[2][4096 * 1024];   // bf16 q,k inputs
__device__ float         g_Xr[4096 * 1024];      // tf32-rounded v input
__device__ __nv_bfloat16 g_Wcb[2][1024 * 1024];  // folded Wq,Wk (bf16)
__device__ float         g_Wc[1024 * 1024];      // folded Wv (tf32)
__device__ float         g_bc[3][1024];          // folded biases
__device__ __nv_bfloat16 g_Qb[64 * 1024 * 64];   // per-head Q (bf16, pre-scaled)
__device__ __nv_bfloat16 g_Kb[64 * 1024 * 64];   // per-head K (bf16)
__device__ float         g_Vp[64 * 1024 * 64];   // V' = V @ Wo^T (tf32), [bh][s][d]

// ---------------------------------------------------------------------------
// helpers
// ---------------------------------------------------------------------------
__device__ __forceinline__ uint32_t tf32r(float x) {
    uint32_t u; asm("cvt.rna.tf32.f32 %0, %1;" : "=r"(u) : "f"(x)); return u;
}
__device__ __forceinline__ float tf32f(float x) { return __uint_as_float(tf32r(x)); }
__device__ __forceinline__ void mma8(float (&d)[4], uint32_t a0, uint32_t a1, uint32_t a2,
                                     uint32_t a3, uint32_t b0, uint32_t b1) {
    asm volatile(
        "mma.sync.aligned.m16n8k8.row.col.f32.tf32.tf32.f32 "
        "{%0,%1,%2,%3},{%4,%5,%6,%7},{%8,%9},{%0,%1,%2,%3};"
        : "+f"(d[0]), "+f"(d[1]), "+f"(d[2]), "+f"(d[3])
        : "r"(a0), "r"(a1), "r"(a2), "r"(a3), "r"(b0), "r"(b1));
}
__device__ __forceinline__ void mma16(float (&d)[4], const uint32_t (&a)[4],
                                      uint32_t b0, uint32_t b1) {
    asm volatile(
        "mma.sync.aligned.m16n8k16.row.col.f32.bf16.bf16.f32 "
        "{%0,%1,%2,%3},{%4,%5,%6,%7},{%8,%9},{%0,%1,%2,%3};"
        : "+f"(d[0]), "+f"(d[1]), "+f"(d[2]), "+f"(d[3])
        : "r"(a[0]), "r"(a[1]), "r"(a[2]), "r"(a[3]), "r"(b0), "r"(b1));
}
__device__ __forceinline__ void ldsm4(uint32_t (&r)[4], const uint16_t* p) {
    uint32_t a = (uint32_t)__cvta_generic_to_shared(p);
    asm volatile("ldmatrix.sync.aligned.m8n8.x4.shared.b16 {%0,%1,%2,%3},[%4];"
                 : "=r"(r[0]), "=r"(r[1]), "=r"(r[2]), "=r"(r[3]) : "r"(a));
}
__device__ __forceinline__ void cp16(void* s, const void* g) {
    uint32_t sa = (uint32_t)__cvta_generic_to_shared(s);
    asm volatile("cp.async.cg.shared.global [%0], [%1], 16;" :: "r"(sa), "l"(g));
}
__device__ __forceinline__ uint32_t pack_bf2(float a, float b) {
    __nv_bfloat162 t = __float22bfloat162_rn(make_float2(a, b));
    return *reinterpret_cast<uint32_t*>(&t);
}
__device__ __forceinline__ float ex2f(float x) {
    float y; asm("ex2.approx.f32 %0,%1;" : "=f"(y) : "f"(x)); return y;
}

// ---------------------------------------------------------------------------
// preround: q,k -> bf16 ; v -> tf32-rounded f32
// ---------------------------------------------------------------------------
__global__ void preround(const float* __restrict__ q, const float* __restrict__ k,
                         const float* __restrict__ v) {
    size_t i = (size_t)blockIdx.x * blockDim.x + threadIdx.x;  // float4 index
    float4 a = ((const float4*)q)[i];
    uint32_t* dq = (uint32_t*)g_Xb[0];
    dq[i * 2] = pack_bf2(a.x, a.y); dq[i * 2 + 1] = pack_bf2(a.z, a.w);
    float4 b = ((const float4*)k)[i];
    uint32_t* dk = (uint32_t*)g_Xb[1];
    dk[i * 2] = pack_bf2(b.x, b.y); dk[i * 2 + 1] = pack_bf2(b.z, b.w);
    float4 c = ((const float4*)v)[i];
    float4 r; r.x = tf32f(c.x); r.y = tf32f(c.y); r.z = tf32f(c.z); r.w = tf32f(c.w);
    ((float4*)g_Xr)[i] = r;
}

// ---------------------------------------------------------------------------
// Fold: Wc[t][(h*64+o)*1024 + j] = sum_i Wf[o,i] * Wbig[h*64+i, j]
// t<2 -> bf16 (g_Wcb), t==2 -> tf32-rounded f32 (g_Wc)
// ---------------------------------------------------------------------------
__global__ void fold_kernel(const float* __restrict__ Wq, const float* __restrict__ Wqf,
                            const float* __restrict__ Wk, const float* __restrict__ Wkf,
                            const float* __restrict__ Wv, const float* __restrict__ Wvf) {
    int t = blockIdx.z, h = blockIdx.y, j0 = blockIdx.x * 64;
    const float* Wbig = (t == 0) ? Wq : (t == 1) ? Wk : Wv;
    const float* Wf   = (t == 0) ? Wqf : (t == 1) ? Wkf : Wvf;

    __shared__ float fs[64][65];
    __shared__ float bs[64][65];

    int tid = threadIdx.x;
    for (int idx = tid; idx < 64 * 16; idx += 256) {
        int r = idx >> 4, c4 = (idx & 15) * 4;
        float4 fv = *(const float4*)(Wf + r * 64 + c4);
        fs[r][c4] = fv.x; fs[r][c4 + 1] = fv.y; fs[r][c4 + 2] = fv.z; fs[r][c4 + 3] = fv.w;
        float4 bv = *(const float4*)(Wbig + (h * 64 + r) * Dd + j0 + c4);
        bs[r][c4] = bv.x; bs[r][c4 + 1] = bv.y; bs[r][c4 + 2] = bv.z; bs[r][c4 + 3] = bv.w;
    }
    __syncthreads();

    int ty = tid >> 4, tx = tid & 15;
    float acc[4][4] = {};
#pragma unroll 8
    for (int i = 0; i < 64; i++) {
        float a[4], b[4];
#pragma unroll
        for (int u = 0; u < 4; u++) { a[u] = fs[ty * 4 + u][i]; b[u] = bs[i][tx * 4 + u]; }
#pragma unroll
        for (int u = 0; u < 4; u++)
#pragma unroll
            for (int w = 0; w < 4; w++) acc[u][w] += a[u] * b[w];
    }
    if (t < 2) {
        uint32_t* dst = (uint32_t*)g_Wcb[t];
#pragma unroll
        for (int u = 0; u < 4; u++) {
            size_t row = (size_t)(h * 64 + ty * 4 + u) * Dd + j0 + tx * 4;
            dst[row / 2]     = pack_bf2(acc[u][0], acc[u][1]);
            dst[row / 2 + 1] = pack_bf2(acc[u][2], acc[u][3]);
        }
    } else {
        float* dst = g_Wc;
#pragma unroll
        for (int u = 0; u < 4; u++)
#pragma unroll
            for (int w = 0; w < 4; w++)
                dst[(size_t)(h * 64 + ty * 4 + u) * Dd + j0 + tx * 4 + w] = tf32f(acc[u][w]);
    }
}

__global__ void bfold_kernel(const float* __restrict__ bq, const float* __restrict__ bqf,
                             const float* __restrict__ bk, const float* __restrict__ bkf,
                             const float* __restrict__ bv, const float* __restrict__ bvf,
                             const float* __restrict__ Wqf, const float* __restrict__ Wkf,
                             const float* __restrict__ Wvf) {
    int t = blockIdx.x, n = threadIdx.x;
    const float* b1 = (t == 0) ? bq : (t == 1) ? bk : bv;
    const float* b2 = (t == 0) ? bqf : (t == 1) ? bkf : bvf;
    const float* Wf = (t == 0) ? Wqf : (t == 1) ? Wkf : Wvf;
    int h = n >> 6, o = n & 63;
    float s = b2[o];
    for (int i = 0; i < 64; i++) s += Wf[o * 64 + i] * b1[h * 64 + i];
    g_bc[t][n] = s;
}

// ---------------------------------------------------------------------------
// bf16 projection GEMM (Q and K): Y = relu(Xb @ Wcb^T + bc) -> bf16 per-head
// t==0 scaled by QSCALE. BM=128, BN=64(head), BK=32. 8 warps, ldmatrix,
// 3-stage cp.async. smem: 3 x (128+64) x 40 u16 = 46080 B
// ---------------------------------------------------------------------------
#define BP 40
__global__ __launch_bounds__(256) void gemm_bf() {
    extern __shared__ uint16_t sb[];

    int t = blockIdx.z;
    const __nv_bfloat16* X = g_Xb[t];
    const __nv_bfloat16* W = g_Wcb[t];
    const float* bias = g_bc[t];
    __nv_bfloat16* Y = (t == 0) ? g_Qb : g_Kb;
    float sc = (t == 0) ? QSCALE : 1.0f;
    int head = blockIdx.x, m0 = blockIdx.y * 128;

    int tid = threadIdx.x;
    int w = tid >> 5, lane = tid & 31, g = lane >> 2, tg = lane & 3;
    int wm = w & 3, wn = w >> 2;

    const int loA40 = ((lane & 7) + ((lane >> 3) & 1) * 8) * BP + ((lane >> 4) & 1) * 8;
    const int loB40 = ((lane & 7) + ((lane >> 4) & 1) * 8) * BP + ((lane >> 3) & 1) * 8;

    float acc[2][4][4] = {};

#define BLOAD(I, S)                                                                     \
    do {                                                                                \
        uint16_t* Xd = sb + (S) * 7680;                                                 \
        uint16_t* Wd = Xd + 128 * BP;                                                   \
        int k0_ = (I) * 32;                                                             \
        _Pragma("unroll")                                                               \
        for (int j = 0; j < 2; j++) {                                                   \
            int idx = tid + j * 256; int r = idx >> 2, c = (idx & 3) * 8;               \
            cp16(Xd + r * BP + c, (const uint16_t*)X + (size_t)(m0 + r) * Dd + k0_ + c);\
        }                                                                               \
        {                                                                               \
            int r = tid >> 2, c = (tid & 3) * 8;                                        \
            cp16(Wd + r * BP + c,                                                       \
                 (const uint16_t*)W + (size_t)(head * 64 + r) * Dd + k0_ + c);          \
        }                                                                               \
    } while (0)

    BLOAD(0, 0);
    asm volatile("cp.async.commit_group;");
    BLOAD(1, 1);
    asm volatile("cp.async.commit_group;");

    for (int i = 0; i < 32; i++) {
        asm volatile("cp.async.wait_group 1;");
        __syncthreads();
        if (i + 2 < 32) BLOAD(i + 2, (i + 2) % 3);
        asm volatile("cp.async.commit_group;");

        const uint16_t* Xb_ = sb + (i % 3) * 7680;
        const uint16_t* Wb_ = Xb_ + 128 * BP;
#pragma unroll
        for (int ks = 0; ks < 2; ks++) {
            uint32_t a[2][4], b[2][4];
            ldsm4(a[0], Xb_ + (wm * 32) * BP + ks * 16 + loA40);
            ldsm4(a[1], Xb_ + (wm * 32 + 16) * BP + ks * 16 + loA40);
            ldsm4(b[0], Wb_ + (wn * 32) * BP + ks * 16 + loB40);
            ldsm4(b[1], Wb_ + (wn * 32 + 16) * BP + ks * 16 + loB40);
#pragma unroll
            for (int fm = 0; fm < 2; fm++) {
                mma16(acc[fm][0], a[fm], b[0][0], b[0][1]);
                mma16(acc[fm][1], a[fm], b[0][2], b[0][3]);
                mma16(acc[fm][2], a[fm], b[1][0], b[1][1]);
                mma16(acc[fm][3], a[fm], b[1][2], b[1][3]);
            }
        }
    }
#undef BLOAD

#pragma unroll
    for (int fm = 0; fm < 2; fm++) {
#pragma unroll
        for (int fn = 0; fn < 4; fn++) {
            int col = wn * 32 + fn * 8 + 2 * tg;
            float b0 = bias[head * 64 + col], b1 = bias[head * 64 + col + 1];
            int r0 = m0 + wm * 32 + fm * 16 + g, r1 = r0 + 8;
            uint32_t v0 = pack_bf2(fmaxf(acc[fm][fn][0] + b0, 0.f) * sc,
                                   fmaxf(acc[fm][fn][1] + b1, 0.f) * sc);
            uint32_t v1 = pack_bf2(fmaxf(acc[fm][fn][2] + b0, 0.f) * sc,
                                   fmaxf(acc[fm][fn][3] + b1, 0.f) * sc);
            {
                int b_ = r0 >> 10, s = r0 & 1023;
                *(uint32_t*)((uint16_t*)Y + (((size_t)(b_ * Hh + head)) * Ss + s) * DKk + col) = v0;
            }
            {
                int b_ = r1 >> 10, s = r1 & 1023;
                *(uint32_t*)((uint16_t*)Y + (((size_t)(b_ * Hh + head)) * Ss + s) * DKk + col) = v1;
            }
        }
    }
}

// ---------------------------------------------------------------------------
// tf32 projection GEMM (V) + FUSED V' = V @ Wo^T epilogue (tf32 pass 2).
// Mainloop: V = relu(g_Xr @ g_Wc^T + bc[2]) in registers.
// Pass 2 : stage V to smem, Wo (tf32) to smem, D[s][o] = sum_d V[s,d]Wo[o,d],
//          store tf32 f32 to g_Vp[bh][s][d].
// ---------------------------------------------------------------------------
#define GST 36
#define P2 68
__global__ __launch_bounds__(256) void gemm_tc(const float* __restrict__ Wo) {
    extern __shared__ float sm[];
    float* Xs = sm;                  // [2][128][GST]
    float* Ws = sm + 2 * 128 * GST;  // [2][64][GST]

    const float* X = g_Xr;
    const float* W = g_Wc;
    const float* bias = g_bc[2];
    int head = blockIdx.x, m0 = blockIdx.y * 128;

    int tid = threadIdx.x;
    int w = tid >> 5, lane = tid & 31, g = lane >> 2, tg = lane & 3;
    int wm = w & 3, wn = w >> 2;

    float acc[2][4][4] = {};

#define VLOAD(I, BUF)                                                                  \
    do {                                                                               \
        int k0_ = (I) * 32;                                                            \
        _Pragma("unroll")                                                              \
        for (int j = 0; j < 4; j++) {                                                  \
            int idx = tid + j * 256; int r = idx >> 3, c = (idx & 7) * 4;              \
            cp16(&Xs[((BUF) * 128 + r) * GST + c],                                     \
                 X + (size_t)(m0 + r) * Dd + k0_ + c);                                 \
        }                                                                              \
        _Pragma("unroll")                                                              \
        for (int j = 0; j < 2; j++) {                                                  \
            int idx = tid + j * 256; int r = idx >> 3, c = (idx & 7) * 4;              \
            cp16(&Ws[((BUF) * 64 + r) * GST + c],                                      \
                 W + (size_t)(head * 64 + r) * Dd + k0_ + c);                          \
        }                                                                              \
        asm volatile("cp.async.commit_group;");                                       \
    } while (0)

    VLOAD(0, 0);
    for (int i = 0; i < 32; i++) {
        int buf = i & 1;
        if (i < 31) {
            VLOAD(i + 1, buf ^ 1);
            asm volatile("cp.async.wait_group 1;");
        } else {
            asm volatile("cp.async.wait_group 0;");
        }
        __syncthreads();
        float* Xb = &Xs[buf * 128 * GST];
        float* Wb = &Ws[buf * 64 * GST];
#pragma unroll
        for (int ks = 0; ks < 4; ks++) {
            int kk = ks * 8;
            uint32_t a[2][4];
#pragma unroll
            for (int fm = 0; fm < 2; fm++) {
                int r = wm * 32 + fm * 16 + g;
                a[fm][0] = __float_as_uint(Xb[r * GST + kk + tg]);
                a[fm][1] = __float_as_uint(Xb[(r + 8) * GST + kk + tg]);
                a[fm][2] = __float_as_uint(Xb[r * GST + kk + tg + 4]);
                a[fm][3] = __float_as_uint(Xb[(r + 8) * GST + kk + tg + 4]);
            }
#pragma unroll
            for (int fn = 0; fn < 4; fn++) {
                int n = wn * 32 + fn * 8 + g;
                uint32_t b0 = __float_as_uint(Wb[n * GST + kk + tg]);
                uint32_t b1 = __float_as_uint(Wb[n * GST + kk + tg + 4]);
                mma8(acc[0][fn], a[0][0], a[0][1], a[0][2], a[0][3], b0, b1);
                mma8(acc[1][fn], a[1][0], a[1][1], a[1][2], a[1][3], b0, b1);
            }
        }
        __syncthreads();
    }
#undef VLOAD

    // ---- pass 2: V' = V @ Wo^T (tf32) ---------------------------------------
    float* Vt  = sm;               // [128][P2] f32  (34816 B)
    float* WoS = sm + 128 * P2;    // [64][P2]  f32  (17408 B)

    // stage relu'd V tile (tf32-rounded)
#pragma unroll
    for (int fm = 0; fm < 2; fm++) {
#pragma unroll
        for (int fn = 0; fn < 4; fn++) {
            int col = wn * 32 + fn * 8 + 2 * tg;
            float b0 = bias[head * 64 + col], b1 = bias[head * 64 + col + 1];
            int lr0 = wm * 32 + fm * 16 + g, lr1 = lr0 + 8;
            Vt[lr0 * P2 + col]     = tf32f(fmaxf(acc[fm][fn][0] + b0, 0.f));
            Vt[lr0 * P2 + col + 1] = tf32f(fmaxf(acc[fm][fn][1] + b1, 0.f));
            Vt[lr1 * P2 + col]     = tf32f(fmaxf(acc[fm][fn][2] + b0, 0.f));
            Vt[lr1 * P2 + col + 1] = tf32f(fmaxf(acc[fm][fn][3] + b1, 0.f));
        }
    }
    // stage Wo (tf32-rounded): WoS[o][d]
#pragma unroll
    for (int j = 0; j < 4; j++) {
        int idx = tid + j * 256; int r = idx >> 4, c = (idx & 15) * 4;
        float4 wv = *(const float4*)(Wo + r * 64 + c);
        WoS[r * P2 + c]     = tf32f(wv.x);
        WoS[r * P2 + c + 1] = tf32f(wv.y);
        WoS[r * P2 + c + 2] = tf32f(wv.z);
        WoS[r * P2 + c + 3] = tf32f(wv.w);
    }
    __syncthreads();

    // D[s][o] = sum_d V[s,d] * Wo[o,d] ; m=s(128), n=o(64), k=d(64)
    float acc2[2][4][4] = {};
#pragma unroll
    for (int ks = 0; ks < 8; ks++) {
        int kk = ks * 8;
        uint32_t a[2][4];
#pragma unroll
        for (int fm = 0; fm < 2; fm++) {
            int r = wm * 32 + fm * 16 + g;
            a[fm][0] = __float_as_uint(Vt[r * P2 + kk + tg]);
            a[fm][1] = __float_as_uint(Vt[(r + 8) * P2 + kk + tg]);
            a[fm][2] = __float_as_uint(Vt[r * P2 + kk + tg + 4]);
            a[fm][3] = __float_as_uint(Vt[(r + 8) * P2 + kk + tg + 4]);
        }
#pragma unroll
        for (int fn = 0; fn < 4; fn++) {
            int n = wn * 32 + fn * 8 + g;
            uint32_t b0 = __float_as_uint(WoS[n * P2 + kk + tg]);
            uint32_t b1 = __float_as_uint(WoS[n * P2 + kk + tg + 4]);
            mma8(acc2[0][fn], a[0][0], a[0][1], a[0][2], a[0][3], b0, b1);
            mma8(acc2[1][fn], a[1][0], a[1][1], a[1][2], a[1][3], b0, b1);
        }
    }

    // store V' (tf32-rounded) to g_Vp[bh][s][d]
    int b_ = m0 >> 10, s0 = m0 & 1023;
    int bh = b_ * Hh + head;
    float* dst = g_Vp + (((size_t)bh * Ss) + s0) * DKk;
#pragma unroll
    for (int fm = 0; fm < 2; fm++) {
#pragma unroll
        for (int fn = 0; fn < 4; fn++) {
            int col = wn * 32 + fn * 8 + 2 * tg;
            int lr0 = wm * 32 + fm * 16 + g, lr1 = lr0 + 8;
            *(float2*)(dst + (size_t)lr0 * DKk + col) =
                make_float2(tf32f(acc2[0][fn][0]), tf32f(acc2[0][fn][1]));
            *(float2*)(dst + (size_t)lr1 * DKk + col) =
                make_float2(tf32f(acc2[0][fn][2]), tf32f(acc2[0][fn][3]));
            (void)acc2;
        }
    }
    // second half of rows handled by fm index above writes acc2[0]; write acc2[1]:
#pragma unroll
    for (int fn = 0; fn < 4; fn++) {
        int col = wn * 32 + fn * 8 + 2 * tg;
        int lr0 = wm * 32 + 16 + g, lr1 = lr0 + 8;
        *(float2*)(dst + (size_t)lr0 * DKk + col) =
            make_float2(tf32f(acc2[1][fn][0]), tf32f(acc2[1][fn][1]));
        *(float2*)(dst + (size_t)lr1 * DKk + col) =
            make_float2(tf32f(acc2[1][fn][2]), tf32f(acc2[1][fn][3]));
    }
}

// ---------------------------------------------------------------------------
// Flash attention: S-phase bf16 ldmatrix (Q pre-scaled, exp2 softmax),
// PV-phase tf32 (P staged tf32, V' f32). 128 q-rows/CTA, 8 warps.
// smem: Kb bf16[2][64][72] + Vb f32[2][64][72] + Ps f32[8][16][76] + ms = 94720 B
// ---------------------------------------------------------------------------
#define KP 72
#define VP 72
#define PP 76
__global__ __launch_bounds__(256) void attn_tc(const int* __restrict__ mask,
                                               const float* __restrict__ bo,
                                               float* __restrict__ out) {
    extern __shared__ char smraw[];
    uint16_t* Kb = (uint16_t*)smraw;                   // [2][64][KP]  18432 B
    float* Vb = (float*)(smraw + 18432);               // [2][64][VP]  36864 B
    float* Ps = (float*)(smraw + 55296);               // [8][16][PP]  38912 B
    int* ms = (int*)(smraw + 94208);                   // [2][64]        512 B

    int bh = blockIdx.y, q0 = blockIdx.x * 128;
    const uint16_t* Qg = (const uint16_t*)g_Qb + ((size_t)bh * Ss + q0) * DKk;
    const uint16_t* Kg = (const uint16_t*)g_Kb + (size_t)bh * Ss * DKk;
    const float* Vg = g_Vp + (size_t)bh * Ss * DKk;

    int tid = threadIdx.x, w = tid >> 5, lane = tid & 31, g = lane >> 2, tg = lane & 3;
    const int loA72 = ((lane & 7) + ((lane >> 3) & 1) * 8) * KP + ((lane >> 4) & 1) * 8;
    const int loB72 = ((lane & 7) + ((lane >> 4) & 1) * 8) * KP + ((lane >> 3) & 1) * 8;

    // ---- stage Q (bf16) through Ps region, extract A-fragments --------------
    {
        uint16_t* Qs = (uint16_t*)Ps;  // [128][KP] u16, 18432 B
#pragma unroll
        for (int j = 0; j < 4; j++) {
            int idx = tid + j * 256; int r = idx >> 3, c = (idx & 7) * 8;
            *(uint4*)(Qs + r * KP + c) = *(const uint4*)(Qg + (size_t)r * DKk + c);
        }
    }
    __syncthreads();
    uint32_t qa[4][4];
#pragma unroll
    for (int ks = 0; ks < 4; ks++)
        ldsm4(qa[ks], (const uint16_t*)Ps + w * 16 * KP + ks * 16 + loA72);
    float* Pw = Ps + w * 16 * PP;
    __syncthreads();

#define AFILL(KT, BUF)                                                                  \
    do {                                                                                \
        const uint16_t* kg = Kg + (size_t)(KT) * 64 * DKk;                              \
        const float* vg = Vg + (size_t)(KT) * 64 * DKk;                                 \
        _Pragma("unroll")                                                               \
        for (int j = 0; j < 2; j++) {                                                   \
            int idx = tid + j * 256; int r = idx >> 3, c = (idx & 7) * 8;               \
            cp16(Kb + ((BUF) * 64 + r) * KP + c, kg + (size_t)r * DKk + c);             \
        }                                                                               \
        _Pragma("unroll")                                                               \
        for (int j = 0; j < 4; j++) {                                                   \
            int idx = tid + j * 256; int r = idx >> 4, c = (idx & 15) * 4;              \
            cp16(Vb + ((BUF) * 64 + r) * VP + c, vg + (size_t)r * DKk + c);             \
        }                                                                               \
        if (tid < 16)                                                                   \
            cp16(ms + (BUF) * 64 + tid * 4, mask + (size_t)bh * Ss + (KT) * 64 + tid * 4); \
        asm volatile("cp.async.commit_group;");                                        \
    } while (0)

    float oacc[8][4] = {};
    float mrow[2] = {-1e30f, -1e30f};
    float lrow[2] = {0.f, 0.f};

    AFILL(0, 0);
    for (int kt = 0; kt < 16; kt++) {
        int buf = kt & 1;
        if (kt < 15) {
            AFILL(kt + 1, buf ^ 1);
            asm volatile("cp.async.wait_group 1;");
        } else {
            asm volatile("cp.async.wait_group 0;");
        }
        __syncthreads();
        const uint16_t* Kt = Kb + buf * 64 * KP;
        const float* Vt = Vb + buf * 64 * VP;
        const int* mt = ms + buf * 64;

        // ---- S = Q' @ K^T (bf16, exp2 domain) -------------------------------
        float sacc[8][4] = {};
#pragma unroll
        for (int ks = 0; ks < 4; ks++) {
#pragma unroll
            for (int fnp = 0; fnp < 4; fnp++) {
                uint32_t b[4];
                ldsm4(b, Kt + fnp * 16 * KP + ks * 16 + loB72);
                mma16(sacc[2 * fnp],     qa[ks], b[0], b[1]);
                mma16(sacc[2 * fnp + 1], qa[ks], b[2], b[3]);
            }
        }
        // mask
#pragma unroll
        for (int fn = 0; fn < 8; fn++) {
            int c0 = fn * 8 + 2 * tg;
            bool k0m = (mt[c0] == 0), k1m = (mt[c0 + 1] == 0);
            if (k0m) { sacc[fn][0] = MASKVAL; sacc[fn][2] = MASKVAL; }
            if (k1m) { sacc[fn][1] = MASKVAL; sacc[fn][3] = MASKVAL; }
        }
        // online softmax (rows g and g+8), exp2 domain
        float mxA = -1e30f, mxB = -1e30f;
#pragma unroll
        for (int fn = 0; fn < 8; fn++) {
            mxA = fmaxf(mxA, fmaxf(sacc[fn][0], sacc[fn][1]));
            mxB = fmaxf(mxB, fmaxf(sacc[fn][2], sacc[fn][3]));
        }
        mxA = fmaxf(mxA, __shfl_xor_sync(~0u, mxA, 1));
        mxA = fmaxf(mxA, __shfl_xor_sync(~0u, mxA, 2));
        mxB = fmaxf(mxB, __shfl_xor_sync(~0u, mxB, 1));
        mxB = fmaxf(mxB, __shfl_xor_sync(~0u, mxB, 2));
        float mAn = fmaxf(mrow[0], mxA), mBn = fmaxf(mrow[1], mxB);
        float aA = ex2f(mrow[0] - mAn), aB = ex2f(mrow[1] - mBn);
        mrow[0] = mAn; mrow[1] = mBn;
        float sA = 0.f, sB = 0.f;
#pragma unroll
        for (int fn = 0; fn < 8; fn++) {
            sacc[fn][0] = ex2f(sacc[fn][0] - mAn);
            sacc[fn][1] = ex2f(sacc[fn][1] - mAn);
            sacc[fn][2] = ex2f(sacc[fn][2] - mBn);
            sacc[fn][3] = ex2f(sacc[fn][3] - mBn);
            sA += sacc[fn][0] + sacc[fn][1];
            sB += sacc[fn][2] + sacc[fn][3];
        }
        sA += __shfl_xor_sync(~0u, sA, 1); sA += __shfl_xor_sync(~0u, sA, 2);
        sB += __shfl_xor_sync(~0u, sB, 1); sB += __shfl_xor_sync(~0u, sB, 2);
        lrow[0] = lrow[0] * aA + sA;
        lrow[1] = lrow[1] * aB + sB;
#pragma unroll
        for (int fn = 0; fn < 8; fn++) {
            oacc[fn][0] *= aA; oacc[fn][1] *= aA; oacc[fn][2] *= aB; oacc[fn][3] *= aB;
        }
        // stage P (tf32-rounded f32) in per-warp smem
#pragma unroll
        for (int fn = 0; fn < 8; fn++) {
            int c0 = fn * 8 + 2 * tg;
            *(float2*)(Pw + g * PP + c0)       = make_float2(tf32f(sacc[fn][0]), tf32f(sacc[fn][1]));
            *(float2*)(Pw + (g + 8) * PP + c0) = make_float2(tf32f(sacc[fn][2]), tf32f(sacc[fn][3]));
        }
        __syncwarp();
        // ---- O += P @ V' (tf32) ----------------------------------------------
#pragma unroll
        for (int ks = 0; ks < 8; ks++) {
            uint32_t a0 = __float_as_uint(Pw[g * PP + ks * 8 + tg]);
            uint32_t a1 = __float_as_uint(Pw[(g + 8) * PP + ks * 8 + tg]);
            uint32_t a2 = __float_as_uint(Pw[g * PP + ks * 8 + tg + 4]);
            uint32_t a3 = __float_as_uint(Pw[(g + 8) * PP + ks * 8 + tg + 4]);
#pragma unroll
            for (int fn = 0; fn < 8; fn++) {
                int n = fn * 8 + g;
                uint32_t b0 = __float_as_uint(Vt[(ks * 8 + tg) * VP + n]);
                uint32_t b1 = __float_as_uint(Vt[(ks * 8 + tg + 4) * VP + n]);
                mma8(oacc[fn], a0, a1, a2, a3, b0, b1);
            }
        }
        __syncthreads();
    }
#undef AFILL

    // ---- epilogue: normalize, +bo, transpose-out write ----------------------
    float invA = 1.f / lrow[0], invB = 1.f / lrow[1];
    int b_ = bh >> 4, h = bh & 15;
#pragma unroll
    for (int fn = 0; fn < 8; fn++) {
        int col = fn * 8 + 2 * tg;
        float b0v = bo[col], b1v = bo[col + 1];
        int r0 = q0 + w * 16 + g, r1 = r0 + 8;
        *(float2*)(out + ((size_t)(b_ * Ss + r0)) * Dd + h * 64 + col) =
            make_float2(oacc[fn][0] * invA + b0v, oacc[fn][1] * invA + b1v);
        *(float2*)(out + ((size_t)(b_ * Ss + r1)) * Dd + h * 64 + col) =
            make_float2(oacc[fn][2] * invB + b0v, oacc[fn][3] * invB + b1v);
    }
}

// ---------------------------------------------------------------------------
extern "C" void kernel_launch(void* const* d_in, const int* in_sizes, int n_in,
                              void* d_out, int out_size) {
    const float* q   = (const float*)d_in[0];
    const float* k   = (const float*)d_in[1];
    const float* v   = (const float*)d_in[2];
    const int*   msk = (const int*)d_in[3];
    const float* Wq  = (const float*)d_in[4];
    const float* bq  = (const float*)d_in[5];
    const float* Wk  = (const float*)d_in[6];
    const float* bk  = (const float*)d_in[7];
    const float* Wv  = (const float*)d_in[8];
    const float* bv  = (const float*)d_in[9];
    const float* Wqf = (const float*)d_in[10];
    const float* bqf = (const float*)d_in[11];
    const float* Wkf = (const float*)d_in[12];
    const float* bkf = (const float*)d_in[13];
    const float* Wvf = (const float*)d_in[14];
    const float* bvf = (const float*)d_in[15];
    const float* Wo  = (const float*)d_in[16];
    const float* bo  = (const float*)d_in[17];
    float* out = (float*)d_out;

    const int bf_smem   = 3 * (128 + 64) * BP * 2;                              // 46080
    const int gemm_smem = (2 * 128 * GST + 2 * 64 * GST) * (int)sizeof(float);  // 55296
    const int attn_smem = 94720;

    static int cfg = 0;
    if (!cfg) {
        cudaFuncSetAttribute(gemm_bf, cudaFuncAttributeMaxDynamicSharedMemorySize, bf_smem);
        cudaFuncSetAttribute(gemm_tc, cudaFuncAttributeMaxDynamicSharedMemorySize, gemm_smem);
        cudaFuncSetAttribute(attn_tc, cudaFuncAttributeMaxDynamicSharedMemorySize, attn_smem);
        cfg = 1;
    }

    preround<<<4096, 256>>>(q, k, v);
    fold_kernel<<<dim3(16, 16, 3), 256>>>(Wq, Wqf, Wk, Wkf, Wv, Wvf);
    bfold_kernel<<<3, 1024>>>(bq, bqf, bk, bkf, bv, bvf, Wqf, Wkf, Wvf);
    gemm_bf<<<dim3(16, 32, 2), 256, bf_smem>>>();
    gemm_tc<<<dim3(16, 32), 256, gemm_smem>>>(Wo);
    attn_tc<<<dim3(8, 64), 256, attn_smem>>>(msk, bo, out);
}

// round 7
// speedup vs baseline: 4.7556x; 1.3446x over previous
#include <cuda_runtime.h>
#include <cuda_bf16.h>
#include <cuda_fp16.h>
#include <math.h>
#include <stdint.h>

#define Bb 4
#define Ss 1024
#define Dd 1024
#define Hh 16
#define DKk 64

#define QSCALE 0.18033688011112042f
#define MASKVAL -14426.950408889634f

// ---------------------------------------------------------------------------
// Device scratch
// ---------------------------------------------------------------------------
__device__ __nv_bfloat16 g_Xb[2][4096 * 1024];   // bf16 q,k inputs
__device__ __half        g_Xf[4096 * 1024];      // fp16 v input
__device__ __nv_bfloat16 g_Wcb[2][1024 * 1024];  // folded Wq,Wk (bf16)
__device__ __half        g_Wcf[1024 * 1024];     // folded Wv (fp16)
__device__ float         g_bc[3][1024];          // folded biases
__device__ __nv_bfloat16 g_Qb[64 * 1024 * 64];   // per-head Q (bf16, pre-scaled)
__device__ __nv_bfloat16 g_Kb[64 * 1024 * 64];   // per-head K (bf16)
__device__ __half        g_Vp[64 * 1024 * 64];   // V' = V @ Wo^T (fp16) [bh][s][d]

// ---------------------------------------------------------------------------
// helpers
// ---------------------------------------------------------------------------
__device__ __forceinline__ void mma16(float (&d)[4], const uint32_t (&a)[4],
                                      uint32_t b0, uint32_t b1) {
    asm volatile(
        "mma.sync.aligned.m16n8k16.row.col.f32.bf16.bf16.f32 "
        "{%0,%1,%2,%3},{%4,%5,%6,%7},{%8,%9},{%0,%1,%2,%3};"
        : "+f"(d[0]), "+f"(d[1]), "+f"(d[2]), "+f"(d[3])
        : "r"(a[0]), "r"(a[1]), "r"(a[2]), "r"(a[3]), "r"(b0), "r"(b1));
}
__device__ __forceinline__ void mma16f(float (&d)[4], const uint32_t (&a)[4],
                                       uint32_t b0, uint32_t b1) {
    asm volatile(
        "mma.sync.aligned.m16n8k16.row.col.f32.f16.f16.f32 "
        "{%0,%1,%2,%3},{%4,%5,%6,%7},{%8,%9},{%0,%1,%2,%3};"
        : "+f"(d[0]), "+f"(d[1]), "+f"(d[2]), "+f"(d[3])
        : "r"(a[0]), "r"(a[1]), "r"(a[2]), "r"(a[3]), "r"(b0), "r"(b1));
}
__device__ __forceinline__ void ldsm4(uint32_t (&r)[4], const uint16_t* p) {
    uint32_t a = (uint32_t)__cvta_generic_to_shared(p);
    asm volatile("ldmatrix.sync.aligned.m8n8.x4.shared.b16 {%0,%1,%2,%3},[%4];"
                 : "=r"(r[0]), "=r"(r[1]), "=r"(r[2]), "=r"(r[3]) : "r"(a));
}
__device__ __forceinline__ void ldsm4t(uint32_t (&r)[4], const uint16_t* p) {
    uint32_t a = (uint32_t)__cvta_generic_to_shared(p);
    asm volatile("ldmatrix.sync.aligned.m8n8.x4.trans.shared.b16 {%0,%1,%2,%3},[%4];"
                 : "=r"(r[0]), "=r"(r[1]), "=r"(r[2]), "=r"(r[3]) : "r"(a));
}
__device__ __forceinline__ void cp16(void* s, const void* g) {
    uint32_t sa = (uint32_t)__cvta_generic_to_shared(s);
    asm volatile("cp.async.cg.shared.global [%0], [%1], 16;" :: "r"(sa), "l"(g));
}
__device__ __forceinline__ uint32_t pack_bf2(float a, float b) {
    __nv_bfloat162 t = __float22bfloat162_rn(make_float2(a, b));
    return *reinterpret_cast<uint32_t*>(&t);
}
__device__ __forceinline__ uint32_t pack_hf2(float a, float b) {
    __half2 t = __floats2half2_rn(a, b);
    return *reinterpret_cast<uint32_t*>(&t);
}
__device__ __forceinline__ float ex2f(float x) {
    float y; asm("ex2.approx.f32 %0,%1;" : "=f"(y) : "f"(x)); return y;
}

// ---------------------------------------------------------------------------
// preround: q,k -> bf16 ; v -> fp16
// ---------------------------------------------------------------------------
__global__ void preround(const float* __restrict__ q, const float* __restrict__ k,
                         const float* __restrict__ v) {
    size_t i = (size_t)blockIdx.x * blockDim.x + threadIdx.x;  // float4 index
    float4 a = ((const float4*)q)[i];
    uint32_t* dq = (uint32_t*)g_Xb[0];
    dq[i * 2] = pack_bf2(a.x, a.y); dq[i * 2 + 1] = pack_bf2(a.z, a.w);
    float4 b = ((const float4*)k)[i];
    uint32_t* dk = (uint32_t*)g_Xb[1];
    dk[i * 2] = pack_bf2(b.x, b.y); dk[i * 2 + 1] = pack_bf2(b.z, b.w);
    float4 c = ((const float4*)v)[i];
    uint32_t* dv = (uint32_t*)g_Xf;
    dv[i * 2] = pack_hf2(c.x, c.y); dv[i * 2 + 1] = pack_hf2(c.z, c.w);
}

// ---------------------------------------------------------------------------
// Fold: Wc[t][(h*64+o)*1024 + j] = sum_i Wf[o,i] * Wbig[h*64+i, j]
// t<2 -> bf16 (g_Wcb), t==2 -> fp16 (g_Wcf)
// ---------------------------------------------------------------------------
__global__ void fold_kernel(const float* __restrict__ Wq, const float* __restrict__ Wqf,
                            const float* __restrict__ Wk, const float* __restrict__ Wkf,
                            const float* __restrict__ Wv, const float* __restrict__ Wvf) {
    int t = blockIdx.z, h = blockIdx.y, j0 = blockIdx.x * 64;
    const float* Wbig = (t == 0) ? Wq : (t == 1) ? Wk : Wv;
    const float* Wf   = (t == 0) ? Wqf : (t == 1) ? Wkf : Wvf;

    __shared__ float fs[64][65];
    __shared__ float bs[64][65];

    int tid = threadIdx.x;
    for (int idx = tid; idx < 64 * 16; idx += 256) {
        int r = idx >> 4, c4 = (idx & 15) * 4;
        float4 fv = *(const float4*)(Wf + r * 64 + c4);
        fs[r][c4] = fv.x; fs[r][c4 + 1] = fv.y; fs[r][c4 + 2] = fv.z; fs[r][c4 + 3] = fv.w;
        float4 bv = *(const float4*)(Wbig + (h * 64 + r) * Dd + j0 + c4);
        bs[r][c4] = bv.x; bs[r][c4 + 1] = bv.y; bs[r][c4 + 2] = bv.z; bs[r][c4 + 3] = bv.w;
    }
    __syncthreads();

    int ty = tid >> 4, tx = tid & 15;
    float acc[4][4] = {};
#pragma unroll 8
    for (int i = 0; i < 64; i++) {
        float a[4], b[4];
#pragma unroll
        for (int u = 0; u < 4; u++) { a[u] = fs[ty * 4 + u][i]; b[u] = bs[i][tx * 4 + u]; }
#pragma unroll
        for (int u = 0; u < 4; u++)
#pragma unroll
            for (int w = 0; w < 4; w++) acc[u][w] += a[u] * b[w];
    }
    if (t < 2) {
        uint32_t* dst = (uint32_t*)g_Wcb[t];
#pragma unroll
        for (int u = 0; u < 4; u++) {
            size_t row = (size_t)(h * 64 + ty * 4 + u) * Dd + j0 + tx * 4;
            dst[row / 2]     = pack_bf2(acc[u][0], acc[u][1]);
            dst[row / 2 + 1] = pack_bf2(acc[u][2], acc[u][3]);
        }
    } else {
        uint32_t* dst = (uint32_t*)g_Wcf;
#pragma unroll
        for (int u = 0; u < 4; u++) {
            size_t row = (size_t)(h * 64 + ty * 4 + u) * Dd + j0 + tx * 4;
            dst[row / 2]     = pack_hf2(acc[u][0], acc[u][1]);
            dst[row / 2 + 1] = pack_hf2(acc[u][2], acc[u][3]);
        }
    }
}

__global__ void bfold_kernel(const float* __restrict__ bq, const float* __restrict__ bqf,
                             const float* __restrict__ bk, const float* __restrict__ bkf,
                             const float* __restrict__ bv, const float* __restrict__ bvf,
                             const float* __restrict__ Wqf, const float* __restrict__ Wkf,
                             const float* __restrict__ Wvf) {
    int t = blockIdx.x, n = threadIdx.x;
    const float* b1 = (t == 0) ? bq : (t == 1) ? bk : bv;
    const float* b2 = (t == 0) ? bqf : (t == 1) ? bkf : bvf;
    const float* Wf = (t == 0) ? Wqf : (t == 1) ? Wkf : Wvf;
    int h = n >> 6, o = n & 63;
    float s = b2[o];
    for (int i = 0; i < 64; i++) s += Wf[o * 64 + i] * b1[h * 64 + i];
    g_bc[t][n] = s;
}

// ---------------------------------------------------------------------------
// bf16 projection GEMM (Q and K) — unchanged from round 5 (passing).
// ---------------------------------------------------------------------------
#define BP 40
__global__ __launch_bounds__(256) void gemm_bf() {
    extern __shared__ uint16_t sb[];

    int t = blockIdx.z;
    const __nv_bfloat16* X = g_Xb[t];
    const __nv_bfloat16* W = g_Wcb[t];
    const float* bias = g_bc[t];
    __nv_bfloat16* Y = (t == 0) ? g_Qb : g_Kb;
    float sc = (t == 0) ? QSCALE : 1.0f;
    int head = blockIdx.x, m0 = blockIdx.y * 128;

    int tid = threadIdx.x;
    int w = tid >> 5, lane = tid & 31, g = lane >> 2, tg = lane & 3;
    int wm = w & 3, wn = w >> 2;

    const int loA40 = ((lane & 7) + ((lane >> 3) & 1) * 8) * BP + ((lane >> 4) & 1) * 8;
    const int loB40 = ((lane & 7) + ((lane >> 4) & 1) * 8) * BP + ((lane >> 3) & 1) * 8;

    float acc[2][4][4] = {};

#define BLOAD(I, S)                                                                     \
    do {                                                                                \
        uint16_t* Xd = sb + (S) * 7680;                                                 \
        uint16_t* Wd = Xd + 128 * BP;                                                   \
        int k0_ = (I) * 32;                                                             \
        _Pragma("unroll")                                                               \
        for (int j = 0; j < 2; j++) {                                                   \
            int idx = tid + j * 256; int r = idx >> 2, c = (idx & 3) * 8;               \
            cp16(Xd + r * BP + c, (const uint16_t*)X + (size_t)(m0 + r) * Dd + k0_ + c);\
        }                                                                               \
        {                                                                               \
            int r = tid >> 2, c = (tid & 3) * 8;                                        \
            cp16(Wd + r * BP + c,                                                       \
                 (const uint16_t*)W + (size_t)(head * 64 + r) * Dd + k0_ + c);          \
        }                                                                               \
    } while (0)

    BLOAD(0, 0);
    asm volatile("cp.async.commit_group;");
    BLOAD(1, 1);
    asm volatile("cp.async.commit_group;");

    for (int i = 0; i < 32; i++) {
        asm volatile("cp.async.wait_group 1;");
        __syncthreads();
        if (i + 2 < 32) BLOAD(i + 2, (i + 2) % 3);
        asm volatile("cp.async.commit_group;");

        const uint16_t* Xb_ = sb + (i % 3) * 7680;
        const uint16_t* Wb_ = Xb_ + 128 * BP;
#pragma unroll
        for (int ks = 0; ks < 2; ks++) {
            uint32_t a[2][4], b[2][4];
            ldsm4(a[0], Xb_ + (wm * 32) * BP + ks * 16 + loA40);
            ldsm4(a[1], Xb_ + (wm * 32 + 16) * BP + ks * 16 + loA40);
            ldsm4(b[0], Wb_ + (wn * 32) * BP + ks * 16 + loB40);
            ldsm4(b[1], Wb_ + (wn * 32 + 16) * BP + ks * 16 + loB40);
#pragma unroll
            for (int fm = 0; fm < 2; fm++) {
                mma16(acc[fm][0], a[fm], b[0][0], b[0][1]);
                mma16(acc[fm][1], a[fm], b[0][2], b[0][3]);
                mma16(acc[fm][2], a[fm], b[1][0], b[1][1]);
                mma16(acc[fm][3], a[fm], b[1][2], b[1][3]);
            }
        }
    }
#undef BLOAD

#pragma unroll
    for (int fm = 0; fm < 2; fm++) {
#pragma unroll
        for (int fn = 0; fn < 4; fn++) {
            int col = wn * 32 + fn * 8 + 2 * tg;
            float b0 = bias[head * 64 + col], b1 = bias[head * 64 + col + 1];
            int r0 = m0 + wm * 32 + fm * 16 + g, r1 = r0 + 8;
            uint32_t v0 = pack_bf2(fmaxf(acc[fm][fn][0] + b0, 0.f) * sc,
                                   fmaxf(acc[fm][fn][1] + b1, 0.f) * sc);
            uint32_t v1 = pack_bf2(fmaxf(acc[fm][fn][2] + b0, 0.f) * sc,
                                   fmaxf(acc[fm][fn][3] + b1, 0.f) * sc);
            {
                int b_ = r0 >> 10, s = r0 & 1023;
                *(uint32_t*)((uint16_t*)Y + (((size_t)(b_ * Hh + head)) * Ss + s) * DKk + col) = v0;
            }
            {
                int b_ = r1 >> 10, s = r1 & 1023;
                *(uint32_t*)((uint16_t*)Y + (((size_t)(b_ * Hh + head)) * Ss + s) * DKk + col) = v1;
            }
        }
    }
}

// ---------------------------------------------------------------------------
// fp16 V projection GEMM + FUSED V' = V @ Wo^T (fp16 mma, f32 accum).
// Mainloop identical in shape to gemm_bf. Epilogue: stage V tile fp16 to smem,
// Wo fp16 to smem, pass-2 mma16f, store V' fp16 to g_Vp[bh][s][d].
// ---------------------------------------------------------------------------
__global__ __launch_bounds__(256) void gemm_hf(const float* __restrict__ Wo) {
    extern __shared__ uint16_t sb[];

    const uint16_t* X = (const uint16_t*)g_Xf;
    const uint16_t* W = (const uint16_t*)g_Wcf;
    const float* bias = g_bc[2];
    int head = blockIdx.x, m0 = blockIdx.y * 128;

    int tid = threadIdx.x;
    int w = tid >> 5, lane = tid & 31, g = lane >> 2, tg = lane & 3;
    int wm = w & 3, wn = w >> 2;

    const int loA40 = ((lane & 7) + ((lane >> 3) & 1) * 8) * BP + ((lane >> 4) & 1) * 8;
    const int loB40 = ((lane & 7) + ((lane >> 4) & 1) * 8) * BP + ((lane >> 3) & 1) * 8;

    float acc[2][4][4] = {};

#define HLOAD(I, S)                                                                     \
    do {                                                                                \
        uint16_t* Xd = sb + (S) * 7680;                                                 \
        uint16_t* Wd = Xd + 128 * BP;                                                   \
        int k0_ = (I) * 32;                                                             \
        _Pragma("unroll")                                                               \
        for (int j = 0; j < 2; j++) {                                                   \
            int idx = tid + j * 256; int r = idx >> 2, c = (idx & 3) * 8;               \
            cp16(Xd + r * BP + c, X + (size_t)(m0 + r) * Dd + k0_ + c);                 \
        }                                                                               \
        {                                                                               \
            int r = tid >> 2, c = (tid & 3) * 8;                                        \
            cp16(Wd + r * BP + c, W + (size_t)(head * 64 + r) * Dd + k0_ + c);          \
        }                                                                               \
    } while (0)

    HLOAD(0, 0);
    asm volatile("cp.async.commit_group;");
    HLOAD(1, 1);
    asm volatile("cp.async.commit_group;");

    for (int i = 0; i < 32; i++) {
        asm volatile("cp.async.wait_group 1;");
        __syncthreads();
        if (i + 2 < 32) HLOAD(i + 2, (i + 2) % 3);
        asm volatile("cp.async.commit_group;");

        const uint16_t* Xb_ = sb + (i % 3) * 7680;
        const uint16_t* Wb_ = Xb_ + 128 * BP;
#pragma unroll
        for (int ks = 0; ks < 2; ks++) {
            uint32_t a[2][4], b[2][4];
            ldsm4(a[0], Xb_ + (wm * 32) * BP + ks * 16 + loA40);
            ldsm4(a[1], Xb_ + (wm * 32 + 16) * BP + ks * 16 + loA40);
            ldsm4(b[0], Wb_ + (wn * 32) * BP + ks * 16 + loB40);
            ldsm4(b[1], Wb_ + (wn * 32 + 16) * BP + ks * 16 + loB40);
#pragma unroll
            for (int fm = 0; fm < 2; fm++) {
                mma16f(acc[fm][0], a[fm], b[0][0], b[0][1]);
                mma16f(acc[fm][1], a[fm], b[0][2], b[0][3]);
                mma16f(acc[fm][2], a[fm], b[1][0], b[1][1]);
                mma16f(acc[fm][3], a[fm], b[1][2], b[1][3]);
            }
        }
    }
#undef HLOAD
    __syncthreads();  // mainloop smem reads complete before reuse

    // ---- pass 2: V' = V @ Wo^T (fp16 mma) -----------------------------------
    uint16_t* Vt  = sb;              // [128][72] fp16  (18432 B)
    uint16_t* WoS = sb + 128 * 72;   // [64][72]  fp16  ( 9216 B)

    // stage relu'd V tile (fp16)
#pragma unroll
    for (int fm = 0; fm < 2; fm++) {
#pragma unroll
        for (int fn = 0; fn < 4; fn++) {
            int col = wn * 32 + fn * 8 + 2 * tg;
            float b0 = bias[head * 64 + col], b1 = bias[head * 64 + col + 1];
            int lr0 = wm * 32 + fm * 16 + g, lr1 = lr0 + 8;
            *(uint32_t*)(Vt + lr0 * 72 + col) = pack_hf2(fmaxf(acc[fm][fn][0] + b0, 0.f),
                                                         fmaxf(acc[fm][fn][1] + b1, 0.f));
            *(uint32_t*)(Vt + lr1 * 72 + col) = pack_hf2(fmaxf(acc[fm][fn][2] + b0, 0.f),
                                                         fmaxf(acc[fm][fn][3] + b1, 0.f));
        }
    }
    // stage Wo (fp16): WoS[o][d]
#pragma unroll
    for (int j = 0; j < 4; j++) {
        int idx = tid + j * 256; int r = idx >> 4, c = (idx & 15) * 4;
        float4 wv = *(const float4*)(Wo + r * 64 + c);
        *(uint32_t*)(WoS + r * 72 + c)     = pack_hf2(wv.x, wv.y);
        *(uint32_t*)(WoS + r * 72 + c + 2) = pack_hf2(wv.z, wv.w);
    }
    __syncthreads();

    // D[s][o] = sum_d V[s,d] * Wo[o,d] ; m=s(128), n=o(64), k=d(64)
    const int loA72 = ((lane & 7) + ((lane >> 3) & 1) * 8) * 72 + ((lane >> 4) & 1) * 8;
    const int loB72 = ((lane & 7) + ((lane >> 4) & 1) * 8) * 72 + ((lane >> 3) & 1) * 8;
    float acc2[2][4][4] = {};
#pragma unroll
    for (int ks = 0; ks < 4; ks++) {
        uint32_t a[2][4], b[2][4];
        ldsm4(a[0], Vt + (wm * 32) * 72 + ks * 16 + loA72);
        ldsm4(a[1], Vt + (wm * 32 + 16) * 72 + ks * 16 + loA72);
        ldsm4(b[0], WoS + (wn * 32) * 72 + ks * 16 + loB72);
        ldsm4(b[1], WoS + (wn * 32 + 16) * 72 + ks * 16 + loB72);
#pragma unroll
        for (int fm = 0; fm < 2; fm++) {
            mma16f(acc2[fm][0], a[fm], b[0][0], b[0][1]);
            mma16f(acc2[fm][1], a[fm], b[0][2], b[0][3]);
            mma16f(acc2[fm][2], a[fm], b[1][0], b[1][1]);
            mma16f(acc2[fm][3], a[fm], b[1][2], b[1][3]);
        }
    }

    // store V' (fp16) to g_Vp[bh][s][d]
    int b_ = m0 >> 10, s0 = m0 & 1023;
    int bh = b_ * Hh + head;
    uint16_t* dst = (uint16_t*)g_Vp + ((size_t)bh * Ss + s0) * DKk;
#pragma unroll
    for (int fm = 0; fm < 2; fm++) {
#pragma unroll
        for (int fn = 0; fn < 4; fn++) {
            int col = wn * 32 + fn * 8 + 2 * tg;
            int lr0 = wm * 32 + fm * 16 + g, lr1 = lr0 + 8;
            *(uint32_t*)(dst + (size_t)lr0 * DKk + col) =
                pack_hf2(acc2[fm][fn][0], acc2[fm][fn][1]);
            *(uint32_t*)(dst + (size_t)lr1 * DKk + col) =
                pack_hf2(acc2[fm][fn][2], acc2[fm][fn][3]);
        }
    }
}

// ---------------------------------------------------------------------------
// Flash attention: S-phase bf16 (unchanged), PV-phase fp16 (P fp16, V' fp16,
// ldmatrix.trans B fragments). 128 q-rows/CTA, 8 warps, double-buffered.
// smem: Kb[2][64][72]u16 + Vb[2][64][72]u16 + Ps[8][16][72]u16 + ms = 55808 B
// ---------------------------------------------------------------------------
#define KP 72
__global__ __launch_bounds__(256) void attn_tc(const int* __restrict__ mask,
                                               const float* __restrict__ bo,
                                               float* __restrict__ out) {
    extern __shared__ char smraw[];
    uint16_t* Kb = (uint16_t*)smraw;                   // [2][64][72]  18432 B
    uint16_t* Vb = (uint16_t*)(smraw + 18432);         // [2][64][72]  18432 B
    uint16_t* Ps = (uint16_t*)(smraw + 36864);         // [8][16][72]  18432 B (Q staging too)
    int* ms = (int*)(smraw + 55296);                   // [2][64]        512 B

    int bh = blockIdx.y, q0 = blockIdx.x * 128;
    const uint16_t* Qg = (const uint16_t*)g_Qb + ((size_t)bh * Ss + q0) * DKk;
    const uint16_t* Kg = (const uint16_t*)g_Kb + (size_t)bh * Ss * DKk;
    const uint16_t* Vg = (const uint16_t*)g_Vp + (size_t)bh * Ss * DKk;

    int tid = threadIdx.x, w = tid >> 5, lane = tid & 31, g = lane >> 2, tg = lane & 3;
    const int loA72 = ((lane & 7) + ((lane >> 3) & 1) * 8) * KP + ((lane >> 4) & 1) * 8;
    const int loB72 = ((lane & 7) + ((lane >> 4) & 1) * 8) * KP + ((lane >> 3) & 1) * 8;
    // trans B-fragment addressing for V' [k=s][n=d] row-major
    const int loBT72 = ((lane & 7) + ((lane >> 3) & 1) * 8) * KP + ((lane >> 4) & 1) * 8;

    // ---- stage Q (bf16) through Ps region, extract A-fragments --------------
#pragma unroll
    for (int j = 0; j < 4; j++) {
        int idx = tid + j * 256; int r = idx >> 3, c = (idx & 7) * 8;
        *(uint4*)(Ps + r * KP + c) = *(const uint4*)(Qg + (size_t)r * DKk + c);
    }
    __syncthreads();
    uint32_t qa[4][4];
#pragma unroll
    for (int ks = 0; ks < 4; ks++)
        ldsm4(qa[ks], Ps + w * 16 * KP + ks * 16 + loA72);
    uint16_t* Pw = Ps + w * 16 * KP;
    __syncthreads();

#define AFILL(KT, BUF)                                                                  \
    do {                                                                                \
        const uint16_t* kg = Kg + (size_t)(KT) * 64 * DKk;                              \
        const uint16_t* vg = Vg + (size_t)(KT) * 64 * DKk;                              \
        _Pragma("unroll")                                                               \
        for (int j = 0; j < 2; j++) {                                                   \
            int idx = tid + j * 256; int r = idx >> 3, c = (idx & 7) * 8;               \
            cp16(Kb + ((BUF) * 64 + r) * KP + c, kg + (size_t)r * DKk + c);             \
            cp16(Vb + ((BUF) * 64 + r) * KP + c, vg + (size_t)r * DKk + c);             \
        }                                                                               \
        if (tid < 16)                                                                   \
            cp16(ms + (BUF) * 64 + tid * 4, mask + (size_t)bh * Ss + (KT) * 64 + tid * 4); \
        asm volatile("cp.async.commit_group;");                                        \
    } while (0)

    float oacc[8][4] = {};
    float mrow[2] = {-1e30f, -1e30f};
    float lrow[2] = {0.f, 0.f};

    AFILL(0, 0);
    for (int kt = 0; kt < 16; kt++) {
        int buf = kt & 1;
        if (kt < 15) {
            AFILL(kt + 1, buf ^ 1);
            asm volatile("cp.async.wait_group 1;");
        } else {
            asm volatile("cp.async.wait_group 0;");
        }
        __syncthreads();
        const uint16_t* Kt = Kb + buf * 64 * KP;
        const uint16_t* Vt = Vb + buf * 64 * KP;
        const int* mt = ms + buf * 64;

        // ---- S = Q' @ K^T (bf16, exp2 domain) -------------------------------
        float sacc[8][4] = {};
#pragma unroll
        for (int ks = 0; ks < 4; ks++) {
#pragma unroll
            for (int fnp = 0; fnp < 4; fnp++) {
                uint32_t b[4];
                ldsm4(b, Kt + fnp * 16 * KP + ks * 16 + loB72);
                mma16(sacc[2 * fnp],     qa[ks], b[0], b[1]);
                mma16(sacc[2 * fnp + 1], qa[ks], b[2], b[3]);
            }
        }
        // mask
#pragma unroll
        for (int fn = 0; fn < 8; fn++) {
            int c0 = fn * 8 + 2 * tg;
            bool k0m = (mt[c0] == 0), k1m = (mt[c0 + 1] == 0);
            if (k0m) { sacc[fn][0] = MASKVAL; sacc[fn][2] = MASKVAL; }
            if (k1m) { sacc[fn][1] = MASKVAL; sacc[fn][3] = MASKVAL; }
        }
        // online softmax (rows g and g+8), exp2 domain
        float mxA = -1e30f, mxB = -1e30f;
#pragma unroll
        for (int fn = 0; fn < 8; fn++) {
            mxA = fmaxf(mxA, fmaxf(sacc[fn][0], sacc[fn][1]));
            mxB = fmaxf(mxB, fmaxf(sacc[fn][2], sacc[fn][3]));
        }
        mxA = fmaxf(mxA, __shfl_xor_sync(~0u, mxA, 1));
        mxA = fmaxf(mxA, __shfl_xor_sync(~0u, mxA, 2));
        mxB = fmaxf(mxB, __shfl_xor_sync(~0u, mxB, 1));
        mxB = fmaxf(mxB, __shfl_xor_sync(~0u, mxB, 2));
        float mAn = fmaxf(mrow[0], mxA), mBn = fmaxf(mrow[1], mxB);
        float aA = ex2f(mrow[0] - mAn), aB = ex2f(mrow[1] - mBn);
        mrow[0] = mAn; mrow[1] = mBn;
        float sA = 0.f, sB = 0.f;
#pragma unroll
        for (int fn = 0; fn < 8; fn++) {
            sacc[fn][0] = ex2f(sacc[fn][0] - mAn);
            sacc[fn][1] = ex2f(sacc[fn][1] - mAn);
            sacc[fn][2] = ex2f(sacc[fn][2] - mBn);
            sacc[fn][3] = ex2f(sacc[fn][3] - mBn);
            sA += sacc[fn][0] + sacc[fn][1];
            sB += sacc[fn][2] + sacc[fn][3];
        }
        sA += __shfl_xor_sync(~0u, sA, 1); sA += __shfl_xor_sync(~0u, sA, 2);
        sB += __shfl_xor_sync(~0u, sB, 1); sB += __shfl_xor_sync(~0u, sB, 2);
        lrow[0] = lrow[0] * aA + sA;
        lrow[1] = lrow[1] * aB + sB;
#pragma unroll
        for (int fn = 0; fn < 8; fn++) {
            oacc[fn][0] *= aA; oacc[fn][1] *= aA; oacc[fn][2] *= aB; oacc[fn][3] *= aB;
        }
        // stage P (fp16) in per-warp smem
#pragma unroll
        for (int fn = 0; fn < 8; fn++) {
            int c0 = fn * 8 + 2 * tg;
            *(uint32_t*)(Pw + g * KP + c0)       = pack_hf2(sacc[fn][0], sacc[fn][1]);
            *(uint32_t*)(Pw + (g + 8) * KP + c0) = pack_hf2(sacc[fn][2], sacc[fn][3]);
        }
        __syncwarp();
        // ---- O += P @ V' (fp16 mma, trans B from V'[s][d]) -------------------
#pragma unroll
        for (int ks = 0; ks < 4; ks++) {
            uint32_t pa[4];
            ldsm4(pa, Pw + ks * 16 + loA72);
#pragma unroll
            for (int fnp = 0; fnp < 4; fnp++) {
                uint32_t b[4];
                ldsm4t(b, Vt + (ks * 16) * KP + fnp * 16 + loBT72);
                mma16f(oacc[2 * fnp],     pa, b[0], b[1]);
                mma16f(oacc[2 * fnp + 1], pa, b[2], b[3]);
            }
        }
        __syncthreads();
    }
#undef AFILL

    // ---- epilogue: normalize, +bo, transpose-out write ----------------------
    float invA = 1.f / lrow[0], invB = 1.f / lrow[1];
    int b_ = bh >> 4, h = bh & 15;
#pragma unroll
    for (int fn = 0; fn < 8; fn++) {
        int col = fn * 8 + 2 * tg;
        float b0v = bo[col], b1v = bo[col + 1];
        int r0 = q0 + w * 16 + g, r1 = r0 + 8;
        *(float2*)(out + ((size_t)(b_ * Ss + r0)) * Dd + h * 64 + col) =
            make_float2(oacc[fn][0] * invA + b0v, oacc[fn][1] * invA + b1v);
        *(float2*)(out + ((size_t)(b_ * Ss + r1)) * Dd + h * 64 + col) =
            make_float2(oacc[fn][2] * invB + b0v, oacc[fn][3] * invB + b1v);
    }
}

// ---------------------------------------------------------------------------
extern "C" void kernel_launch(void* const* d_in, const int* in_sizes, int n_in,
                              void* d_out, int out_size) {
    const float* q   = (const float*)d_in[0];
    const float* k   = (const float*)d_in[1];
    const float* v   = (const float*)d_in[2];
    const int*   msk = (const int*)d_in[3];
    const float* Wq  = (const float*)d_in[4];
    const float* bq  = (const float*)d_in[5];
    const float* Wk  = (const float*)d_in[6];
    const float* bk  = (const float*)d_in[7];
    const float* Wv  = (const float*)d_in[8];
    const float* bv  = (const float*)d_in[9];
    const float* Wqf = (const float*)d_in[10];
    const float* bqf = (const float*)d_in[11];
    const float* Wkf = (const float*)d_in[12];
    const float* bkf = (const float*)d_in[13];
    const float* Wvf = (const float*)d_in[14];
    const float* bvf = (const float*)d_in[15];
    const float* Wo  = (const float*)d_in[16];
    const float* bo  = (const float*)d_in[17];
    float* out = (float*)d_out;

    const int bf_smem   = 3 * (128 + 64) * BP * 2;  // 46080
    const int attn_smem = 55808;

    static int cfg = 0;
    if (!cfg) {
        cudaFuncSetAttribute(gemm_bf, cudaFuncAttributeMaxDynamicSharedMemorySize, bf_smem);
        cudaFuncSetAttribute(gemm_hf, cudaFuncAttributeMaxDynamicSharedMemorySize, bf_smem);
        cudaFuncSetAttribute(attn_tc, cudaFuncAttributeMaxDynamicSharedMemorySize, attn_smem);
        cfg = 1;
    }

    preround<<<4096, 256>>>(q, k, v);
    fold_kernel<<<dim3(16, 16, 3), 256>>>(Wq, Wqf, Wk, Wkf, Wv, Wvf);
    bfold_kernel<<<3, 1024>>>(bq, bqf, bk, bkf, bv, bvf, Wqf, Wkf, Wvf);
    gemm_bf<<<dim3(16, 32, 2), 256, bf_smem>>>();
    gemm_hf<<<dim3(16, 32), 256, bf_smem>>>(Wo);
    attn_tc<<<dim3(8, 64), 256, attn_smem>>>(msk, bo, out);
}

// round 8
// speedup vs baseline: 4.8702x; 1.0241x over previous
#include <cuda_runtime.h>
#include <cuda_bf16.h>
#include <cuda_fp16.h>
#include <math.h>
#include <stdint.h>

#define Bb 4
#define Ss 1024
#define Dd 1024
#define Hh 16
#define DKk 64

#define QSCALE 0.18033688011112042f
#define MASKVAL -14426.950408889634f

// ---------------------------------------------------------------------------
// Device scratch
// ---------------------------------------------------------------------------
__device__ __nv_bfloat16 g_Xb[2][4096 * 1024];   // bf16 q,k inputs
__device__ __half        g_Xf[4096 * 1024];      // fp16 v input
__device__ __nv_bfloat16 g_Wcb[2][1024 * 1024];  // folded Wq,Wk (bf16)
__device__ __half        g_Wcf[1024 * 1024];     // folded Wv (fp16)
__device__ float         g_bc[3][1024];          // folded biases
__device__ __nv_bfloat16 g_Qb[64 * 1024 * 64];   // per-head Q (bf16, pre-scaled)
__device__ __nv_bfloat16 g_Kb[64 * 1024 * 64];   // per-head K (bf16)
__device__ __half        g_Vp[64 * 1024 * 64];   // V' = V @ Wo^T (fp16) [bh][s][d]

// ---------------------------------------------------------------------------
// helpers
// ---------------------------------------------------------------------------
__device__ __forceinline__ void mma16(float (&d)[4], const uint32_t (&a)[4],
                                      uint32_t b0, uint32_t b1) {
    asm volatile(
        "mma.sync.aligned.m16n8k16.row.col.f32.bf16.bf16.f32 "
        "{%0,%1,%2,%3},{%4,%5,%6,%7},{%8,%9},{%0,%1,%2,%3};"
        : "+f"(d[0]), "+f"(d[1]), "+f"(d[2]), "+f"(d[3])
        : "r"(a[0]), "r"(a[1]), "r"(a[2]), "r"(a[3]), "r"(b0), "r"(b1));
}
__device__ __forceinline__ void mma16f(float (&d)[4], const uint32_t (&a)[4],
                                       uint32_t b0, uint32_t b1) {
    asm volatile(
        "mma.sync.aligned.m16n8k16.row.col.f32.f16.f16.f32 "
        "{%0,%1,%2,%3},{%4,%5,%6,%7},{%8,%9},{%0,%1,%2,%3};"
        : "+f"(d[0]), "+f"(d[1]), "+f"(d[2]), "+f"(d[3])
        : "r"(a[0]), "r"(a[1]), "r"(a[2]), "r"(a[3]), "r"(b0), "r"(b1));
}
__device__ __forceinline__ void ldsm4(uint32_t (&r)[4], const uint16_t* p) {
    uint32_t a = (uint32_t)__cvta_generic_to_shared(p);
    asm volatile("ldmatrix.sync.aligned.m8n8.x4.shared.b16 {%0,%1,%2,%3},[%4];"
                 : "=r"(r[0]), "=r"(r[1]), "=r"(r[2]), "=r"(r[3]) : "r"(a));
}
__device__ __forceinline__ void ldsm4t(uint32_t (&r)[4], const uint16_t* p) {
    uint32_t a = (uint32_t)__cvta_generic_to_shared(p);
    asm volatile("ldmatrix.sync.aligned.m8n8.x4.trans.shared.b16 {%0,%1,%2,%3},[%4];"
                 : "=r"(r[0]), "=r"(r[1]), "=r"(r[2]), "=r"(r[3]) : "r"(a));
}
__device__ __forceinline__ void cp16(void* s, const void* g) {
    uint32_t sa = (uint32_t)__cvta_generic_to_shared(s);
    asm volatile("cp.async.cg.shared.global [%0], [%1], 16;" :: "r"(sa), "l"(g));
}
__device__ __forceinline__ uint32_t pack_bf2(float a, float b) {
    __nv_bfloat162 t = __float22bfloat162_rn(make_float2(a, b));
    return *reinterpret_cast<uint32_t*>(&t);
}
__device__ __forceinline__ uint32_t pack_hf2(float a, float b) {
    __half2 t = __floats2half2_rn(a, b);
    return *reinterpret_cast<uint32_t*>(&t);
}
__device__ __forceinline__ float ex2f(float x) {
    float y; asm("ex2.approx.f32 %0,%1;" : "=f"(y) : "f"(x)); return y;
}

// ---------------------------------------------------------------------------
// preround: q,k -> bf16 ; v -> fp16
// ---------------------------------------------------------------------------
__global__ void preround(const float* __restrict__ q, const float* __restrict__ k,
                         const float* __restrict__ v) {
    size_t i = (size_t)blockIdx.x * blockDim.x + threadIdx.x;  // float4 index
    float4 a = ((const float4*)q)[i];
    uint32_t* dq = (uint32_t*)g_Xb[0];
    dq[i * 2] = pack_bf2(a.x, a.y); dq[i * 2 + 1] = pack_bf2(a.z, a.w);
    float4 b = ((const float4*)k)[i];
    uint32_t* dk = (uint32_t*)g_Xb[1];
    dk[i * 2] = pack_bf2(b.x, b.y); dk[i * 2 + 1] = pack_bf2(b.z, b.w);
    float4 c = ((const float4*)v)[i];
    uint32_t* dv = (uint32_t*)g_Xf;
    dv[i * 2] = pack_hf2(c.x, c.y); dv[i * 2 + 1] = pack_hf2(c.z, c.w);
}

// ---------------------------------------------------------------------------
// Fold: Wc[t][(h*64+o)*1024 + j] = sum_i Wf[o,i] * Wbig[h*64+i, j]
// t<2 -> bf16 (g_Wcb), t==2 -> fp16 (g_Wcf)
// ---------------------------------------------------------------------------
__global__ void fold_kernel(const float* __restrict__ Wq, const float* __restrict__ Wqf,
                            const float* __restrict__ Wk, const float* __restrict__ Wkf,
                            const float* __restrict__ Wv, const float* __restrict__ Wvf) {
    int t = blockIdx.z, h = blockIdx.y, j0 = blockIdx.x * 64;
    const float* Wbig = (t == 0) ? Wq : (t == 1) ? Wk : Wv;
    const float* Wf   = (t == 0) ? Wqf : (t == 1) ? Wkf : Wvf;

    __shared__ float fs[64][65];
    __shared__ float bs[64][65];

    int tid = threadIdx.x;
    for (int idx = tid; idx < 64 * 16; idx += 256) {
        int r = idx >> 4, c4 = (idx & 15) * 4;
        float4 fv = *(const float4*)(Wf + r * 64 + c4);
        fs[r][c4] = fv.x; fs[r][c4 + 1] = fv.y; fs[r][c4 + 2] = fv.z; fs[r][c4 + 3] = fv.w;
        float4 bv = *(const float4*)(Wbig + (h * 64 + r) * Dd + j0 + c4);
        bs[r][c4] = bv.x; bs[r][c4 + 1] = bv.y; bs[r][c4 + 2] = bv.z; bs[r][c4 + 3] = bv.w;
    }
    __syncthreads();

    int ty = tid >> 4, tx = tid & 15;
    float acc[4][4] = {};
#pragma unroll 8
    for (int i = 0; i < 64; i++) {
        float a[4], b[4];
#pragma unroll
        for (int u = 0; u < 4; u++) { a[u] = fs[ty * 4 + u][i]; b[u] = bs[i][tx * 4 + u]; }
#pragma unroll
        for (int u = 0; u < 4; u++)
#pragma unroll
            for (int w = 0; w < 4; w++) acc[u][w] += a[u] * b[w];
    }
    if (t < 2) {
        uint32_t* dst = (uint32_t*)g_Wcb[t];
#pragma unroll
        for (int u = 0; u < 4; u++) {
            size_t row = (size_t)(h * 64 + ty * 4 + u) * Dd + j0 + tx * 4;
            dst[row / 2]     = pack_bf2(acc[u][0], acc[u][1]);
            dst[row / 2 + 1] = pack_bf2(acc[u][2], acc[u][3]);
        }
    } else {
        uint32_t* dst = (uint32_t*)g_Wcf;
#pragma unroll
        for (int u = 0; u < 4; u++) {
            size_t row = (size_t)(h * 64 + ty * 4 + u) * Dd + j0 + tx * 4;
            dst[row / 2]     = pack_hf2(acc[u][0], acc[u][1]);
            dst[row / 2 + 1] = pack_hf2(acc[u][2], acc[u][3]);
        }
    }
}

__global__ void bfold_kernel(const float* __restrict__ bq, const float* __restrict__ bqf,
                             const float* __restrict__ bk, const float* __restrict__ bkf,
                             const float* __restrict__ bv, const float* __restrict__ bvf,
                             const float* __restrict__ Wqf, const float* __restrict__ Wkf,
                             const float* __restrict__ Wvf) {
    int t = blockIdx.x, n = threadIdx.x;
    const float* b1 = (t == 0) ? bq : (t == 1) ? bk : bv;
    const float* b2 = (t == 0) ? bqf : (t == 1) ? bkf : bvf;
    const float* Wf = (t == 0) ? Wqf : (t == 1) ? Wkf : Wvf;
    int h = n >> 6, o = n & 63;
    float s = b2[o];
    for (int i = 0; i < 64; i++) s += Wf[o * 64 + i] * b1[h * 64 + i];
    g_bc[t][n] = s;
}

// ---------------------------------------------------------------------------
// Unified projection GEMM: BM=128, BN=128 (2 heads/CTA), BK=32, 3-stage.
// z=0 -> Q (bf16, QSCALE), z=1 -> K (bf16), z=2 -> V (fp16 + fused V'=V@Wo^T).
// 256 threads = 8 warps (4m x 2n), warp tile 32x64.
// smem: 3 stages x (X[128][40] + W[128][40]) u16 = 61440 B
// ---------------------------------------------------------------------------
#define BP 40
__global__ __launch_bounds__(256) void proj_all(const float* __restrict__ Wo) {
    extern __shared__ uint16_t sb[];

    const int t = blockIdx.z;
    const bool VM = (t == 2);
    const uint16_t* X = VM ? (const uint16_t*)g_Xf : (const uint16_t*)g_Xb[t];
    const uint16_t* W = VM ? (const uint16_t*)g_Wcf : (const uint16_t*)g_Wcb[t];
    const float* bias = g_bc[t];
    const int hp = blockIdx.x;          // head pair (2 heads)
    const int m0 = blockIdx.y * 128;

    const int tid = threadIdx.x;
    const int w = tid >> 5, lane = tid & 31, g = lane >> 2, tg = lane & 3;
    const int wm = w & 3, wn = w >> 2;  // 4 m-groups x 2 n-groups

    const int loA40 = ((lane & 7) + ((lane >> 3) & 1) * 8) * BP + ((lane >> 4) & 1) * 8;
    const int loB40 = ((lane & 7) + ((lane >> 4) & 1) * 8) * BP + ((lane >> 3) & 1) * 8;

    float acc[2][8][4] = {};

#define GLOAD(I, S)                                                                     \
    do {                                                                                \
        uint16_t* Xd = sb + (S) * 10240;                                                \
        uint16_t* Wd = Xd + 5120;                                                       \
        int k0_ = (I) * 32;                                                             \
        _Pragma("unroll")                                                               \
        for (int j = 0; j < 2; j++) {                                                   \
            int idx = tid + j * 256; int r = idx >> 2, c = (idx & 3) * 8;               \
            cp16(Xd + r * BP + c, X + (size_t)(m0 + r) * Dd + k0_ + c);                 \
        }                                                                               \
        _Pragma("unroll")                                                               \
        for (int j = 0; j < 2; j++) {                                                   \
            int idx = tid + j * 256; int r = idx >> 2, c = (idx & 3) * 8;               \
            cp16(Wd + r * BP + c, W + (size_t)(hp * 128 + r) * Dd + k0_ + c);           \
        }                                                                               \
        asm volatile("cp.async.commit_group;");                                        \
    } while (0)

#define MAINLOOP(MMAOP)                                                                 \
    for (int i = 0; i < 32; i++) {                                                      \
        asm volatile("cp.async.wait_group 1;");                                         \
        __syncthreads();                                                                \
        if (i + 2 < 32) GLOAD(i + 2, (i + 2) % 3);                                      \
        else asm volatile("cp.async.commit_group;");                                    \
        const uint16_t* Xb_ = sb + (i % 3) * 10240;                                     \
        const uint16_t* Wb_ = Xb_ + 5120;                                               \
        _Pragma("unroll")                                                               \
        for (int ks = 0; ks < 2; ks++) {                                                \
            uint32_t a[2][4], b[4][4];                                                  \
            ldsm4(a[0], Xb_ + (wm * 32) * BP + ks * 16 + loA40);                        \
            ldsm4(a[1], Xb_ + (wm * 32 + 16) * BP + ks * 16 + loA40);                   \
            _Pragma("unroll")                                                           \
            for (int fnp = 0; fnp < 4; fnp++)                                           \
                ldsm4(b[fnp], Wb_ + (wn * 64 + fnp * 16) * BP + ks * 16 + loB40);       \
            _Pragma("unroll")                                                           \
            for (int fm = 0; fm < 2; fm++)                                              \
                _Pragma("unroll")                                                       \
                for (int fnp = 0; fnp < 4; fnp++) {                                     \
                    MMAOP(acc[fm][2 * fnp],     a[fm], b[fnp][0], b[fnp][1]);           \
                    MMAOP(acc[fm][2 * fnp + 1], a[fm], b[fnp][2], b[fnp][3]);           \
                }                                                                       \
        }                                                                               \
    }

    GLOAD(0, 0);
    GLOAD(1, 1);
    if (!VM) { MAINLOOP(mma16); }
    else     { MAINLOOP(mma16f); }
#undef MAINLOOP
#undef GLOAD

    const int b_ = m0 >> 10, s0 = m0 & 1023;
    if (!VM) {
        __nv_bfloat16* Y = (t == 0) ? g_Qb : g_Kb;
        const float sc = (t == 0) ? QSCALE : 1.0f;
        const int head = hp * 2 + wn;
        const float* bh_ = bias + head * 64;
#pragma unroll
        for (int fm = 0; fm < 2; fm++) {
#pragma unroll
            for (int fn = 0; fn < 8; fn++) {
                int col = fn * 8 + 2 * tg;
                float b0 = bh_[col], b1 = bh_[col + 1];
                int r0 = m0 + wm * 32 + fm * 16 + g, r1 = r0 + 8;
                uint32_t v0 = pack_bf2(fmaxf(acc[fm][fn][0] + b0, 0.f) * sc,
                                       fmaxf(acc[fm][fn][1] + b1, 0.f) * sc);
                uint32_t v1 = pack_bf2(fmaxf(acc[fm][fn][2] + b0, 0.f) * sc,
                                       fmaxf(acc[fm][fn][3] + b1, 0.f) * sc);
                {
                    int bb = r0 >> 10, s = r0 & 1023;
                    *(uint32_t*)((uint16_t*)Y + (((size_t)(bb * Hh + head)) * Ss + s) * DKk + col) = v0;
                }
                {
                    int bb = r1 >> 10, s = r1 & 1023;
                    *(uint32_t*)((uint16_t*)Y + (((size_t)(bb * Hh + head)) * Ss + s) * DKk + col) = v1;
                }
            }
        }
    } else {
        // ---- fused pass-2: V' = V @ Wo^T per head (fp16 mma) -----------------
        __syncthreads();  // mainloop smem reads complete
        uint16_t* Vt  = sb;                  // [128][136] fp16 (34816 B)
        uint16_t* WoS = sb + 128 * 136;      // [64][72]   fp16 ( 9216 B)

        // stage relu'd V tile (both heads), col = wn*64 + fn*8 + 2tg in [0,128)
#pragma unroll
        for (int fm = 0; fm < 2; fm++) {
#pragma unroll
            for (int fn = 0; fn < 8; fn++) {
                int col = wn * 64 + fn * 8 + 2 * tg;
                float b0 = bias[hp * 128 + col], b1 = bias[hp * 128 + col + 1];
                int lr0 = wm * 32 + fm * 16 + g, lr1 = lr0 + 8;
                *(uint32_t*)(Vt + lr0 * 136 + col) = pack_hf2(fmaxf(acc[fm][fn][0] + b0, 0.f),
                                                              fmaxf(acc[fm][fn][1] + b1, 0.f));
                *(uint32_t*)(Vt + lr1 * 136 + col) = pack_hf2(fmaxf(acc[fm][fn][2] + b0, 0.f),
                                                              fmaxf(acc[fm][fn][3] + b1, 0.f));
            }
        }
        // stage Wo (fp16) [o][d] pitch 72
#pragma unroll
        for (int j = 0; j < 4; j++) {
            int idx = tid + j * 256; int r = idx >> 4, c = (idx & 15) * 4;
            float4 wv = *(const float4*)(Wo + r * 64 + c);
            *(uint32_t*)(WoS + r * 72 + c)     = pack_hf2(wv.x, wv.y);
            *(uint32_t*)(WoS + r * 72 + c + 2) = pack_hf2(wv.z, wv.w);
        }
        __syncthreads();

        const int loA136 = ((lane & 7) + ((lane >> 3) & 1) * 8) * 136 + ((lane >> 4) & 1) * 8;
        const int loB72  = ((lane & 7) + ((lane >> 4) & 1) * 8) * 72 + ((lane >> 3) & 1) * 8;

        // per head j: D[s][o] = sum_d V[s, j*64+d] * Wo[o,d]
#pragma unroll
        for (int j = 0; j < 2; j++) {
            const int head = hp * 2 + j, bh = b_ * Hh + head;
            float acc2[2][4][4] = {};
#pragma unroll
            for (int ks = 0; ks < 4; ks++) {
                uint32_t a[2][4], bfr[2][4];
                ldsm4(a[0], Vt + (wm * 32) * 136 + j * 64 + ks * 16 + loA136);
                ldsm4(a[1], Vt + (wm * 32 + 16) * 136 + j * 64 + ks * 16 + loA136);
                ldsm4(bfr[0], WoS + (wn * 32) * 72 + ks * 16 + loB72);
                ldsm4(bfr[1], WoS + (wn * 32 + 16) * 72 + ks * 16 + loB72);
#pragma unroll
                for (int fm = 0; fm < 2; fm++) {
                    mma16f(acc2[fm][0], a[fm], bfr[0][0], bfr[0][1]);
                    mma16f(acc2[fm][1], a[fm], bfr[0][2], bfr[0][3]);
                    mma16f(acc2[fm][2], a[fm], bfr[1][0], bfr[1][1]);
                    mma16f(acc2[fm][3], a[fm], bfr[1][2], bfr[1][3]);
                }
            }
            uint16_t* dst = (uint16_t*)g_Vp + ((size_t)bh * Ss + s0) * DKk;
#pragma unroll
            for (int fm = 0; fm < 2; fm++) {
#pragma unroll
                for (int fn = 0; fn < 4; fn++) {
                    int col = wn * 32 + fn * 8 + 2 * tg;
                    int lr0 = wm * 32 + fm * 16 + g, lr1 = lr0 + 8;
                    *(uint32_t*)(dst + (size_t)lr0 * DKk + col) =
                        pack_hf2(acc2[fm][fn][0], acc2[fm][fn][1]);
                    *(uint32_t*)(dst + (size_t)lr1 * DKk + col) =
                        pack_hf2(acc2[fm][fn][2], acc2[fm][fn][3]);
                }
            }
        }
    }
}

// ---------------------------------------------------------------------------
// Flash attention (unchanged from round 7, passing): S bf16 + exp2 softmax,
// PV fp16 with trans-ldmatrix V'. 128 q-rows/CTA, 8 warps, double-buffered.
// smem: Kb[2][64][72]u16 + Vb[2][64][72]u16 + Ps[8][16][72]u16 + ms = 55808 B
// ---------------------------------------------------------------------------
#define KP 72
__global__ __launch_bounds__(256) void attn_tc(const int* __restrict__ mask,
                                               const float* __restrict__ bo,
                                               float* __restrict__ out) {
    extern __shared__ char smraw[];
    uint16_t* Kb = (uint16_t*)smraw;                   // [2][64][72]
    uint16_t* Vb = (uint16_t*)(smraw + 18432);         // [2][64][72]
    uint16_t* Ps = (uint16_t*)(smraw + 36864);         // [8][16][72]
    int* ms = (int*)(smraw + 55296);                   // [2][64]

    int bh = blockIdx.y, q0 = blockIdx.x * 128;
    const uint16_t* Qg = (const uint16_t*)g_Qb + ((size_t)bh * Ss + q0) * DKk;
    const uint16_t* Kg = (const uint16_t*)g_Kb + (size_t)bh * Ss * DKk;
    const uint16_t* Vg = (const uint16_t*)g_Vp + (size_t)bh * Ss * DKk;

    int tid = threadIdx.x, w = tid >> 5, lane = tid & 31, g = lane >> 2, tg = lane & 3;
    const int loA72 = ((lane & 7) + ((lane >> 3) & 1) * 8) * KP + ((lane >> 4) & 1) * 8;
    const int loB72 = ((lane & 7) + ((lane >> 4) & 1) * 8) * KP + ((lane >> 3) & 1) * 8;
    const int loBT72 = ((lane & 7) + ((lane >> 3) & 1) * 8) * KP + ((lane >> 4) & 1) * 8;

#pragma unroll
    for (int j = 0; j < 4; j++) {
        int idx = tid + j * 256; int r = idx >> 3, c = (idx & 7) * 8;
        *(uint4*)(Ps + r * KP + c) = *(const uint4*)(Qg + (size_t)r * DKk + c);
    }
    __syncthreads();
    uint32_t qa[4][4];
#pragma unroll
    for (int ks = 0; ks < 4; ks++)
        ldsm4(qa[ks], Ps + w * 16 * KP + ks * 16 + loA72);
    uint16_t* Pw = Ps + w * 16 * KP;
    __syncthreads();

#define AFILL(KT, BUF)                                                                  \
    do {                                                                                \
        const uint16_t* kg = Kg + (size_t)(KT) * 64 * DKk;                              \
        const uint16_t* vg = Vg + (size_t)(KT) * 64 * DKk;                              \
        _Pragma("unroll")                                                               \
        for (int j = 0; j < 2; j++) {                                                   \
            int idx = tid + j * 256; int r = idx >> 3, c = (idx & 7) * 8;               \
            cp16(Kb + ((BUF) * 64 + r) * KP + c, kg + (size_t)r * DKk + c);             \
            cp16(Vb + ((BUF) * 64 + r) * KP + c, vg + (size_t)r * DKk + c);             \
        }                                                                               \
        if (tid < 16)                                                                   \
            cp16(ms + (BUF) * 64 + tid * 4, mask + (size_t)bh * Ss + (KT) * 64 + tid * 4); \
        asm volatile("cp.async.commit_group;");                                        \
    } while (0)

    float oacc[8][4] = {};
    float mrow[2] = {-1e30f, -1e30f};
    float lrow[2] = {0.f, 0.f};

    AFILL(0, 0);
    for (int kt = 0; kt < 16; kt++) {
        int buf = kt & 1;
        if (kt < 15) {
            AFILL(kt + 1, buf ^ 1);
            asm volatile("cp.async.wait_group 1;");
        } else {
            asm volatile("cp.async.wait_group 0;");
        }
        __syncthreads();
        const uint16_t* Kt = Kb + buf * 64 * KP;
        const uint16_t* Vt = Vb + buf * 64 * KP;
        const int* mt = ms + buf * 64;

        float sacc[8][4] = {};
#pragma unroll
        for (int ks = 0; ks < 4; ks++) {
#pragma unroll
            for (int fnp = 0; fnp < 4; fnp++) {
                uint32_t b[4];
                ldsm4(b, Kt + fnp * 16 * KP + ks * 16 + loB72);
                mma16(sacc[2 * fnp],     qa[ks], b[0], b[1]);
                mma16(sacc[2 * fnp + 1], qa[ks], b[2], b[3]);
            }
        }
#pragma unroll
        for (int fn = 0; fn < 8; fn++) {
            int c0 = fn * 8 + 2 * tg;
            bool k0m = (mt[c0] == 0), k1m = (mt[c0 + 1] == 0);
            if (k0m) { sacc[fn][0] = MASKVAL; sacc[fn][2] = MASKVAL; }
            if (k1m) { sacc[fn][1] = MASKVAL; sacc[fn][3] = MASKVAL; }
        }
        float mxA = -1e30f, mxB = -1e30f;
#pragma unroll
        for (int fn = 0; fn < 8; fn++) {
            mxA = fmaxf(mxA, fmaxf(sacc[fn][0], sacc[fn][1]));
            mxB = fmaxf(mxB, fmaxf(sacc[fn][2], sacc[fn][3]));
        }
        mxA = fmaxf(mxA, __shfl_xor_sync(~0u, mxA, 1));
        mxA = fmaxf(mxA, __shfl_xor_sync(~0u, mxA, 2));
        mxB = fmaxf(mxB, __shfl_xor_sync(~0u, mxB, 1));
        mxB = fmaxf(mxB, __shfl_xor_sync(~0u, mxB, 2));
        float mAn = fmaxf(mrow[0], mxA), mBn = fmaxf(mrow[1], mxB);
        float aA = ex2f(mrow[0] - mAn), aB = ex2f(mrow[1] - mBn);
        mrow[0] = mAn; mrow[1] = mBn;
        float sA = 0.f, sB = 0.f;
#pragma unroll
        for (int fn = 0; fn < 8; fn++) {
            sacc[fn][0] = ex2f(sacc[fn][0] - mAn);
            sacc[fn][1] = ex2f(sacc[fn][1] - mAn);
            sacc[fn][2] = ex2f(sacc[fn][2] - mBn);
            sacc[fn][3] = ex2f(sacc[fn][3] - mBn);
            sA += sacc[fn][0] + sacc[fn][1];
            sB += sacc[fn][2] + sacc[fn][3];
        }
        sA += __shfl_xor_sync(~0u, sA, 1); sA += __shfl_xor_sync(~0u, sA, 2);
        sB += __shfl_xor_sync(~0u, sB, 1); sB += __shfl_xor_sync(~0u, sB, 2);
        lrow[0] = lrow[0] * aA + sA;
        lrow[1] = lrow[1] * aB + sB;
#pragma unroll
        for (int fn = 0; fn < 8; fn++) {
            oacc[fn][0] *= aA; oacc[fn][1] *= aA; oacc[fn][2] *= aB; oacc[fn][3] *= aB;
        }
#pragma unroll
        for (int fn = 0; fn < 8; fn++) {
            int c0 = fn * 8 + 2 * tg;
            *(uint32_t*)(Pw + g * KP + c0)       = pack_hf2(sacc[fn][0], sacc[fn][1]);
            *(uint32_t*)(Pw + (g + 8) * KP + c0) = pack_hf2(sacc[fn][2], sacc[fn][3]);
        }
        __syncwarp();
#pragma unroll
        for (int ks = 0; ks < 4; ks++) {
            uint32_t pa[4];
            ldsm4(pa, Pw + ks * 16 + loA72);
#pragma unroll
            for (int fnp = 0; fnp < 4; fnp++) {
                uint32_t b[4];
                ldsm4t(b, Vt + (ks * 16) * KP + fnp * 16 + loBT72);
                mma16f(oacc[2 * fnp],     pa, b[0], b[1]);
                mma16f(oacc[2 * fnp + 1], pa, b[2], b[3]);
            }
        }
        __syncthreads();
    }
#undef AFILL

    float invA = 1.f / lrow[0], invB = 1.f / lrow[1];
    int b_ = bh >> 4, h = bh & 15;
#pragma unroll
    for (int fn = 0; fn < 8; fn++) {
        int col = fn * 8 + 2 * tg;
        float b0v = bo[col], b1v = bo[col + 1];
        int r0 = q0 + w * 16 + g, r1 = r0 + 8;
        *(float2*)(out + ((size_t)(b_ * Ss + r0)) * Dd + h * 64 + col) =
            make_float2(oacc[fn][0] * invA + b0v, oacc[fn][1] * invA + b1v);
        *(float2*)(out + ((size_t)(b_ * Ss + r1)) * Dd + h * 64 + col) =
            make_float2(oacc[fn][2] * invB + b0v, oacc[fn][3] * invB + b1v);
    }
}

// ---------------------------------------------------------------------------
extern "C" void kernel_launch(void* const* d_in, const int* in_sizes, int n_in,
                              void* d_out, int out_size) {
    const float* q   = (const float*)d_in[0];
    const float* k   = (const float*)d_in[1];
    const float* v   = (const float*)d_in[2];
    const int*   msk = (const int*)d_in[3];
    const float* Wq  = (const float*)d_in[4];
    const float* bq  = (const float*)d_in[5];
    const float* Wk  = (const float*)d_in[6];
    const float* bk  = (const float*)d_in[7];
    const float* Wv  = (const float*)d_in[8];
    const float* bv  = (const float*)d_in[9];
    const float* Wqf = (const float*)d_in[10];
    const float* bqf = (const float*)d_in[11];
    const float* Wkf = (const float*)d_in[12];
    const float* bkf = (const float*)d_in[13];
    const float* Wvf = (const float*)d_in[14];
    const float* bvf = (const float*)d_in[15];
    const float* Wo  = (const float*)d_in[16];
    const float* bo  = (const float*)d_in[17];
    float* out = (float*)d_out;

    const int proj_smem = 3 * 2 * 128 * BP * 2;  // 61440
    const int attn_smem = 55808;

    static int cfg = 0;
    if (!cfg) {
        cudaFuncSetAttribute(proj_all, cudaFuncAttributeMaxDynamicSharedMemorySize, proj_smem);
        cudaFuncSetAttribute(attn_tc, cudaFuncAttributeMaxDynamicSharedMemorySize, attn_smem);
        cfg = 1;
    }

    preround<<<4096, 256>>>(q, k, v);
    fold_kernel<<<dim3(16, 16, 3), 256>>>(Wq, Wqf, Wk, Wkf, Wv, Wvf);
    bfold_kernel<<<3, 1024>>>(bq, bqf, bk, bkf, bv, bvf, Wqf, Wkf, Wvf);
    proj_all<<<dim3(8, 32, 3), 256, proj_smem>>>(Wo);
    attn_tc<<<dim3(8, 64), 256, attn_smem>>>(msk, bo, out);
}

// round 9
// speedup vs baseline: 4.9042x; 1.0070x over previous
#include <cuda_runtime.h>
#include <cuda_bf16.h>
#include <cuda_fp16.h>
#include <math.h>
#include <stdint.h>

#define Bb 4
#define Ss 1024
#define Dd 1024
#define Hh 16
#define DKk 64

#define QSCALE 0.18033688011112042f
#define MASKVAL -14426.950408889634f

// ---------------------------------------------------------------------------
// Device scratch
// ---------------------------------------------------------------------------
__device__ __nv_bfloat16 g_Xb[2][4096 * 1024];   // bf16 q,k inputs
__device__ __half        g_Xf[4096 * 1024];      // fp16 v input
__device__ __nv_bfloat16 g_Wcb[2][1024 * 1024];  // folded Wq,Wk (bf16)
__device__ __half        g_Wcf[1024 * 1024];     // folded Wv (fp16)
__device__ float         g_bc[3][1024];          // folded biases
__device__ __nv_bfloat16 g_Qb[64 * 1024 * 64];   // per-head Q (bf16, pre-scaled)
__device__ __nv_bfloat16 g_Kb[64 * 1024 * 64];   // per-head K (bf16)
__device__ __half        g_Vp[64 * 1024 * 64];   // V' = V @ Wo^T (fp16) [bh][s][d]

// ---------------------------------------------------------------------------
// helpers
// ---------------------------------------------------------------------------
__device__ __forceinline__ void mma16(float (&d)[4], const uint32_t (&a)[4],
                                      uint32_t b0, uint32_t b1) {
    asm volatile(
        "mma.sync.aligned.m16n8k16.row.col.f32.bf16.bf16.f32 "
        "{%0,%1,%2,%3},{%4,%5,%6,%7},{%8,%9},{%0,%1,%2,%3};"
        : "+f"(d[0]), "+f"(d[1]), "+f"(d[2]), "+f"(d[3])
        : "r"(a[0]), "r"(a[1]), "r"(a[2]), "r"(a[3]), "r"(b0), "r"(b1));
}
__device__ __forceinline__ void mma16f(float (&d)[4], const uint32_t (&a)[4],
                                       uint32_t b0, uint32_t b1) {
    asm volatile(
        "mma.sync.aligned.m16n8k16.row.col.f32.f16.f16.f32 "
        "{%0,%1,%2,%3},{%4,%5,%6,%7},{%8,%9},{%0,%1,%2,%3};"
        : "+f"(d[0]), "+f"(d[1]), "+f"(d[2]), "+f"(d[3])
        : "r"(a[0]), "r"(a[1]), "r"(a[2]), "r"(a[3]), "r"(b0), "r"(b1));
}
__device__ __forceinline__ void ldsm4(uint32_t (&r)[4], const uint16_t* p) {
    uint32_t a = (uint32_t)__cvta_generic_to_shared(p);
    asm volatile("ldmatrix.sync.aligned.m8n8.x4.shared.b16 {%0,%1,%2,%3},[%4];"
                 : "=r"(r[0]), "=r"(r[1]), "=r"(r[2]), "=r"(r[3]) : "r"(a));
}
__device__ __forceinline__ void ldsm4t(uint32_t (&r)[4], const uint16_t* p) {
    uint32_t a = (uint32_t)__cvta_generic_to_shared(p);
    asm volatile("ldmatrix.sync.aligned.m8n8.x4.trans.shared.b16 {%0,%1,%2,%3},[%4];"
                 : "=r"(r[0]), "=r"(r[1]), "=r"(r[2]), "=r"(r[3]) : "r"(a));
}
__device__ __forceinline__ void cp16(void* s, const void* g) {
    uint32_t sa = (uint32_t)__cvta_generic_to_shared(s);
    asm volatile("cp.async.cg.shared.global [%0], [%1], 16;" :: "r"(sa), "l"(g));
}
__device__ __forceinline__ uint32_t pack_bf2(float a, float b) {
    __nv_bfloat162 t = __float22bfloat162_rn(make_float2(a, b));
    return *reinterpret_cast<uint32_t*>(&t);
}
__device__ __forceinline__ uint32_t pack_hf2(float a, float b) {
    __half2 t = __floats2half2_rn(a, b);
    return *reinterpret_cast<uint32_t*>(&t);
}
__device__ __forceinline__ float ex2f(float x) {
    float y; asm("ex2.approx.f32 %0,%1;" : "=f"(y) : "f"(x)); return y;
}

// ---------------------------------------------------------------------------
// preround: q,k -> bf16 ; v -> fp16
// ---------------------------------------------------------------------------
__global__ void preround(const float* __restrict__ q, const float* __restrict__ k,
                         const float* __restrict__ v) {
    size_t i = (size_t)blockIdx.x * blockDim.x + threadIdx.x;  // float4 index
    float4 a = ((const float4*)q)[i];
    uint32_t* dq = (uint32_t*)g_Xb[0];
    dq[i * 2] = pack_bf2(a.x, a.y); dq[i * 2 + 1] = pack_bf2(a.z, a.w);
    float4 b = ((const float4*)k)[i];
    uint32_t* dk = (uint32_t*)g_Xb[1];
    dk[i * 2] = pack_bf2(b.x, b.y); dk[i * 2 + 1] = pack_bf2(b.z, b.w);
    float4 c = ((const float4*)v)[i];
    uint32_t* dv = (uint32_t*)g_Xf;
    dv[i * 2] = pack_hf2(c.x, c.y); dv[i * 2 + 1] = pack_hf2(c.z, c.w);
}

// ---------------------------------------------------------------------------
// Fold: Wc[t][(h*64+o)*1024 + j] = sum_i Wf[o,i] * Wbig[h*64+i, j]
// t<2 -> bf16 (g_Wcb), t==2 -> fp16 (g_Wcf)
// ---------------------------------------------------------------------------
__global__ void fold_kernel(const float* __restrict__ Wq, const float* __restrict__ Wqf,
                            const float* __restrict__ Wk, const float* __restrict__ Wkf,
                            const float* __restrict__ Wv, const float* __restrict__ Wvf) {
    int t = blockIdx.z, h = blockIdx.y, j0 = blockIdx.x * 64;
    const float* Wbig = (t == 0) ? Wq : (t == 1) ? Wk : Wv;
    const float* Wf   = (t == 0) ? Wqf : (t == 1) ? Wkf : Wvf;

    __shared__ float fs[64][65];
    __shared__ float bs[64][65];

    int tid = threadIdx.x;
    for (int idx = tid; idx < 64 * 16; idx += 256) {
        int r = idx >> 4, c4 = (idx & 15) * 4;
        float4 fv = *(const float4*)(Wf + r * 64 + c4);
        fs[r][c4] = fv.x; fs[r][c4 + 1] = fv.y; fs[r][c4 + 2] = fv.z; fs[r][c4 + 3] = fv.w;
        float4 bv = *(const float4*)(Wbig + (h * 64 + r) * Dd + j0 + c4);
        bs[r][c4] = bv.x; bs[r][c4 + 1] = bv.y; bs[r][c4 + 2] = bv.z; bs[r][c4 + 3] = bv.w;
    }
    __syncthreads();

    int ty = tid >> 4, tx = tid & 15;
    float acc[4][4] = {};
#pragma unroll 8
    for (int i = 0; i < 64; i++) {
        float a[4], b[4];
#pragma unroll
        for (int u = 0; u < 4; u++) { a[u] = fs[ty * 4 + u][i]; b[u] = bs[i][tx * 4 + u]; }
#pragma unroll
        for (int u = 0; u < 4; u++)
#pragma unroll
            for (int w = 0; w < 4; w++) acc[u][w] += a[u] * b[w];
    }
    if (t < 2) {
        uint32_t* dst = (uint32_t*)g_Wcb[t];
#pragma unroll
        for (int u = 0; u < 4; u++) {
            size_t row = (size_t)(h * 64 + ty * 4 + u) * Dd + j0 + tx * 4;
            dst[row / 2]     = pack_bf2(acc[u][0], acc[u][1]);
            dst[row / 2 + 1] = pack_bf2(acc[u][2], acc[u][3]);
        }
    } else {
        uint32_t* dst = (uint32_t*)g_Wcf;
#pragma unroll
        for (int u = 0; u < 4; u++) {
            size_t row = (size_t)(h * 64 + ty * 4 + u) * Dd + j0 + tx * 4;
            dst[row / 2]     = pack_hf2(acc[u][0], acc[u][1]);
            dst[row / 2 + 1] = pack_hf2(acc[u][2], acc[u][3]);
        }
    }
}

__global__ void bfold_kernel(const float* __restrict__ bq, const float* __restrict__ bqf,
                             const float* __restrict__ bk, const float* __restrict__ bkf,
                             const float* __restrict__ bv, const float* __restrict__ bvf,
                             const float* __restrict__ Wqf, const float* __restrict__ Wkf,
                             const float* __restrict__ Wvf) {
    int t = blockIdx.x, n = threadIdx.x;
    const float* b1 = (t == 0) ? bq : (t == 1) ? bk : bv;
    const float* b2 = (t == 0) ? bqf : (t == 1) ? bkf : bvf;
    const float* Wf = (t == 0) ? Wqf : (t == 1) ? Wkf : Wvf;
    int h = n >> 6, o = n & 63;
    float s = b2[o];
    for (int i = 0; i < 64; i++) s += Wf[o * 64 + i] * b1[h * 64 + i];
    g_bc[t][n] = s;
}

// ---------------------------------------------------------------------------
// Unified projection GEMM (unchanged from round 8, at mma.sync floor).
// BM=128, BN=128 (2 heads/CTA), BK=32, 3-stage.
// ---------------------------------------------------------------------------
#define BP 40
__global__ __launch_bounds__(256) void proj_all(const float* __restrict__ Wo) {
    extern __shared__ uint16_t sb[];

    const int t = blockIdx.z;
    const bool VM = (t == 2);
    const uint16_t* X = VM ? (const uint16_t*)g_Xf : (const uint16_t*)g_Xb[t];
    const uint16_t* W = VM ? (const uint16_t*)g_Wcf : (const uint16_t*)g_Wcb[t];
    const float* bias = g_bc[t];
    const int hp = blockIdx.x;
    const int m0 = blockIdx.y * 128;

    const int tid = threadIdx.x;
    const int w = tid >> 5, lane = tid & 31, g = lane >> 2, tg = lane & 3;
    const int wm = w & 3, wn = w >> 2;

    const int loA40 = ((lane & 7) + ((lane >> 3) & 1) * 8) * BP + ((lane >> 4) & 1) * 8;
    const int loB40 = ((lane & 7) + ((lane >> 4) & 1) * 8) * BP + ((lane >> 3) & 1) * 8;

    float acc[2][8][4] = {};

#define GLOAD(I, S)                                                                     \
    do {                                                                                \
        uint16_t* Xd = sb + (S) * 10240;                                                \
        uint16_t* Wd = Xd + 5120;                                                       \
        int k0_ = (I) * 32;                                                             \
        _Pragma("unroll")                                                               \
        for (int j = 0; j < 2; j++) {                                                   \
            int idx = tid + j * 256; int r = idx >> 2, c = (idx & 3) * 8;               \
            cp16(Xd + r * BP + c, X + (size_t)(m0 + r) * Dd + k0_ + c);                 \
        }                                                                               \
        _Pragma("unroll")                                                               \
        for (int j = 0; j < 2; j++) {                                                   \
            int idx = tid + j * 256; int r = idx >> 2, c = (idx & 3) * 8;               \
            cp16(Wd + r * BP + c, W + (size_t)(hp * 128 + r) * Dd + k0_ + c);           \
        }                                                                               \
        asm volatile("cp.async.commit_group;");                                        \
    } while (0)

#define MAINLOOP(MMAOP)                                                                 \
    for (int i = 0; i < 32; i++) {                                                      \
        asm volatile("cp.async.wait_group 1;");                                         \
        __syncthreads();                                                                \
        if (i + 2 < 32) GLOAD(i + 2, (i + 2) % 3);                                      \
        else asm volatile("cp.async.commit_group;");                                    \
        const uint16_t* Xb_ = sb + (i % 3) * 10240;                                     \
        const uint16_t* Wb_ = Xb_ + 5120;                                               \
        _Pragma("unroll")                                                               \
        for (int ks = 0; ks < 2; ks++) {                                                \
            uint32_t a[2][4], b[4][4];                                                  \
            ldsm4(a[0], Xb_ + (wm * 32) * BP + ks * 16 + loA40);                        \
            ldsm4(a[1], Xb_ + (wm * 32 + 16) * BP + ks * 16 + loA40);                   \
            _Pragma("unroll")                                                           \
            for (int fnp = 0; fnp < 4; fnp++)                                           \
                ldsm4(b[fnp], Wb_ + (wn * 64 + fnp * 16) * BP + ks * 16 + loB40);       \
            _Pragma("unroll")                                                           \
            for (int fm = 0; fm < 2; fm++)                                              \
                _Pragma("unroll")                                                       \
                for (int fnp = 0; fnp < 4; fnp++) {                                     \
                    MMAOP(acc[fm][2 * fnp],     a[fm], b[fnp][0], b[fnp][1]);           \
                    MMAOP(acc[fm][2 * fnp + 1], a[fm], b[fnp][2], b[fnp][3]);           \
                }                                                                       \
        }                                                                               \
    }

    GLOAD(0, 0);
    GLOAD(1, 1);
    if (!VM) { MAINLOOP(mma16); }
    else     { MAINLOOP(mma16f); }
#undef MAINLOOP
#undef GLOAD

    const int b_ = m0 >> 10, s0 = m0 & 1023;
    if (!VM) {
        __nv_bfloat16* Y = (t == 0) ? g_Qb : g_Kb;
        const float sc = (t == 0) ? QSCALE : 1.0f;
        const int head = hp * 2 + wn;
        const float* bh_ = bias + head * 64;
#pragma unroll
        for (int fm = 0; fm < 2; fm++) {
#pragma unroll
            for (int fn = 0; fn < 8; fn++) {
                int col = fn * 8 + 2 * tg;
                float b0 = bh_[col], b1 = bh_[col + 1];
                int r0 = m0 + wm * 32 + fm * 16 + g, r1 = r0 + 8;
                uint32_t v0 = pack_bf2(fmaxf(acc[fm][fn][0] + b0, 0.f) * sc,
                                       fmaxf(acc[fm][fn][1] + b1, 0.f) * sc);
                uint32_t v1 = pack_bf2(fmaxf(acc[fm][fn][2] + b0, 0.f) * sc,
                                       fmaxf(acc[fm][fn][3] + b1, 0.f) * sc);
                {
                    int bb = r0 >> 10, s = r0 & 1023;
                    *(uint32_t*)((uint16_t*)Y + (((size_t)(bb * Hh + head)) * Ss + s) * DKk + col) = v0;
                }
                {
                    int bb = r1 >> 10, s = r1 & 1023;
                    *(uint32_t*)((uint16_t*)Y + (((size_t)(bb * Hh + head)) * Ss + s) * DKk + col) = v1;
                }
            }
        }
    } else {
        // ---- fused pass-2: V' = V @ Wo^T per head (fp16 mma) -----------------
        __syncthreads();
        uint16_t* Vt  = sb;                  // [128][136] fp16 (34816 B)
        uint16_t* WoS = sb + 128 * 136;      // [64][72]   fp16 ( 9216 B)

#pragma unroll
        for (int fm = 0; fm < 2; fm++) {
#pragma unroll
            for (int fn = 0; fn < 8; fn++) {
                int col = wn * 64 + fn * 8 + 2 * tg;
                float b0 = bias[hp * 128 + col], b1 = bias[hp * 128 + col + 1];
                int lr0 = wm * 32 + fm * 16 + g, lr1 = lr0 + 8;
                *(uint32_t*)(Vt + lr0 * 136 + col) = pack_hf2(fmaxf(acc[fm][fn][0] + b0, 0.f),
                                                              fmaxf(acc[fm][fn][1] + b1, 0.f));
                *(uint32_t*)(Vt + lr1 * 136 + col) = pack_hf2(fmaxf(acc[fm][fn][2] + b0, 0.f),
                                                              fmaxf(acc[fm][fn][3] + b1, 0.f));
            }
        }
#pragma unroll
        for (int j = 0; j < 4; j++) {
            int idx = tid + j * 256; int r = idx >> 4, c = (idx & 15) * 4;
            float4 wv = *(const float4*)(Wo + r * 64 + c);
            *(uint32_t*)(WoS + r * 72 + c)     = pack_hf2(wv.x, wv.y);
            *(uint32_t*)(WoS + r * 72 + c + 2) = pack_hf2(wv.z, wv.w);
        }
        __syncthreads();

        const int loA136 = ((lane & 7) + ((lane >> 3) & 1) * 8) * 136 + ((lane >> 4) & 1) * 8;
        const int loB72  = ((lane & 7) + ((lane >> 4) & 1) * 8) * 72 + ((lane >> 3) & 1) * 8;

#pragma unroll
        for (int j = 0; j < 2; j++) {
            const int head = hp * 2 + j, bh = b_ * Hh + head;
            float acc2[2][4][4] = {};
#pragma unroll
            for (int ks = 0; ks < 4; ks++) {
                uint32_t a[2][4], bfr[2][4];
                ldsm4(a[0], Vt + (wm * 32) * 136 + j * 64 + ks * 16 + loA136);
                ldsm4(a[1], Vt + (wm * 32 + 16) * 136 + j * 64 + ks * 16 + loA136);
                ldsm4(bfr[0], WoS + (wn * 32) * 72 + ks * 16 + loB72);
                ldsm4(bfr[1], WoS + (wn * 32 + 16) * 72 + ks * 16 + loB72);
#pragma unroll
                for (int fm = 0; fm < 2; fm++) {
                    mma16f(acc2[fm][0], a[fm], bfr[0][0], bfr[0][1]);
                    mma16f(acc2[fm][1], a[fm], bfr[0][2], bfr[0][3]);
                    mma16f(acc2[fm][2], a[fm], bfr[1][0], bfr[1][1]);
                    mma16f(acc2[fm][3], a[fm], bfr[1][2], bfr[1][3]);
                }
            }
            uint16_t* dst = (uint16_t*)g_Vp + ((size_t)bh * Ss + s0) * DKk;
#pragma unroll
            for (int fm = 0; fm < 2; fm++) {
#pragma unroll
                for (int fn = 0; fn < 4; fn++) {
                    int col = wn * 32 + fn * 8 + 2 * tg;
                    int lr0 = wm * 32 + fm * 16 + g, lr1 = lr0 + 8;
                    *(uint32_t*)(dst + (size_t)lr0 * DKk + col) =
                        pack_hf2(acc2[fm][fn][0], acc2[fm][fn][1]);
                    *(uint32_t*)(dst + (size_t)lr1 * DKk + col) =
                        pack_hf2(acc2[fm][fn][2], acc2[fm][fn][3]);
                }
            }
        }
    }
}

// ---------------------------------------------------------------------------
// Flash attention: S bf16 + exp2 softmax, PV fp16 with trans-ldmatrix V'.
// NEW: 3-stage K/V ring, single __syncthreads per tile, forced 2 CTAs/SM.
// smem: Kb[3][64][72] + Vb[3][64][72] + Ps[8][16][72] (u16) + ms[3][64] = 74496 B
// ---------------------------------------------------------------------------
#define KP 72
__global__ __launch_bounds__(256, 2) void attn_tc(const int* __restrict__ mask,
                                                  const float* __restrict__ bo,
                                                  float* __restrict__ out) {
    extern __shared__ char smraw[];
    uint16_t* Kb = (uint16_t*)smraw;                   // [3][64][72]  27648 B
    uint16_t* Vb = (uint16_t*)(smraw + 27648);         // [3][64][72]  27648 B
    uint16_t* Ps = (uint16_t*)(smraw + 55296);         // [8][16][72]  18432 B (Q staging too)
    int* ms = (int*)(smraw + 73728);                   // [3][64]        768 B

    int bh = blockIdx.y, q0 = blockIdx.x * 128;
    const uint16_t* Qg = (const uint16_t*)g_Qb + ((size_t)bh * Ss + q0) * DKk;
    const uint16_t* Kg = (const uint16_t*)g_Kb + (size_t)bh * Ss * DKk;
    const uint16_t* Vg = (const uint16_t*)g_Vp + (size_t)bh * Ss * DKk;

    int tid = threadIdx.x, w = tid >> 5, lane = tid & 31, g = lane >> 2, tg = lane & 3;
    const int loA72 = ((lane & 7) + ((lane >> 3) & 1) * 8) * KP + ((lane >> 4) & 1) * 8;
    const int loB72 = ((lane & 7) + ((lane >> 4) & 1) * 8) * KP + ((lane >> 3) & 1) * 8;
    const int loBT72 = ((lane & 7) + ((lane >> 3) & 1) * 8) * KP + ((lane >> 4) & 1) * 8;

    // ---- stage Q (bf16) into Ps region, extract per-warp A-fragments --------
#pragma unroll
    for (int j = 0; j < 4; j++) {
        int idx = tid + j * 256; int r = idx >> 3, c = (idx & 7) * 8;
        *(uint4*)(Ps + r * KP + c) = *(const uint4*)(Qg + (size_t)r * DKk + c);
    }
    __syncthreads();
    uint32_t qa[4][4];
#pragma unroll
    for (int ks = 0; ks < 4; ks++)
        ldsm4(qa[ks], Ps + w * 16 * KP + ks * 16 + loA72);
    uint16_t* Pw = Ps + w * 16 * KP;   // per-warp P slice (own rows only)

#define AFILL(KT, BUF)                                                                  \
    do {                                                                                \
        const uint16_t* kg = Kg + (size_t)(KT) * 64 * DKk;                              \
        const uint16_t* vg = Vg + (size_t)(KT) * 64 * DKk;                              \
        _Pragma("unroll")                                                               \
        for (int j = 0; j < 2; j++) {                                                   \
            int idx = tid + j * 256; int r = idx >> 3, c = (idx & 7) * 8;               \
            cp16(Kb + ((BUF) * 64 + r) * KP + c, kg + (size_t)r * DKk + c);             \
            cp16(Vb + ((BUF) * 64 + r) * KP + c, vg + (size_t)r * DKk + c);             \
        }                                                                               \
        if (tid < 16)                                                                   \
            cp16(ms + (BUF) * 64 + tid * 4, mask + (size_t)bh * Ss + (KT) * 64 + tid * 4); \
        asm volatile("cp.async.commit_group;");                                        \
    } while (0)

    float oacc[8][4] = {};
    float mrow[2] = {-1e30f, -1e30f};
    float lrow[2] = {0.f, 0.f};

    AFILL(0, 0);
    AFILL(1, 1);
    for (int kt = 0; kt < 16; kt++) {
        int buf = kt % 3;
        // in-order group retirement: after wait_group 1, only the newest group
        // (fill kt+1 / empty) may be pending -> fill(kt) is complete.
        asm volatile("cp.async.wait_group 1;");
        __syncthreads();  // all warps done with buffer (kt-1)%3 == (kt+2)%3
        if (kt + 2 < 16) AFILL(kt + 2, (kt + 2) % 3);
        else asm volatile("cp.async.commit_group;");

        const uint16_t* Kt = Kb + buf * 64 * KP;
        const uint16_t* Vt = Vb + buf * 64 * KP;
        const int* mt = ms + buf * 64;

        // ---- S = Q' @ K^T (bf16, exp2 domain) -------------------------------
        float sacc[8][4] = {};
#pragma unroll
        for (int ks = 0; ks < 4; ks++) {
#pragma unroll
            for (int fnp = 0; fnp < 4; fnp++) {
                uint32_t b[4];
                ldsm4(b, Kt + fnp * 16 * KP + ks * 16 + loB72);
                mma16(sacc[2 * fnp],     qa[ks], b[0], b[1]);
                mma16(sacc[2 * fnp + 1], qa[ks], b[2], b[3]);
            }
        }
        // mask
#pragma unroll
        for (int fn = 0; fn < 8; fn++) {
            int c0 = fn * 8 + 2 * tg;
            bool k0m = (mt[c0] == 0), k1m = (mt[c0 + 1] == 0);
            if (k0m) { sacc[fn][0] = MASKVAL; sacc[fn][2] = MASKVAL; }
            if (k1m) { sacc[fn][1] = MASKVAL; sacc[fn][3] = MASKVAL; }
        }
        // online softmax (rows g and g+8), exp2 domain
        float mxA = -1e30f, mxB = -1e30f;
#pragma unroll
        for (int fn = 0; fn < 8; fn++) {
            mxA = fmaxf(mxA, fmaxf(sacc[fn][0], sacc[fn][1]));
            mxB = fmaxf(mxB, fmaxf(sacc[fn][2], sacc[fn][3]));
        }
        mxA = fmaxf(mxA, __shfl_xor_sync(~0u, mxA, 1));
        mxA = fmaxf(mxA, __shfl_xor_sync(~0u, mxA, 2));
        mxB = fmaxf(mxB, __shfl_xor_sync(~0u, mxB, 1));
        mxB = fmaxf(mxB, __shfl_xor_sync(~0u, mxB, 2));
        float mAn = fmaxf(mrow[0], mxA), mBn = fmaxf(mrow[1], mxB);
        float aA = ex2f(mrow[0] - mAn), aB = ex2f(mrow[1] - mBn);
        mrow[0] = mAn; mrow[1] = mBn;
        float sA = 0.f, sB = 0.f;
#pragma unroll
        for (int fn = 0; fn < 8; fn++) {
            sacc[fn][0] = ex2f(sacc[fn][0] - mAn);
            sacc[fn][1] = ex2f(sacc[fn][1] - mAn);
            sacc[fn][2] = ex2f(sacc[fn][2] - mBn);
            sacc[fn][3] = ex2f(sacc[fn][3] - mBn);
            sA += sacc[fn][0] + sacc[fn][1];
            sB += sacc[fn][2] + sacc[fn][3];
        }
        sA += __shfl_xor_sync(~0u, sA, 1); sA += __shfl_xor_sync(~0u, sA, 2);
        sB += __shfl_xor_sync(~0u, sB, 1); sB += __shfl_xor_sync(~0u, sB, 2);
        lrow[0] = lrow[0] * aA + sA;
        lrow[1] = lrow[1] * aB + sB;
#pragma unroll
        for (int fn = 0; fn < 8; fn++) {
            oacc[fn][0] *= aA; oacc[fn][1] *= aA; oacc[fn][2] *= aB; oacc[fn][3] *= aB;
        }
        // stage P (fp16) in per-warp smem slice
#pragma unroll
        for (int fn = 0; fn < 8; fn++) {
            int c0 = fn * 8 + 2 * tg;
            *(uint32_t*)(Pw + g * KP + c0)       = pack_hf2(sacc[fn][0], sacc[fn][1]);
            *(uint32_t*)(Pw + (g + 8) * KP + c0) = pack_hf2(sacc[fn][2], sacc[fn][3]);
        }
        __syncwarp();
        // ---- O += P @ V' (fp16 mma, trans B from V'[s][d]) -------------------
#pragma unroll
        for (int ks = 0; ks < 4; ks++) {
            uint32_t pa[4];
            ldsm4(pa, Pw + ks * 16 + loA72);
#pragma unroll
            for (int fnp = 0; fnp < 4; fnp++) {
                uint32_t b[4];
                ldsm4t(b, Vt + (ks * 16) * KP + fnp * 16 + loBT72);
                mma16f(oacc[2 * fnp],     pa, b[0], b[1]);
                mma16f(oacc[2 * fnp + 1], pa, b[2], b[3]);
            }
        }
        // no trailing __syncthreads: next iteration's barrier protects the ring
    }
#undef AFILL

    // ---- epilogue: normalize, +bo, transpose-out write ----------------------
    float invA = 1.f / lrow[0], invB = 1.f / lrow[1];
    int b_ = bh >> 4, h = bh & 15;
#pragma unroll
    for (int fn = 0; fn < 8; fn++) {
        int col = fn * 8 + 2 * tg;
        float b0v = bo[col], b1v = bo[col + 1];
        int r0 = q0 + w * 16 + g, r1 = r0 + 8;
        *(float2*)(out + ((size_t)(b_ * Ss + r0)) * Dd + h * 64 + col) =
            make_float2(oacc[fn][0] * invA + b0v, oacc[fn][1] * invA + b1v);
        *(float2*)(out + ((size_t)(b_ * Ss + r1)) * Dd + h * 64 + col) =
            make_float2(oacc[fn][2] * invB + b0v, oacc[fn][3] * invB + b1v);
    }
}

// ---------------------------------------------------------------------------
extern "C" void kernel_launch(void* const* d_in, const int* in_sizes, int n_in,
                              void* d_out, int out_size) {
    const float* q   = (const float*)d_in[0];
    const float* k   = (const float*)d_in[1];
    const float* v   = (const float*)d_in[2];
    const int*   msk = (const int*)d_in[3];
    const float* Wq  = (const float*)d_in[4];
    const float* bq  = (const float*)d_in[5];
    const float* Wk  = (const float*)d_in[6];
    const float* bk  = (const float*)d_in[7];
    const float* Wv  = (const float*)d_in[8];
    const float* bv  = (const float*)d_in[9];
    const float* Wqf = (const float*)d_in[10];
    const float* bqf = (const float*)d_in[11];
    const float* Wkf = (const float*)d_in[12];
    const float* bkf = (const float*)d_in[13];
    const float* Wvf = (const float*)d_in[14];
    const float* bvf = (const float*)d_in[15];
    const float* Wo  = (const float*)d_in[16];
    const float* bo  = (const float*)d_in[17];
    float* out = (float*)d_out;

    const int proj_smem = 3 * 2 * 128 * BP * 2;  // 61440
    const int attn_smem = 74496;

    static int cfg = 0;
    if (!cfg) {
        cudaFuncSetAttribute(proj_all, cudaFuncAttributeMaxDynamicSharedMemorySize, proj_smem);
        cudaFuncSetAttribute(attn_tc, cudaFuncAttributeMaxDynamicSharedMemorySize, attn_smem);
        cfg = 1;
    }

    preround<<<4096, 256>>>(q, k, v);
    fold_kernel<<<dim3(16, 16, 3), 256>>>(Wq, Wqf, Wk, Wkf, Wv, Wvf);
    bfold_kernel<<<3, 1024>>>(bq, bqf, bk, bkf, bv, bvf, Wqf, Wkf, Wvf);
    proj_all<<<dim3(8, 32, 3), 256, proj_smem>>>(Wo);
    attn_tc<<<dim3(8, 64), 256, attn_smem>>>(msk, bo, out);
}

// round 10
// speedup vs baseline: 5.0452x; 1.0287x over previous
#include <cuda_runtime.h>
#include <cuda_bf16.h>
#include <cuda_fp16.h>
#include <math.h>
#include <stdint.h>

#define Bb 4
#define Ss 1024
#define Dd 1024
#define Hh 16
#define DKk 64

#define QSCALE 0.18033688011112042f
#define MASKVAL -14426.950408889634f

// ---------------------------------------------------------------------------
// Device scratch
// ---------------------------------------------------------------------------
__device__ __nv_bfloat16 g_Xb[2][4096 * 1024];   // bf16 q,k inputs
__device__ __half        g_Xf[4096 * 1024];      // fp16 v input
__device__ __nv_bfloat16 g_Wcb[2][1024 * 1024];  // folded Wq,Wk (bf16)
__device__ __half        g_Wcf[1024 * 1024];     // folded Wv (fp16)
__device__ float         g_bc[3][1024];          // folded biases
__device__ __nv_bfloat16 g_Qb[64 * 1024 * 64];   // per-head Q (bf16, pre-scaled)
__device__ __nv_bfloat16 g_Kb[64 * 1024 * 64];   // per-head K (bf16)
__device__ __half        g_Vp[64 * 1024 * 64];   // V' = V @ Wo^T (fp16) [bh][s][d]

// ---------------------------------------------------------------------------
// helpers
// ---------------------------------------------------------------------------
__device__ __forceinline__ void mma16(float (&d)[4], const uint32_t (&a)[4],
                                      uint32_t b0, uint32_t b1) {
    asm volatile(
        "mma.sync.aligned.m16n8k16.row.col.f32.bf16.bf16.f32 "
        "{%0,%1,%2,%3},{%4,%5,%6,%7},{%8,%9},{%0,%1,%2,%3};"
        : "+f"(d[0]), "+f"(d[1]), "+f"(d[2]), "+f"(d[3])
        : "r"(a[0]), "r"(a[1]), "r"(a[2]), "r"(a[3]), "r"(b0), "r"(b1));
}
__device__ __forceinline__ void mma16f(float (&d)[4], const uint32_t (&a)[4],
                                       uint32_t b0, uint32_t b1) {
    asm volatile(
        "mma.sync.aligned.m16n8k16.row.col.f32.f16.f16.f32 "
        "{%0,%1,%2,%3},{%4,%5,%6,%7},{%8,%9},{%0,%1,%2,%3};"
        : "+f"(d[0]), "+f"(d[1]), "+f"(d[2]), "+f"(d[3])
        : "r"(a[0]), "r"(a[1]), "r"(a[2]), "r"(a[3]), "r"(b0), "r"(b1));
}
__device__ __forceinline__ void ldsm4(uint32_t (&r)[4], const uint16_t* p) {
    uint32_t a = (uint32_t)__cvta_generic_to_shared(p);
    asm volatile("ldmatrix.sync.aligned.m8n8.x4.shared.b16 {%0,%1,%2,%3},[%4];"
                 : "=r"(r[0]), "=r"(r[1]), "=r"(r[2]), "=r"(r[3]) : "r"(a));
}
__device__ __forceinline__ void ldsm4t(uint32_t (&r)[4], const uint16_t* p) {
    uint32_t a = (uint32_t)__cvta_generic_to_shared(p);
    asm volatile("ldmatrix.sync.aligned.m8n8.x4.trans.shared.b16 {%0,%1,%2,%3},[%4];"
                 : "=r"(r[0]), "=r"(r[1]), "=r"(r[2]), "=r"(r[3]) : "r"(a));
}
__device__ __forceinline__ void cp16(void* s, const void* g) {
    uint32_t sa = (uint32_t)__cvta_generic_to_shared(s);
    asm volatile("cp.async.cg.shared.global [%0], [%1], 16;" :: "r"(sa), "l"(g));
}
__device__ __forceinline__ uint32_t pack_bf2(float a, float b) {
    __nv_bfloat162 t = __float22bfloat162_rn(make_float2(a, b));
    return *reinterpret_cast<uint32_t*>(&t);
}
__device__ __forceinline__ uint32_t pack_hf2(float a, float b) {
    __half2 t = __floats2half2_rn(a, b);
    return *reinterpret_cast<uint32_t*>(&t);
}
__device__ __forceinline__ float ex2f(float x) {
    float y; asm("ex2.approx.f32 %0,%1;" : "=f"(y) : "f"(x)); return y;
}

// ---------------------------------------------------------------------------
// preround: q,k -> bf16 ; v -> fp16
// ---------------------------------------------------------------------------
__global__ void preround(const float* __restrict__ q, const float* __restrict__ k,
                         const float* __restrict__ v) {
    size_t i = (size_t)blockIdx.x * blockDim.x + threadIdx.x;  // float4 index
    float4 a = ((const float4*)q)[i];
    uint32_t* dq = (uint32_t*)g_Xb[0];
    dq[i * 2] = pack_bf2(a.x, a.y); dq[i * 2 + 1] = pack_bf2(a.z, a.w);
    float4 b = ((const float4*)k)[i];
    uint32_t* dk = (uint32_t*)g_Xb[1];
    dk[i * 2] = pack_bf2(b.x, b.y); dk[i * 2 + 1] = pack_bf2(b.z, b.w);
    float4 c = ((const float4*)v)[i];
    uint32_t* dv = (uint32_t*)g_Xf;
    dv[i * 2] = pack_hf2(c.x, c.y); dv[i * 2 + 1] = pack_hf2(c.z, c.w);
}

// ---------------------------------------------------------------------------
// Fold: Wc[t][(h*64+o)*1024 + j] = sum_i Wf[o,i] * Wbig[h*64+i, j]
// ---------------------------------------------------------------------------
__global__ void fold_kernel(const float* __restrict__ Wq, const float* __restrict__ Wqf,
                            const float* __restrict__ Wk, const float* __restrict__ Wkf,
                            const float* __restrict__ Wv, const float* __restrict__ Wvf) {
    int t = blockIdx.z, h = blockIdx.y, j0 = blockIdx.x * 64;
    const float* Wbig = (t == 0) ? Wq : (t == 1) ? Wk : Wv;
    const float* Wf   = (t == 0) ? Wqf : (t == 1) ? Wkf : Wvf;

    __shared__ float fs[64][65];
    __shared__ float bs[64][65];

    int tid = threadIdx.x;
    for (int idx = tid; idx < 64 * 16; idx += 256) {
        int r = idx >> 4, c4 = (idx & 15) * 4;
        float4 fv = *(const float4*)(Wf + r * 64 + c4);
        fs[r][c4] = fv.x; fs[r][c4 + 1] = fv.y; fs[r][c4 + 2] = fv.z; fs[r][c4 + 3] = fv.w;
        float4 bv = *(const float4*)(Wbig + (h * 64 + r) * Dd + j0 + c4);
        bs[r][c4] = bv.x; bs[r][c4 + 1] = bv.y; bs[r][c4 + 2] = bv.z; bs[r][c4 + 3] = bv.w;
    }
    __syncthreads();

    int ty = tid >> 4, tx = tid & 15;
    float acc[4][4] = {};
#pragma unroll 8
    for (int i = 0; i < 64; i++) {
        float a[4], b[4];
#pragma unroll
        for (int u = 0; u < 4; u++) { a[u] = fs[ty * 4 + u][i]; b[u] = bs[i][tx * 4 + u]; }
#pragma unroll
        for (int u = 0; u < 4; u++)
#pragma unroll
            for (int w = 0; w < 4; w++) acc[u][w] += a[u] * b[w];
    }
    if (t < 2) {
        uint32_t* dst = (uint32_t*)g_Wcb[t];
#pragma unroll
        for (int u = 0; u < 4; u++) {
            size_t row = (size_t)(h * 64 + ty * 4 + u) * Dd + j0 + tx * 4;
            dst[row / 2]     = pack_bf2(acc[u][0], acc[u][1]);
            dst[row / 2 + 1] = pack_bf2(acc[u][2], acc[u][3]);
        }
    } else {
        uint32_t* dst = (uint32_t*)g_Wcf;
#pragma unroll
        for (int u = 0; u < 4; u++) {
            size_t row = (size_t)(h * 64 + ty * 4 + u) * Dd + j0 + tx * 4;
            dst[row / 2]     = pack_hf2(acc[u][0], acc[u][1]);
            dst[row / 2 + 1] = pack_hf2(acc[u][2], acc[u][3]);
        }
    }
}

__global__ void bfold_kernel(const float* __restrict__ bq, const float* __restrict__ bqf,
                             const float* __restrict__ bk, const float* __restrict__ bkf,
                             const float* __restrict__ bv, const float* __restrict__ bvf,
                             const float* __restrict__ Wqf, const float* __restrict__ Wkf,
                             const float* __restrict__ Wvf) {
    int t = blockIdx.x, n = threadIdx.x;
    const float* b1 = (t == 0) ? bq : (t == 1) ? bk : bv;
    const float* b2 = (t == 0) ? bqf : (t == 1) ? bkf : bvf;
    const float* Wf = (t == 0) ? Wqf : (t == 1) ? Wkf : Wvf;
    int h = n >> 6, o = n & 63;
    float s = b2[o];
    for (int i = 0; i < 64; i++) s += Wf[o * 64 + i] * b1[h * 64 + i];
    g_bc[t][n] = s;
}

// ---------------------------------------------------------------------------
// Unified projection GEMM (unchanged, at mma.sync floor).
// ---------------------------------------------------------------------------
#define BP 40
__global__ __launch_bounds__(256) void proj_all(const float* __restrict__ Wo) {
    extern __shared__ uint16_t sb[];

    const int t = blockIdx.z;
    const bool VM = (t == 2);
    const uint16_t* X = VM ? (const uint16_t*)g_Xf : (const uint16_t*)g_Xb[t];
    const uint16_t* W = VM ? (const uint16_t*)g_Wcf : (const uint16_t*)g_Wcb[t];
    const float* bias = g_bc[t];
    const int hp = blockIdx.x;
    const int m0 = blockIdx.y * 128;

    const int tid = threadIdx.x;
    const int w = tid >> 5, lane = tid & 31, g = lane >> 2, tg = lane & 3;
    const int wm = w & 3, wn = w >> 2;

    const int loA40 = ((lane & 7) + ((lane >> 3) & 1) * 8) * BP + ((lane >> 4) & 1) * 8;
    const int loB40 = ((lane & 7) + ((lane >> 4) & 1) * 8) * BP + ((lane >> 3) & 1) * 8;

    float acc[2][8][4] = {};

#define GLOAD(I, S)                                                                     \
    do {                                                                                \
        uint16_t* Xd = sb + (S) * 10240;                                                \
        uint16_t* Wd = Xd + 5120;                                                       \
        int k0_ = (I) * 32;                                                             \
        _Pragma("unroll")                                                               \
        for (int j = 0; j < 2; j++) {                                                   \
            int idx = tid + j * 256; int r = idx >> 2, c = (idx & 3) * 8;               \
            cp16(Xd + r * BP + c, X + (size_t)(m0 + r) * Dd + k0_ + c);                 \
        }                                                                               \
        _Pragma("unroll")                                                               \
        for (int j = 0; j < 2; j++) {                                                   \
            int idx = tid + j * 256; int r = idx >> 2, c = (idx & 3) * 8;               \
            cp16(Wd + r * BP + c, W + (size_t)(hp * 128 + r) * Dd + k0_ + c);           \
        }                                                                               \
        asm volatile("cp.async.commit_group;");                                        \
    } while (0)

#define MAINLOOP(MMAOP)                                                                 \
    for (int i = 0; i < 32; i++) {                                                      \
        asm volatile("cp.async.wait_group 1;");                                         \
        __syncthreads();                                                                \
        if (i + 2 < 32) GLOAD(i + 2, (i + 2) % 3);                                      \
        else asm volatile("cp.async.commit_group;");                                    \
        const uint16_t* Xb_ = sb + (i % 3) * 10240;                                     \
        const uint16_t* Wb_ = Xb_ + 5120;                                               \
        _Pragma("unroll")                                                               \
        for (int ks = 0; ks < 2; ks++) {                                                \
            uint32_t a[2][4], b[4][4];                                                  \
            ldsm4(a[0], Xb_ + (wm * 32) * BP + ks * 16 + loA40);                        \
            ldsm4(a[1], Xb_ + (wm * 32 + 16) * BP + ks * 16 + loA40);                   \
            _Pragma("unroll")                                                           \
            for (int fnp = 0; fnp < 4; fnp++)                                           \
                ldsm4(b[fnp], Wb_ + (wn * 64 + fnp * 16) * BP + ks * 16 + loB40);       \
            _Pragma("unroll")                                                           \
            for (int fm = 0; fm < 2; fm++)                                              \
                _Pragma("unroll")                                                       \
                for (int fnp = 0; fnp < 4; fnp++) {                                     \
                    MMAOP(acc[fm][2 * fnp],     a[fm], b[fnp][0], b[fnp][1]);           \
                    MMAOP(acc[fm][2 * fnp + 1], a[fm], b[fnp][2], b[fnp][3]);           \
                }                                                                       \
        }                                                                               \
    }

    GLOAD(0, 0);
    GLOAD(1, 1);
    if (!VM) { MAINLOOP(mma16); }
    else     { MAINLOOP(mma16f); }
#undef MAINLOOP
#undef GLOAD

    const int b_ = m0 >> 10, s0 = m0 & 1023;
    if (!VM) {
        __nv_bfloat16* Y = (t == 0) ? g_Qb : g_Kb;
        const float sc = (t == 0) ? QSCALE : 1.0f;
        const int head = hp * 2 + wn;
        const float* bh_ = bias + head * 64;
#pragma unroll
        for (int fm = 0; fm < 2; fm++) {
#pragma unroll
            for (int fn = 0; fn < 8; fn++) {
                int col = fn * 8 + 2 * tg;
                float b0 = bh_[col], b1 = bh_[col + 1];
                int r0 = m0 + wm * 32 + fm * 16 + g, r1 = r0 + 8;
                uint32_t v0 = pack_bf2(fmaxf(acc[fm][fn][0] + b0, 0.f) * sc,
                                       fmaxf(acc[fm][fn][1] + b1, 0.f) * sc);
                uint32_t v1 = pack_bf2(fmaxf(acc[fm][fn][2] + b0, 0.f) * sc,
                                       fmaxf(acc[fm][fn][3] + b1, 0.f) * sc);
                {
                    int bb = r0 >> 10, s = r0 & 1023;
                    *(uint32_t*)((uint16_t*)Y + (((size_t)(bb * Hh + head)) * Ss + s) * DKk + col) = v0;
                }
                {
                    int bb = r1 >> 10, s = r1 & 1023;
                    *(uint32_t*)((uint16_t*)Y + (((size_t)(bb * Hh + head)) * Ss + s) * DKk + col) = v1;
                }
            }
        }
    } else {
        // ---- fused pass-2: V' = V @ Wo^T per head (fp16 mma) -----------------
        __syncthreads();
        uint16_t* Vt  = sb;                  // [128][136] fp16 (34816 B)
        uint16_t* WoS = sb + 128 * 136;      // [64][72]   fp16 ( 9216 B)

#pragma unroll
        for (int fm = 0; fm < 2; fm++) {
#pragma unroll
            for (int fn = 0; fn < 8; fn++) {
                int col = wn * 64 + fn * 8 + 2 * tg;
                float b0 = bias[hp * 128 + col], b1 = bias[hp * 128 + col + 1];
                int lr0 = wm * 32 + fm * 16 + g, lr1 = lr0 + 8;
                *(uint32_t*)(Vt + lr0 * 136 + col) = pack_hf2(fmaxf(acc[fm][fn][0] + b0, 0.f),
                                                              fmaxf(acc[fm][fn][1] + b1, 0.f));
                *(uint32_t*)(Vt + lr1 * 136 + col) = pack_hf2(fmaxf(acc[fm][fn][2] + b0, 0.f),
                                                              fmaxf(acc[fm][fn][3] + b1, 0.f));
            }
        }
#pragma unroll
        for (int j = 0; j < 4; j++) {
            int idx = tid + j * 256; int r = idx >> 4, c = (idx & 15) * 4;
            float4 wv = *(const float4*)(Wo + r * 64 + c);
            *(uint32_t*)(WoS + r * 72 + c)     = pack_hf2(wv.x, wv.y);
            *(uint32_t*)(WoS + r * 72 + c + 2) = pack_hf2(wv.z, wv.w);
        }
        __syncthreads();

        const int loA136 = ((lane & 7) + ((lane >> 3) & 1) * 8) * 136 + ((lane >> 4) & 1) * 8;
        const int loB72  = ((lane & 7) + ((lane >> 4) & 1) * 8) * 72 + ((lane >> 3) & 1) * 8;

#pragma unroll
        for (int j = 0; j < 2; j++) {
            const int head = hp * 2 + j, bh = b_ * Hh + head;
            float acc2[2][4][4] = {};
#pragma unroll
            for (int ks = 0; ks < 4; ks++) {
                uint32_t a[2][4], bfr[2][4];
                ldsm4(a[0], Vt + (wm * 32) * 136 + j * 64 + ks * 16 + loA136);
                ldsm4(a[1], Vt + (wm * 32 + 16) * 136 + j * 64 + ks * 16 + loA136);
                ldsm4(bfr[0], WoS + (wn * 32) * 72 + ks * 16 + loB72);
                ldsm4(bfr[1], WoS + (wn * 32 + 16) * 72 + ks * 16 + loB72);
#pragma unroll
                for (int fm = 0; fm < 2; fm++) {
                    mma16f(acc2[fm][0], a[fm], bfr[0][0], bfr[0][1]);
                    mma16f(acc2[fm][1], a[fm], bfr[0][2], bfr[0][3]);
                    mma16f(acc2[fm][2], a[fm], bfr[1][0], bfr[1][1]);
                    mma16f(acc2[fm][3], a[fm], bfr[1][2], bfr[1][3]);
                }
            }
            uint16_t* dst = (uint16_t*)g_Vp + ((size_t)bh * Ss + s0) * DKk;
#pragma unroll
            for (int fm = 0; fm < 2; fm++) {
#pragma unroll
                for (int fn = 0; fn < 4; fn++) {
                    int col = wn * 32 + fn * 8 + 2 * tg;
                    int lr0 = wm * 32 + fm * 16 + g, lr1 = lr0 + 8;
                    *(uint32_t*)(dst + (size_t)lr0 * DKk + col) =
                        pack_hf2(acc2[fm][fn][0], acc2[fm][fn][1]);
                    *(uint32_t*)(dst + (size_t)lr1 * DKk + col) =
                        pack_hf2(acc2[fm][fn][2], acc2[fm][fn][3]);
                }
            }
        }
    }
}

// ---------------------------------------------------------------------------
// Flash attention v3: fixed-max exp2 softmax (logits bounded tiny; masked ->
// exp2(MASKVAL)=0 exactly), P kept in REGISTERS (S accumulator layout == PV
// A-operand layout), single sum-reduction at epilogue. 3-stage K/V ring,
// one __syncthreads per tile, 2 CTAs/SM.
// smem: Kb[3][64][72] + Vb[3][64][72] + Qstage[128][72] (u16) + ms[3][64]
// ---------------------------------------------------------------------------
#define KP 72
__global__ __launch_bounds__(256, 2) void attn_tc(const int* __restrict__ mask,
                                                  const float* __restrict__ bo,
                                                  float* __restrict__ out) {
    extern __shared__ char smraw[];
    uint16_t* Kb = (uint16_t*)smraw;                   // [3][64][72]  27648 B
    uint16_t* Vb = (uint16_t*)(smraw + 27648);         // [3][64][72]  27648 B
    uint16_t* Qs = (uint16_t*)(smraw + 55296);         // [128][72]    18432 B
    int* ms = (int*)(smraw + 73728);                   // [3][64]        768 B

    int bh = blockIdx.y, q0 = blockIdx.x * 128;
    const uint16_t* Qg = (const uint16_t*)g_Qb + ((size_t)bh * Ss + q0) * DKk;
    const uint16_t* Kg = (const uint16_t*)g_Kb + (size_t)bh * Ss * DKk;
    const uint16_t* Vg = (const uint16_t*)g_Vp + (size_t)bh * Ss * DKk;

    int tid = threadIdx.x, w = tid >> 5, lane = tid & 31, g = lane >> 2, tg = lane & 3;
    const int loA72 = ((lane & 7) + ((lane >> 3) & 1) * 8) * KP + ((lane >> 4) & 1) * 8;
    const int loB72 = ((lane & 7) + ((lane >> 4) & 1) * 8) * KP + ((lane >> 3) & 1) * 8;
    const int loBT72 = ((lane & 7) + ((lane >> 3) & 1) * 8) * KP + ((lane >> 4) & 1) * 8;

    // ---- stage Q (bf16), extract per-warp A-fragments ------------------------
#pragma unroll
    for (int j = 0; j < 4; j++) {
        int idx = tid + j * 256; int r = idx >> 3, c = (idx & 7) * 8;
        *(uint4*)(Qs + r * KP + c) = *(const uint4*)(Qg + (size_t)r * DKk + c);
    }
    __syncthreads();
    uint32_t qa[4][4];
#pragma unroll
    for (int ks = 0; ks < 4; ks++)
        ldsm4(qa[ks], Qs + w * 16 * KP + ks * 16 + loA72);

#define AFILL(KT, BUF)                                                                  \
    do {                                                                                \
        const uint16_t* kg = Kg + (size_t)(KT) * 64 * DKk;                              \
        const uint16_t* vg = Vg + (size_t)(KT) * 64 * DKk;                              \
        _Pragma("unroll")                                                               \
        for (int j = 0; j < 2; j++) {                                                   \
            int idx = tid + j * 256; int r = idx >> 3, c = (idx & 7) * 8;               \
            cp16(Kb + ((BUF) * 64 + r) * KP + c, kg + (size_t)r * DKk + c);             \
            cp16(Vb + ((BUF) * 64 + r) * KP + c, vg + (size_t)r * DKk + c);             \
        }                                                                               \
        if (tid < 16)                                                                   \
            cp16(ms + (BUF) * 64 + tid * 4, mask + (size_t)bh * Ss + (KT) * 64 + tid * 4); \
        asm volatile("cp.async.commit_group;");                                        \
    } while (0)

    float oacc[8][4] = {};
    float sumA = 0.f, sumB = 0.f;   // row sums (fixed max = 0, purely additive)

    AFILL(0, 0);
    AFILL(1, 1);
    for (int kt = 0; kt < 16; kt++) {
        int buf = kt % 3;
        asm volatile("cp.async.wait_group 1;");
        __syncthreads();  // all warps done with ring slot (kt+2)%3 == (kt-1)%3
        if (kt + 2 < 16) AFILL(kt + 2, (kt + 2) % 3);
        else asm volatile("cp.async.commit_group;");

        const uint16_t* Kt = Kb + buf * 64 * KP;
        const uint16_t* Vt = Vb + buf * 64 * KP;
        const int* mt = ms + buf * 64;

        // ---- S = Q' @ K^T (bf16, exp2 domain) -------------------------------
        float sacc[8][4] = {};
#pragma unroll
        for (int ks = 0; ks < 4; ks++) {
#pragma unroll
            for (int fnp = 0; fnp < 4; fnp++) {
                uint32_t b[4];
                ldsm4(b, Kt + fnp * 16 * KP + ks * 16 + loB72);
                mma16(sacc[2 * fnp],     qa[ks], b[0], b[1]);
                mma16(sacc[2 * fnp + 1], qa[ks], b[2], b[3]);
            }
        }
        // ---- P = exp2(S) with fixed max 0; masked -> 0 ----------------------
#pragma unroll
        for (int fn = 0; fn < 8; fn++) {
            int c0 = fn * 8 + 2 * tg;
            bool k0m = (mt[c0] == 0), k1m = (mt[c0 + 1] == 0);
            sacc[fn][0] = k0m ? 0.f : ex2f(sacc[fn][0]);
            sacc[fn][1] = k1m ? 0.f : ex2f(sacc[fn][1]);
            sacc[fn][2] = k0m ? 0.f : ex2f(sacc[fn][2]);
            sacc[fn][3] = k1m ? 0.f : ex2f(sacc[fn][3]);
            sumA += sacc[fn][0] + sacc[fn][1];
            sumB += sacc[fn][2] + sacc[fn][3];
        }
        // ---- O += P @ V' : P directly from registers (acc layout == A layout)
#pragma unroll
        for (int ks = 0; ks < 4; ks++) {
            uint32_t pa[4];
            pa[0] = pack_hf2(sacc[2 * ks][0],     sacc[2 * ks][1]);
            pa[1] = pack_hf2(sacc[2 * ks][2],     sacc[2 * ks][3]);
            pa[2] = pack_hf2(sacc[2 * ks + 1][0], sacc[2 * ks + 1][1]);
            pa[3] = pack_hf2(sacc[2 * ks + 1][2], sacc[2 * ks + 1][3]);
#pragma unroll
            for (int fnp = 0; fnp < 4; fnp++) {
                uint32_t b[4];
                ldsm4t(b, Vt + (ks * 16) * KP + fnp * 16 + loBT72);
                mma16f(oacc[2 * fnp],     pa, b[0], b[1]);
                mma16f(oacc[2 * fnp + 1], pa, b[2], b[3]);
            }
        }
    }
#undef AFILL

    // ---- single softmax reduction + epilogue ---------------------------------
    sumA += __shfl_xor_sync(~0u, sumA, 1); sumA += __shfl_xor_sync(~0u, sumA, 2);
    sumB += __shfl_xor_sync(~0u, sumB, 1); sumB += __shfl_xor_sync(~0u, sumB, 2);
    float invA = 1.f / sumA, invB = 1.f / sumB;
    int b_ = bh >> 4, h = bh & 15;
#pragma unroll
    for (int fn = 0; fn < 8; fn++) {
        int col = fn * 8 + 2 * tg;
        float b0v = bo[col], b1v = bo[col + 1];
        int r0 = q0 + w * 16 + g, r1 = r0 + 8;
        *(float2*)(out + ((size_t)(b_ * Ss + r0)) * Dd + h * 64 + col) =
            make_float2(oacc[fn][0] * invA + b0v, oacc[fn][1] * invA + b1v);
        *(float2*)(out + ((size_t)(b_ * Ss + r1)) * Dd + h * 64 + col) =
            make_float2(oacc[fn][2] * invB + b0v, oacc[fn][3] * invB + b1v);
    }
}

// ---------------------------------------------------------------------------
extern "C" void kernel_launch(void* const* d_in, const int* in_sizes, int n_in,
                              void* d_out, int out_size) {
    const float* q   = (const float*)d_in[0];
    const float* k   = (const float*)d_in[1];
    const float* v   = (const float*)d_in[2];
    const int*   msk = (const int*)d_in[3];
    const float* Wq  = (const float*)d_in[4];
    const float* bq  = (const float*)d_in[5];
    const float* Wk  = (const float*)d_in[6];
    const float* bk  = (const float*)d_in[7];
    const float* Wv  = (const float*)d_in[8];
    const float* bv  = (const float*)d_in[9];
    const float* Wqf = (const float*)d_in[10];
    const float* bqf = (const float*)d_in[11];
    const float* Wkf = (const float*)d_in[12];
    const float* bkf = (const float*)d_in[13];
    const float* Wvf = (const float*)d_in[14];
    const float* bvf = (const float*)d_in[15];
    const float* Wo  = (const float*)d_in[16];
    const float* bo  = (const float*)d_in[17];
    float* out = (float*)d_out;

    const int proj_smem = 3 * 2 * 128 * BP * 2;  // 61440
    const int attn_smem = 74496;

    static int cfg = 0;
    if (!cfg) {
        cudaFuncSetAttribute(proj_all, cudaFuncAttributeMaxDynamicSharedMemorySize, proj_smem);
        cudaFuncSetAttribute(attn_tc, cudaFuncAttributeMaxDynamicSharedMemorySize, attn_smem);
        cfg = 1;
    }

    preround<<<4096, 256>>>(q, k, v);
    fold_kernel<<<dim3(16, 16, 3), 256>>>(Wq, Wqf, Wk, Wkf, Wv, Wvf);
    bfold_kernel<<<3, 1024>>>(bq, bqf, bk, bkf, bv, bvf, Wqf, Wkf, Wvf);
    proj_all<<<dim3(8, 32, 3), 256, proj_smem>>>(Wo);
    attn_tc<<<dim3(8, 64), 256, attn_smem>>>(msk, bo, out);
}

// round 11
// speedup vs baseline: 5.5994x; 1.1099x over previous
#include <cuda_runtime.h>
#include <cuda_bf16.h>
#include <cuda_fp16.h>
#include <math.h>
#include <stdint.h>

#define Bb 4
#define Ss 1024
#define Dd 1024
#define Hh 16
#define DKk 64

#define QSCALE 0.18033688011112042f
#define MASKVAL -14426.950408889634f

// ---------------------------------------------------------------------------
// Device scratch
// ---------------------------------------------------------------------------
__device__ __nv_bfloat16 g_Xb[2][4096 * 1024];   // bf16 q,k inputs
__device__ __half        g_Xf[4096 * 1024];      // fp16 v input
__device__ __nv_bfloat16 g_Wcb[2][1024 * 1024];  // folded Wq,Wk (bf16)
__device__ __half        g_Wcf[1024 * 1024];     // folded Wv (fp16)
__device__ float         g_bc[3][1024];          // folded biases
__device__ __nv_bfloat16 g_Qb[64 * 1024 * 64];   // per-head Q (bf16, pre-scaled)
__device__ __nv_bfloat16 g_Kb[64 * 1024 * 64];   // per-head K (bf16)
__device__ __half        g_Vp[64 * 1024 * 64];   // V' = V @ Wo^T (fp16) [bh][s][d]

// ---------------------------------------------------------------------------
// helpers
// ---------------------------------------------------------------------------
__device__ __forceinline__ void mma16(float (&d)[4], const uint32_t (&a)[4],
                                      uint32_t b0, uint32_t b1) {
    asm volatile(
        "mma.sync.aligned.m16n8k16.row.col.f32.bf16.bf16.f32 "
        "{%0,%1,%2,%3},{%4,%5,%6,%7},{%8,%9},{%0,%1,%2,%3};"
        : "+f"(d[0]), "+f"(d[1]), "+f"(d[2]), "+f"(d[3])
        : "r"(a[0]), "r"(a[1]), "r"(a[2]), "r"(a[3]), "r"(b0), "r"(b1));
}
__device__ __forceinline__ void mma16f(float (&d)[4], const uint32_t (&a)[4],
                                       uint32_t b0, uint32_t b1) {
    asm volatile(
        "mma.sync.aligned.m16n8k16.row.col.f32.f16.f16.f32 "
        "{%0,%1,%2,%3},{%4,%5,%6,%7},{%8,%9},{%0,%1,%2,%3};"
        : "+f"(d[0]), "+f"(d[1]), "+f"(d[2]), "+f"(d[3])
        : "r"(a[0]), "r"(a[1]), "r"(a[2]), "r"(a[3]), "r"(b0), "r"(b1));
}
__device__ __forceinline__ void ldsm4(uint32_t (&r)[4], const uint16_t* p) {
    uint32_t a = (uint32_t)__cvta_generic_to_shared(p);
    asm volatile("ldmatrix.sync.aligned.m8n8.x4.shared.b16 {%0,%1,%2,%3},[%4];"
                 : "=r"(r[0]), "=r"(r[1]), "=r"(r[2]), "=r"(r[3]) : "r"(a));
}
__device__ __forceinline__ void ldsm4t(uint32_t (&r)[4], const uint16_t* p) {
    uint32_t a = (uint32_t)__cvta_generic_to_shared(p);
    asm volatile("ldmatrix.sync.aligned.m8n8.x4.trans.shared.b16 {%0,%1,%2,%3},[%4];"
                 : "=r"(r[0]), "=r"(r[1]), "=r"(r[2]), "=r"(r[3]) : "r"(a));
}
__device__ __forceinline__ void cp16(void* s, const void* g) {
    uint32_t sa = (uint32_t)__cvta_generic_to_shared(s);
    asm volatile("cp.async.cg.shared.global [%0], [%1], 16;" :: "r"(sa), "l"(g));
}
__device__ __forceinline__ uint32_t pack_bf2(float a, float b) {
    __nv_bfloat162 t = __float22bfloat162_rn(make_float2(a, b));
    return *reinterpret_cast<uint32_t*>(&t);
}
__device__ __forceinline__ uint32_t pack_hf2(float a, float b) {
    __half2 t = __floats2half2_rn(a, b);
    return *reinterpret_cast<uint32_t*>(&t);
}
__device__ __forceinline__ float ex2f(float x) {
    float y; asm("ex2.approx.f32 %0,%1;" : "=f"(y) : "f"(x)); return y;
}

// ---------------------------------------------------------------------------
// Merged prologue: one launch, three independent jobs running concurrently.
//   blocks [0, 4096)        : preround  (q,k -> bf16 ; v -> fp16)
//   blocks [4096, 4864)     : fold      (Wc = Wf @ Wbig, bf16/fp16)
//   blocks [4864, 4867)     : bfold     (bc = Wf @ b1 + b2)
// ---------------------------------------------------------------------------
__global__ __launch_bounds__(256) void prologue(
    const float* __restrict__ q, const float* __restrict__ k, const float* __restrict__ v,
    const float* __restrict__ Wq, const float* __restrict__ Wqf,
    const float* __restrict__ Wk, const float* __restrict__ Wkf,
    const float* __restrict__ Wv, const float* __restrict__ Wvf,
    const float* __restrict__ bq, const float* __restrict__ bqf,
    const float* __restrict__ bk, const float* __restrict__ bkf,
    const float* __restrict__ bv, const float* __restrict__ bvf) {
    int bid = blockIdx.x;
    int tid = threadIdx.x;

    if (bid < 4096) {
        // ---- preround -------------------------------------------------------
        size_t i = (size_t)bid * 256 + tid;  // float4 index
        float4 a = ((const float4*)q)[i];
        uint32_t* dq = (uint32_t*)g_Xb[0];
        dq[i * 2] = pack_bf2(a.x, a.y); dq[i * 2 + 1] = pack_bf2(a.z, a.w);
        float4 b = ((const float4*)k)[i];
        uint32_t* dk = (uint32_t*)g_Xb[1];
        dk[i * 2] = pack_bf2(b.x, b.y); dk[i * 2 + 1] = pack_bf2(b.z, b.w);
        float4 c = ((const float4*)v)[i];
        uint32_t* dv = (uint32_t*)g_Xf;
        dv[i * 2] = pack_hf2(c.x, c.y); dv[i * 2 + 1] = pack_hf2(c.z, c.w);
        return;
    }
    if (bid < 4864) {
        // ---- fold -----------------------------------------------------------
        int id2 = bid - 4096;
        int t = id2 >> 8, h = (id2 >> 4) & 15, j0 = (id2 & 15) * 64;
        const float* Wbig = (t == 0) ? Wq : (t == 1) ? Wk : Wv;
        const float* Wf   = (t == 0) ? Wqf : (t == 1) ? Wkf : Wvf;

        __shared__ float fs[64][65];
        __shared__ float bs[64][65];

        for (int idx = tid; idx < 64 * 16; idx += 256) {
            int r = idx >> 4, c4 = (idx & 15) * 4;
            float4 fv = *(const float4*)(Wf + r * 64 + c4);
            fs[r][c4] = fv.x; fs[r][c4 + 1] = fv.y; fs[r][c4 + 2] = fv.z; fs[r][c4 + 3] = fv.w;
            float4 bv2 = *(const float4*)(Wbig + (h * 64 + r) * Dd + j0 + c4);
            bs[r][c4] = bv2.x; bs[r][c4 + 1] = bv2.y; bs[r][c4 + 2] = bv2.z; bs[r][c4 + 3] = bv2.w;
        }
        __syncthreads();

        int ty = tid >> 4, tx = tid & 15;
        float acc[4][4] = {};
#pragma unroll 8
        for (int i = 0; i < 64; i++) {
            float a[4], b[4];
#pragma unroll
            for (int u = 0; u < 4; u++) { a[u] = fs[ty * 4 + u][i]; b[u] = bs[i][tx * 4 + u]; }
#pragma unroll
            for (int u = 0; u < 4; u++)
#pragma unroll
                for (int w = 0; w < 4; w++) acc[u][w] += a[u] * b[w];
        }
        if (t < 2) {
            uint32_t* dst = (uint32_t*)g_Wcb[t];
#pragma unroll
            for (int u = 0; u < 4; u++) {
                size_t row = (size_t)(h * 64 + ty * 4 + u) * Dd + j0 + tx * 4;
                dst[row / 2]     = pack_bf2(acc[u][0], acc[u][1]);
                dst[row / 2 + 1] = pack_bf2(acc[u][2], acc[u][3]);
            }
        } else {
            uint32_t* dst = (uint32_t*)g_Wcf;
#pragma unroll
            for (int u = 0; u < 4; u++) {
                size_t row = (size_t)(h * 64 + ty * 4 + u) * Dd + j0 + tx * 4;
                dst[row / 2]     = pack_hf2(acc[u][0], acc[u][1]);
                dst[row / 2 + 1] = pack_hf2(acc[u][2], acc[u][3]);
            }
        }
        return;
    }
    // ---- bfold (3 blocks, 4 outputs/thread) ---------------------------------
    {
        int t = bid - 4864;
        const float* b1 = (t == 0) ? bq : (t == 1) ? bk : bv;
        const float* b2 = (t == 0) ? bqf : (t == 1) ? bkf : bvf;
        const float* Wf = (t == 0) ? Wqf : (t == 1) ? Wkf : Wvf;
#pragma unroll
        for (int kk = 0; kk < 4; kk++) {
            int n = tid + kk * 256;
            int h = n >> 6, o = n & 63;
            float s = b2[o];
            for (int i = 0; i < 64; i++) s += Wf[o * 64 + i] * b1[h * 64 + i];
            g_bc[t][n] = s;
        }
    }
}

// ---------------------------------------------------------------------------
// Unified projection GEMM (unchanged; at mma.sync issue ceiling).
// ---------------------------------------------------------------------------
#define BP 40
__global__ __launch_bounds__(256) void proj_all(const float* __restrict__ Wo) {
    extern __shared__ uint16_t sb[];

    const int t = blockIdx.z;
    const bool VM = (t == 2);
    const uint16_t* X = VM ? (const uint16_t*)g_Xf : (const uint16_t*)g_Xb[t];
    const uint16_t* W = VM ? (const uint16_t*)g_Wcf : (const uint16_t*)g_Wcb[t];
    const float* bias = g_bc[t];
    const int hp = blockIdx.x;
    const int m0 = blockIdx.y * 128;

    const int tid = threadIdx.x;
    const int w = tid >> 5, lane = tid & 31, g = lane >> 2, tg = lane & 3;
    const int wm = w & 3, wn = w >> 2;

    const int loA40 = ((lane & 7) + ((lane >> 3) & 1) * 8) * BP + ((lane >> 4) & 1) * 8;
    const int loB40 = ((lane & 7) + ((lane >> 4) & 1) * 8) * BP + ((lane >> 3) & 1) * 8;

    float acc[2][8][4] = {};

#define GLOAD(I, S)                                                                     \
    do {                                                                                \
        uint16_t* Xd = sb + (S) * 10240;                                                \
        uint16_t* Wd = Xd + 5120;                                                       \
        int k0_ = (I) * 32;                                                             \
        _Pragma("unroll")                                                               \
        for (int j = 0; j < 2; j++) {                                                   \
            int idx = tid + j * 256; int r = idx >> 2, c = (idx & 3) * 8;               \
            cp16(Xd + r * BP + c, X + (size_t)(m0 + r) * Dd + k0_ + c);                 \
        }                                                                               \
        _Pragma("unroll")                                                               \
        for (int j = 0; j < 2; j++) {                                                   \
            int idx = tid + j * 256; int r = idx >> 2, c = (idx & 3) * 8;               \
            cp16(Wd + r * BP + c, W + (size_t)(hp * 128 + r) * Dd + k0_ + c);           \
        }                                                                               \
        asm volatile("cp.async.commit_group;");                                        \
    } while (0)

#define MAINLOOP(MMAOP)                                                                 \
    for (int i = 0; i < 32; i++) {                                                      \
        asm volatile("cp.async.wait_group 1;");                                         \
        __syncthreads();                                                                \
        if (i + 2 < 32) GLOAD(i + 2, (i + 2) % 3);                                      \
        else asm volatile("cp.async.commit_group;");                                    \
        const uint16_t* Xb_ = sb + (i % 3) * 10240;                                     \
        const uint16_t* Wb_ = Xb_ + 5120;                                               \
        _Pragma("unroll")                                                               \
        for (int ks = 0; ks < 2; ks++) {                                                \
            uint32_t a[2][4], b[4][4];                                                  \
            ldsm4(a[0], Xb_ + (wm * 32) * BP + ks * 16 + loA40);                        \
            ldsm4(a[1], Xb_ + (wm * 32 + 16) * BP + ks * 16 + loA40);                   \
            _Pragma("unroll")                                                           \
            for (int fnp = 0; fnp < 4; fnp++)                                           \
                ldsm4(b[fnp], Wb_ + (wn * 64 + fnp * 16) * BP + ks * 16 + loB40);       \
            _Pragma("unroll")                                                           \
            for (int fm = 0; fm < 2; fm++)                                              \
                _Pragma("unroll")                                                       \
                for (int fnp = 0; fnp < 4; fnp++) {                                     \
                    MMAOP(acc[fm][2 * fnp],     a[fm], b[fnp][0], b[fnp][1]);           \
                    MMAOP(acc[fm][2 * fnp + 1], a[fm], b[fnp][2], b[fnp][3]);           \
                }                                                                       \
        }                                                                               \
    }

    GLOAD(0, 0);
    GLOAD(1, 1);
    if (!VM) { MAINLOOP(mma16); }
    else     { MAINLOOP(mma16f); }
#undef MAINLOOP
#undef GLOAD

    const int b_ = m0 >> 10, s0 = m0 & 1023;
    if (!VM) {
        __nv_bfloat16* Y = (t == 0) ? g_Qb : g_Kb;
        const float sc = (t == 0) ? QSCALE : 1.0f;
        const int head = hp * 2 + wn;
        const float* bh_ = bias + head * 64;
#pragma unroll
        for (int fm = 0; fm < 2; fm++) {
#pragma unroll
            for (int fn = 0; fn < 8; fn++) {
                int col = fn * 8 + 2 * tg;
                float b0 = bh_[col], b1 = bh_[col + 1];
                int r0 = m0 + wm * 32 + fm * 16 + g, r1 = r0 + 8;
                uint32_t v0 = pack_bf2(fmaxf(acc[fm][fn][0] + b0, 0.f) * sc,
                                       fmaxf(acc[fm][fn][1] + b1, 0.f) * sc);
                uint32_t v1 = pack_bf2(fmaxf(acc[fm][fn][2] + b0, 0.f) * sc,
                                       fmaxf(acc[fm][fn][3] + b1, 0.f) * sc);
                {
                    int bb = r0 >> 10, s = r0 & 1023;
                    *(uint32_t*)((uint16_t*)Y + (((size_t)(bb * Hh + head)) * Ss + s) * DKk + col) = v0;
                }
                {
                    int bb = r1 >> 10, s = r1 & 1023;
                    *(uint32_t*)((uint16_t*)Y + (((size_t)(bb * Hh + head)) * Ss + s) * DKk + col) = v1;
                }
            }
        }
    } else {
        // ---- fused pass-2: V' = V @ Wo^T per head (fp16 mma) -----------------
        __syncthreads();
        uint16_t* Vt  = sb;                  // [128][136] fp16 (34816 B)
        uint16_t* WoS = sb + 128 * 136;      // [64][72]   fp16 ( 9216 B)

#pragma unroll
        for (int fm = 0; fm < 2; fm++) {
#pragma unroll
            for (int fn = 0; fn < 8; fn++) {
                int col = wn * 64 + fn * 8 + 2 * tg;
                float b0 = bias[hp * 128 + col], b1 = bias[hp * 128 + col + 1];
                int lr0 = wm * 32 + fm * 16 + g, lr1 = lr0 + 8;
                *(uint32_t*)(Vt + lr0 * 136 + col) = pack_hf2(fmaxf(acc[fm][fn][0] + b0, 0.f),
                                                              fmaxf(acc[fm][fn][1] + b1, 0.f));
                *(uint32_t*)(Vt + lr1 * 136 + col) = pack_hf2(fmaxf(acc[fm][fn][2] + b0, 0.f),
                                                              fmaxf(acc[fm][fn][3] + b1, 0.f));
            }
        }
#pragma unroll
        for (int j = 0; j < 4; j++) {
            int idx = tid + j * 256; int r = idx >> 4, c = (idx & 15) * 4;
            float4 wv = *(const float4*)(Wo + r * 64 + c);
            *(uint32_t*)(WoS + r * 72 + c)     = pack_hf2(wv.x, wv.y);
            *(uint32_t*)(WoS + r * 72 + c + 2) = pack_hf2(wv.z, wv.w);
        }
        __syncthreads();

        const int loA136 = ((lane & 7) + ((lane >> 3) & 1) * 8) * 136 + ((lane >> 4) & 1) * 8;
        const int loB72  = ((lane & 7) + ((lane >> 4) & 1) * 8) * 72 + ((lane >> 3) & 1) * 8;

#pragma unroll
        for (int j = 0; j < 2; j++) {
            const int head = hp * 2 + j, bh = b_ * Hh + head;
            float acc2[2][4][4] = {};
#pragma unroll
            for (int ks = 0; ks < 4; ks++) {
                uint32_t a[2][4], bfr[2][4];
                ldsm4(a[0], Vt + (wm * 32) * 136 + j * 64 + ks * 16 + loA136);
                ldsm4(a[1], Vt + (wm * 32 + 16) * 136 + j * 64 + ks * 16 + loA136);
                ldsm4(bfr[0], WoS + (wn * 32) * 72 + ks * 16 + loB72);
                ldsm4(bfr[1], WoS + (wn * 32 + 16) * 72 + ks * 16 + loB72);
#pragma unroll
                for (int fm = 0; fm < 2; fm++) {
                    mma16f(acc2[fm][0], a[fm], bfr[0][0], bfr[0][1]);
                    mma16f(acc2[fm][1], a[fm], bfr[0][2], bfr[0][3]);
                    mma16f(acc2[fm][2], a[fm], bfr[1][0], bfr[1][1]);
                    mma16f(acc2[fm][3], a[fm], bfr[1][2], bfr[1][3]);
                }
            }
            uint16_t* dst = (uint16_t*)g_Vp + ((size_t)bh * Ss + s0) * DKk;
#pragma unroll
            for (int fm = 0; fm < 2; fm++) {
#pragma unroll
                for (int fn = 0; fn < 4; fn++) {
                    int col = wn * 32 + fn * 8 + 2 * tg;
                    int lr0 = wm * 32 + fm * 16 + g, lr1 = lr0 + 8;
                    *(uint32_t*)(dst + (size_t)lr0 * DKk + col) =
                        pack_hf2(acc2[fm][fn][0], acc2[fm][fn][1]);
                    *(uint32_t*)(dst + (size_t)lr1 * DKk + col) =
                        pack_hf2(acc2[fm][fn][2], acc2[fm][fn][3]);
                }
            }
        }
    }
}

// ---------------------------------------------------------------------------
// Flash attention v4: fixed-max exp2 softmax, register-resident P,
// 4-slot K/V ring with wait_group 2 (TWO tiles of prefetch margin),
// one __syncthreads per tile, 2 CTAs/SM.
// smem: Kb[4][64][72] + Vb[4][64][72] + Qs[128][72] (u16) + ms[4][64] = 93184 B
// ---------------------------------------------------------------------------
#define KP 72
__global__ __launch_bounds__(256, 2) void attn_tc(const int* __restrict__ mask,
                                                  const float* __restrict__ bo,
                                                  float* __restrict__ out) {
    extern __shared__ char smraw[];
    uint16_t* Kb = (uint16_t*)smraw;                   // [4][64][72]  36864 B
    uint16_t* Vb = (uint16_t*)(smraw + 36864);         // [4][64][72]  36864 B
    uint16_t* Qs = (uint16_t*)(smraw + 73728);         // [128][72]    18432 B
    int* ms = (int*)(smraw + 92160);                   // [4][64]       1024 B

    int bh = blockIdx.y, q0 = blockIdx.x * 128;
    const uint16_t* Qg = (const uint16_t*)g_Qb + ((size_t)bh * Ss + q0) * DKk;
    const uint16_t* Kg = (const uint16_t*)g_Kb + (size_t)bh * Ss * DKk;
    const uint16_t* Vg = (const uint16_t*)g_Vp + (size_t)bh * Ss * DKk;

    int tid = threadIdx.x, w = tid >> 5, lane = tid & 31, g = lane >> 2, tg = lane & 3;
    const int loA72 = ((lane & 7) + ((lane >> 3) & 1) * 8) * KP + ((lane >> 4) & 1) * 8;
    const int loB72 = ((lane & 7) + ((lane >> 4) & 1) * 8) * KP + ((lane >> 3) & 1) * 8;
    const int loBT72 = ((lane & 7) + ((lane >> 3) & 1) * 8) * KP + ((lane >> 4) & 1) * 8;

    // ---- stage Q (bf16), extract per-warp A-fragments ------------------------
#pragma unroll
    for (int j = 0; j < 4; j++) {
        int idx = tid + j * 256; int r = idx >> 3, c = (idx & 7) * 8;
        *(uint4*)(Qs + r * KP + c) = *(const uint4*)(Qg + (size_t)r * DKk + c);
    }
    __syncthreads();
    uint32_t qa[4][4];
#pragma unroll
    for (int ks = 0; ks < 4; ks++)
        ldsm4(qa[ks], Qs + w * 16 * KP + ks * 16 + loA72);

#define AFILL(KT, BUF)                                                                  \
    do {                                                                                \
        const uint16_t* kg = Kg + (size_t)(KT) * 64 * DKk;                              \
        const uint16_t* vg = Vg + (size_t)(KT) * 64 * DKk;                              \
        _Pragma("unroll")                                                               \
        for (int j = 0; j < 2; j++) {                                                   \
            int idx = tid + j * 256; int r = idx >> 3, c = (idx & 7) * 8;               \
            cp16(Kb + ((BUF) * 64 + r) * KP + c, kg + (size_t)r * DKk + c);             \
            cp16(Vb + ((BUF) * 64 + r) * KP + c, vg + (size_t)r * DKk + c);             \
        }                                                                               \
        if (tid < 16)                                                                   \
            cp16(ms + (BUF) * 64 + tid * 4, mask + (size_t)bh * Ss + (KT) * 64 + tid * 4); \
        asm volatile("cp.async.commit_group;");                                        \
    } while (0)

    float oacc[8][4] = {};
    float sumA = 0.f, sumB = 0.f;   // fixed max = 0: purely additive row sums

    AFILL(0, 0);
    AFILL(1, 1);
    AFILL(2, 2);
    for (int kt = 0; kt < 16; kt++) {
        int buf = kt & 3;
        // keep 2 newest groups in flight -> fill(kt) is complete after this wait
        asm volatile("cp.async.wait_group 2;");
        __syncthreads();  // slot (kt+3)&3 == (kt-1)&3 fully consumed by all warps
        if (kt + 3 < 16) AFILL(kt + 3, (kt + 3) & 3);
        else asm volatile("cp.async.commit_group;");

        const uint16_t* Kt = Kb + buf * 64 * KP;
        const uint16_t* Vt = Vb + buf * 64 * KP;
        const int* mt = ms + buf * 64;

        // ---- S = Q' @ K^T (bf16, exp2 domain) -------------------------------
        float sacc[8][4] = {};
#pragma unroll
        for (int ks = 0; ks < 4; ks++) {
#pragma unroll
            for (int fnp = 0; fnp < 4; fnp++) {
                uint32_t b[4];
                ldsm4(b, Kt + fnp * 16 * KP + ks * 16 + loB72);
                mma16(sacc[2 * fnp],     qa[ks], b[0], b[1]);
                mma16(sacc[2 * fnp + 1], qa[ks], b[2], b[3]);
            }
        }
        // ---- P = exp2(S), masked -> 0 exactly --------------------------------
#pragma unroll
        for (int fn = 0; fn < 8; fn++) {
            int c0 = fn * 8 + 2 * tg;
            bool k0m = (mt[c0] == 0), k1m = (mt[c0 + 1] == 0);
            sacc[fn][0] = k0m ? 0.f : ex2f(sacc[fn][0]);
            sacc[fn][1] = k1m ? 0.f : ex2f(sacc[fn][1]);
            sacc[fn][2] = k0m ? 0.f : ex2f(sacc[fn][2]);
            sacc[fn][3] = k1m ? 0.f : ex2f(sacc[fn][3]);
            sumA += sacc[fn][0] + sacc[fn][1];
            sumB += sacc[fn][2] + sacc[fn][3];
        }
        // ---- O += P @ V' : P direct from registers ---------------------------
#pragma unroll
        for (int ks = 0; ks < 4; ks++) {
            uint32_t pa[4];
            pa[0] = pack_hf2(sacc[2 * ks][0],     sacc[2 * ks][1]);
            pa[1] = pack_hf2(sacc[2 * ks][2],     sacc[2 * ks][3]);
            pa[2] = pack_hf2(sacc[2 * ks + 1][0], sacc[2 * ks + 1][1]);
            pa[3] = pack_hf2(sacc[2 * ks + 1][2], sacc[2 * ks + 1][3]);
#pragma unroll
            for (int fnp = 0; fnp < 4; fnp++) {
                uint32_t b[4];
                ldsm4t(b, Vt + (ks * 16) * KP + fnp * 16 + loBT72);
                mma16f(oacc[2 * fnp],     pa, b[0], b[1]);
                mma16f(oacc[2 * fnp + 1], pa, b[2], b[3]);
            }
        }
    }
#undef AFILL

    // ---- single softmax reduction + epilogue ---------------------------------
    sumA += __shfl_xor_sync(~0u, sumA, 1); sumA += __shfl_xor_sync(~0u, sumA, 2);
    sumB += __shfl_xor_sync(~0u, sumB, 1); sumB += __shfl_xor_sync(~0u, sumB, 2);
    float invA = 1.f / sumA, invB = 1.f / sumB;
    int b_ = bh >> 4, h = bh & 15;
#pragma unroll
    for (int fn = 0; fn < 8; fn++) {
        int col = fn * 8 + 2 * tg;
        float b0v = bo[col], b1v = bo[col + 1];
        int r0 = q0 + w * 16 + g, r1 = r0 + 8;
        *(float2*)(out + ((size_t)(b_ * Ss + r0)) * Dd + h * 64 + col) =
            make_float2(oacc[fn][0] * invA + b0v, oacc[fn][1] * invA + b1v);
        *(float2*)(out + ((size_t)(b_ * Ss + r1)) * Dd + h * 64 + col) =
            make_float2(oacc[fn][2] * invB + b0v, oacc[fn][3] * invB + b1v);
    }
}

// ---------------------------------------------------------------------------
extern "C" void kernel_launch(void* const* d_in, const int* in_sizes, int n_in,
                              void* d_out, int out_size) {
    const float* q   = (const float*)d_in[0];
    const float* k   = (const float*)d_in[1];
    const float* v   = (const float*)d_in[2];
    const int*   msk = (const int*)d_in[3];
    const float* Wq  = (const float*)d_in[4];
    const float* bq  = (const float*)d_in[5];
    const float* Wk  = (const float*)d_in[6];
    const float* bk  = (const float*)d_in[7];
    const float* Wv  = (const float*)d_in[8];
    const float* bv  = (const float*)d_in[9];
    const float* Wqf = (const float*)d_in[10];
    const float* bqf = (const float*)d_in[11];
    const float* Wkf = (const float*)d_in[12];
    const float* bkf = (const float*)d_in[13];
    const float* Wvf = (const float*)d_in[14];
    const float* bvf = (const float*)d_in[15];
    const float* Wo  = (const float*)d_in[16];
    const float* bo  = (const float*)d_in[17];
    float* out = (float*)d_out;

    const int proj_smem = 3 * 2 * 128 * BP * 2;  // 61440
    const int attn_smem = 93184;

    static int cfg = 0;
    if (!cfg) {
        cudaFuncSetAttribute(proj_all, cudaFuncAttributeMaxDynamicSharedMemorySize, proj_smem);
        cudaFuncSetAttribute(attn_tc, cudaFuncAttributeMaxDynamicSharedMemorySize, attn_smem);
        cfg = 1;
    }

    prologue<<<4867, 256>>>(q, k, v, Wq, Wqf, Wk, Wkf, Wv, Wvf,
                            bq, bqf, bk, bkf, bv, bvf);
    proj_all<<<dim3(8, 32, 3), 256, proj_smem>>>(Wo);
    attn_tc<<<dim3(8, 64), 256, attn_smem>>>(msk, bo, out);
}

// round 12
// speedup vs baseline: 5.6521x; 1.0094x over previous
#include <cuda_runtime.h>
#include <cuda_bf16.h>
#include <cuda_fp16.h>
#include <math.h>
#include <stdint.h>

#define Bb 4
#define Ss 1024
#define Dd 1024
#define Hh 16
#define DKk 64

#define QSCALE 0.18033688011112042f
#define MASKVAL -14426.950408889634f

// ---------------------------------------------------------------------------
// Device scratch
// ---------------------------------------------------------------------------
__device__ __nv_bfloat16 g_Xb[2][4096 * 1024];   // bf16 q,k inputs
__device__ __half        g_Xf[4096 * 1024];      // fp16 v input
__device__ __nv_bfloat16 g_Wcb[2][1024 * 1024];  // folded Wq,Wk (bf16)
__device__ __half        g_Wcf[1024 * 1024];     // folded Wv (fp16)
__device__ float         g_bc[3][1024];          // folded biases
__device__ __nv_bfloat16 g_Qb[64 * 1024 * 64];   // per-head Q (bf16, pre-scaled)
__device__ __nv_bfloat16 g_Kb[64 * 1024 * 64];   // per-head K (bf16)
__device__ __half        g_Vp[64 * 1024 * 64];   // V' = V @ Wo^T (fp16) [bh][s][d]

// ---------------------------------------------------------------------------
// helpers
// ---------------------------------------------------------------------------
__device__ __forceinline__ void mma16(float (&d)[4], const uint32_t (&a)[4],
                                      uint32_t b0, uint32_t b1) {
    asm volatile(
        "mma.sync.aligned.m16n8k16.row.col.f32.bf16.bf16.f32 "
        "{%0,%1,%2,%3},{%4,%5,%6,%7},{%8,%9},{%0,%1,%2,%3};"
        : "+f"(d[0]), "+f"(d[1]), "+f"(d[2]), "+f"(d[3])
        : "r"(a[0]), "r"(a[1]), "r"(a[2]), "r"(a[3]), "r"(b0), "r"(b1));
}
__device__ __forceinline__ void mma16f(float (&d)[4], const uint32_t (&a)[4],
                                       uint32_t b0, uint32_t b1) {
    asm volatile(
        "mma.sync.aligned.m16n8k16.row.col.f32.f16.f16.f32 "
        "{%0,%1,%2,%3},{%4,%5,%6,%7},{%8,%9},{%0,%1,%2,%3};"
        : "+f"(d[0]), "+f"(d[1]), "+f"(d[2]), "+f"(d[3])
        : "r"(a[0]), "r"(a[1]), "r"(a[2]), "r"(a[3]), "r"(b0), "r"(b1));
}
__device__ __forceinline__ void ldsm4(uint32_t (&r)[4], const uint16_t* p) {
    uint32_t a = (uint32_t)__cvta_generic_to_shared(p);
    asm volatile("ldmatrix.sync.aligned.m8n8.x4.shared.b16 {%0,%1,%2,%3},[%4];"
                 : "=r"(r[0]), "=r"(r[1]), "=r"(r[2]), "=r"(r[3]) : "r"(a));
}
__device__ __forceinline__ void ldsm4t(uint32_t (&r)[4], const uint16_t* p) {
    uint32_t a = (uint32_t)__cvta_generic_to_shared(p);
    asm volatile("ldmatrix.sync.aligned.m8n8.x4.trans.shared.b16 {%0,%1,%2,%3},[%4];"
                 : "=r"(r[0]), "=r"(r[1]), "=r"(r[2]), "=r"(r[3]) : "r"(a));
}
__device__ __forceinline__ void cp16(void* s, const void* g) {
    uint32_t sa = (uint32_t)__cvta_generic_to_shared(s);
    asm volatile("cp.async.cg.shared.global [%0], [%1], 16;" :: "r"(sa), "l"(g));
}
__device__ __forceinline__ uint32_t pack_bf2(float a, float b) {
    __nv_bfloat162 t = __float22bfloat162_rn(make_float2(a, b));
    return *reinterpret_cast<uint32_t*>(&t);
}
__device__ __forceinline__ uint32_t pack_hf2(float a, float b) {
    __half2 t = __floats2half2_rn(a, b);
    return *reinterpret_cast<uint32_t*>(&t);
}
__device__ __forceinline__ float ex2f(float x) {
    float y; asm("ex2.approx.f32 %0,%1;" : "=f"(y) : "f"(x)); return y;
}

// ---------------------------------------------------------------------------
// Merged prologue:
//   blocks [0, 2048)    : preround, 2 float4/tensor/thread, 16B stores
//   blocks [2048, 2816) : fold
//   blocks [2816, 2819) : bfold
// ---------------------------------------------------------------------------
__global__ __launch_bounds__(256) void prologue(
    const float* __restrict__ q, const float* __restrict__ k, const float* __restrict__ v,
    const float* __restrict__ Wq, const float* __restrict__ Wqf,
    const float* __restrict__ Wk, const float* __restrict__ Wkf,
    const float* __restrict__ Wv, const float* __restrict__ Wvf,
    const float* __restrict__ bq, const float* __restrict__ bqf,
    const float* __restrict__ bk, const float* __restrict__ bkf,
    const float* __restrict__ bv, const float* __restrict__ bvf) {
    int bid = blockIdx.x;
    int tid = threadIdx.x;

    if (bid < 2048) {
        // ---- preround: each thread converts 2 consecutive float4 per tensor --
        size_t i = ((size_t)bid * 256 + tid) * 2;  // float4 index (even)
        {
            float4 a0 = ((const float4*)q)[i], a1 = ((const float4*)q)[i + 1];
            uint4 o = {pack_bf2(a0.x, a0.y), pack_bf2(a0.z, a0.w),
                       pack_bf2(a1.x, a1.y), pack_bf2(a1.z, a1.w)};
            ((uint4*)g_Xb[0])[i / 2] = o;
        }
        {
            float4 a0 = ((const float4*)k)[i], a1 = ((const float4*)k)[i + 1];
            uint4 o = {pack_bf2(a0.x, a0.y), pack_bf2(a0.z, a0.w),
                       pack_bf2(a1.x, a1.y), pack_bf2(a1.z, a1.w)};
            ((uint4*)g_Xb[1])[i / 2] = o;
        }
        {
            float4 a0 = ((const float4*)v)[i], a1 = ((const float4*)v)[i + 1];
            uint4 o = {pack_hf2(a0.x, a0.y), pack_hf2(a0.z, a0.w),
                       pack_hf2(a1.x, a1.y), pack_hf2(a1.z, a1.w)};
            ((uint4*)g_Xf)[i / 2] = o;
        }
        return;
    }
    if (bid < 2816) {
        // ---- fold -----------------------------------------------------------
        int id2 = bid - 2048;
        int t = id2 >> 8, h = (id2 >> 4) & 15, j0 = (id2 & 15) * 64;
        const float* Wbig = (t == 0) ? Wq : (t == 1) ? Wk : Wv;
        const float* Wf   = (t == 0) ? Wqf : (t == 1) ? Wkf : Wvf;

        __shared__ float fs[64][65];
        __shared__ float bs[64][65];

        for (int idx = tid; idx < 64 * 16; idx += 256) {
            int r = idx >> 4, c4 = (idx & 15) * 4;
            float4 fv = *(const float4*)(Wf + r * 64 + c4);
            fs[r][c4] = fv.x; fs[r][c4 + 1] = fv.y; fs[r][c4 + 2] = fv.z; fs[r][c4 + 3] = fv.w;
            float4 bv2 = *(const float4*)(Wbig + (h * 64 + r) * Dd + j0 + c4);
            bs[r][c4] = bv2.x; bs[r][c4 + 1] = bv2.y; bs[r][c4 + 2] = bv2.z; bs[r][c4 + 3] = bv2.w;
        }
        __syncthreads();

        int ty = tid >> 4, tx = tid & 15;
        float acc[4][4] = {};
#pragma unroll 8
        for (int i = 0; i < 64; i++) {
            float a[4], b[4];
#pragma unroll
            for (int u = 0; u < 4; u++) { a[u] = fs[ty * 4 + u][i]; b[u] = bs[i][tx * 4 + u]; }
#pragma unroll
            for (int u = 0; u < 4; u++)
#pragma unroll
                for (int w = 0; w < 4; w++) acc[u][w] += a[u] * b[w];
        }
        if (t < 2) {
            uint32_t* dst = (uint32_t*)g_Wcb[t];
#pragma unroll
            for (int u = 0; u < 4; u++) {
                size_t row = (size_t)(h * 64 + ty * 4 + u) * Dd + j0 + tx * 4;
                dst[row / 2]     = pack_bf2(acc[u][0], acc[u][1]);
                dst[row / 2 + 1] = pack_bf2(acc[u][2], acc[u][3]);
            }
        } else {
            uint32_t* dst = (uint32_t*)g_Wcf;
#pragma unroll
            for (int u = 0; u < 4; u++) {
                size_t row = (size_t)(h * 64 + ty * 4 + u) * Dd + j0 + tx * 4;
                dst[row / 2]     = pack_hf2(acc[u][0], acc[u][1]);
                dst[row / 2 + 1] = pack_hf2(acc[u][2], acc[u][3]);
            }
        }
        return;
    }
    // ---- bfold (3 blocks, 4 outputs/thread) ---------------------------------
    {
        int t = bid - 2816;
        const float* b1 = (t == 0) ? bq : (t == 1) ? bk : bv;
        const float* b2 = (t == 0) ? bqf : (t == 1) ? bkf : bvf;
        const float* Wf = (t == 0) ? Wqf : (t == 1) ? Wkf : Wvf;
#pragma unroll
        for (int kk = 0; kk < 4; kk++) {
            int n = tid + kk * 256;
            int h = n >> 6, o = n & 63;
            float s = b2[o];
            for (int i = 0; i < 64; i++) s += Wf[o * 64 + i] * b1[h * 64 + i];
            g_bc[t][n] = s;
        }
    }
}

// ---------------------------------------------------------------------------
// Unified projection GEMM (pinned 2 CTAs/SM).
// ---------------------------------------------------------------------------
#define BP 40
__global__ __launch_bounds__(256, 2) void proj_all(const float* __restrict__ Wo) {
    extern __shared__ uint16_t sb[];

    const int t = blockIdx.z;
    const bool VM = (t == 2);
    const uint16_t* X = VM ? (const uint16_t*)g_Xf : (const uint16_t*)g_Xb[t];
    const uint16_t* W = VM ? (const uint16_t*)g_Wcf : (const uint16_t*)g_Wcb[t];
    const float* bias = g_bc[t];
    const int hp = blockIdx.x;
    const int m0 = blockIdx.y * 128;

    const int tid = threadIdx.x;
    const int w = tid >> 5, lane = tid & 31, g = lane >> 2, tg = lane & 3;
    const int wm = w & 3, wn = w >> 2;

    const int loA40 = ((lane & 7) + ((lane >> 3) & 1) * 8) * BP + ((lane >> 4) & 1) * 8;
    const int loB40 = ((lane & 7) + ((lane >> 4) & 1) * 8) * BP + ((lane >> 3) & 1) * 8;

    float acc[2][8][4] = {};

#define GLOAD(I, S)                                                                     \
    do {                                                                                \
        uint16_t* Xd = sb + (S) * 10240;                                                \
        uint16_t* Wd = Xd + 5120;                                                       \
        int k0_ = (I) * 32;                                                             \
        _Pragma("unroll")                                                               \
        for (int j = 0; j < 2; j++) {                                                   \
            int idx = tid + j * 256; int r = idx >> 2, c = (idx & 3) * 8;               \
            cp16(Xd + r * BP + c, X + (size_t)(m0 + r) * Dd + k0_ + c);                 \
        }                                                                               \
        _Pragma("unroll")                                                               \
        for (int j = 0; j < 2; j++) {                                                   \
            int idx = tid + j * 256; int r = idx >> 2, c = (idx & 3) * 8;               \
            cp16(Wd + r * BP + c, W + (size_t)(hp * 128 + r) * Dd + k0_ + c);           \
        }                                                                               \
        asm volatile("cp.async.commit_group;");                                        \
    } while (0)

#define MAINLOOP(MMAOP)                                                                 \
    for (int i = 0; i < 32; i++) {                                                      \
        asm volatile("cp.async.wait_group 1;");                                         \
        __syncthreads();                                                                \
        if (i + 2 < 32) GLOAD(i + 2, (i + 2) % 3);                                      \
        else asm volatile("cp.async.commit_group;");                                    \
        const uint16_t* Xb_ = sb + (i % 3) * 10240;                                     \
        const uint16_t* Wb_ = Xb_ + 5120;                                               \
        _Pragma("unroll")                                                               \
        for (int ks = 0; ks < 2; ks++) {                                                \
            uint32_t a[2][4], b[4][4];                                                  \
            ldsm4(a[0], Xb_ + (wm * 32) * BP + ks * 16 + loA40);                        \
            ldsm4(a[1], Xb_ + (wm * 32 + 16) * BP + ks * 16 + loA40);                   \
            _Pragma("unroll")                                                           \
            for (int fnp = 0; fnp < 4; fnp++)                                           \
                ldsm4(b[fnp], Wb_ + (wn * 64 + fnp * 16) * BP + ks * 16 + loB40);       \
            _Pragma("unroll")                                                           \
            for (int fm = 0; fm < 2; fm++)                                              \
                _Pragma("unroll")                                                       \
                for (int fnp = 0; fnp < 4; fnp++) {                                     \
                    MMAOP(acc[fm][2 * fnp],     a[fm], b[fnp][0], b[fnp][1]);           \
                    MMAOP(acc[fm][2 * fnp + 1], a[fm], b[fnp][2], b[fnp][3]);           \
                }                                                                       \
        }                                                                               \
    }

    GLOAD(0, 0);
    GLOAD(1, 1);
    if (!VM) { MAINLOOP(mma16); }
    else     { MAINLOOP(mma16f); }
#undef MAINLOOP
#undef GLOAD

    const int b_ = m0 >> 10, s0 = m0 & 1023;
    if (!VM) {
        __nv_bfloat16* Y = (t == 0) ? g_Qb : g_Kb;
        const float sc = (t == 0) ? QSCALE : 1.0f;
        const int head = hp * 2 + wn;
        const float* bh_ = bias + head * 64;
#pragma unroll
        for (int fm = 0; fm < 2; fm++) {
#pragma unroll
            for (int fn = 0; fn < 8; fn++) {
                int col = fn * 8 + 2 * tg;
                float b0 = bh_[col], b1 = bh_[col + 1];
                int r0 = m0 + wm * 32 + fm * 16 + g, r1 = r0 + 8;
                uint32_t v0 = pack_bf2(fmaxf(acc[fm][fn][0] + b0, 0.f) * sc,
                                       fmaxf(acc[fm][fn][1] + b1, 0.f) * sc);
                uint32_t v1 = pack_bf2(fmaxf(acc[fm][fn][2] + b0, 0.f) * sc,
                                       fmaxf(acc[fm][fn][3] + b1, 0.f) * sc);
                {
                    int bb = r0 >> 10, s = r0 & 1023;
                    *(uint32_t*)((uint16_t*)Y + (((size_t)(bb * Hh + head)) * Ss + s) * DKk + col) = v0;
                }
                {
                    int bb = r1 >> 10, s = r1 & 1023;
                    *(uint32_t*)((uint16_t*)Y + (((size_t)(bb * Hh + head)) * Ss + s) * DKk + col) = v1;
                }
            }
        }
    } else {
        // ---- fused pass-2: V' = V @ Wo^T per head (fp16 mma) -----------------
        __syncthreads();
        uint16_t* Vt  = sb;                  // [128][136] fp16 (34816 B)
        uint16_t* WoS = sb + 128 * 136;      // [64][72]   fp16 ( 9216 B)

#pragma unroll
        for (int fm = 0; fm < 2; fm++) {
#pragma unroll
            for (int fn = 0; fn < 8; fn++) {
                int col = wn * 64 + fn * 8 + 2 * tg;
                float b0 = bias[hp * 128 + col], b1 = bias[hp * 128 + col + 1];
                int lr0 = wm * 32 + fm * 16 + g, lr1 = lr0 + 8;
                *(uint32_t*)(Vt + lr0 * 136 + col) = pack_hf2(fmaxf(acc[fm][fn][0] + b0, 0.f),
                                                              fmaxf(acc[fm][fn][1] + b1, 0.f));
                *(uint32_t*)(Vt + lr1 * 136 + col) = pack_hf2(fmaxf(acc[fm][fn][2] + b0, 0.f),
                                                              fmaxf(acc[fm][fn][3] + b1, 0.f));
            }
        }
#pragma unroll
        for (int j = 0; j < 4; j++) {
            int idx = tid + j * 256; int r = idx >> 4, c = (idx & 15) * 4;
            float4 wv = *(const float4*)(Wo + r * 64 + c);
            *(uint32_t*)(WoS + r * 72 + c)     = pack_hf2(wv.x, wv.y);
            *(uint32_t*)(WoS + r * 72 + c + 2) = pack_hf2(wv.z, wv.w);
        }
        __syncthreads();

        const int loA136 = ((lane & 7) + ((lane >> 3) & 1) * 8) * 136 + ((lane >> 4) & 1) * 8;
        const int loB72  = ((lane & 7) + ((lane >> 4) & 1) * 8) * 72 + ((lane >> 3) & 1) * 8;

#pragma unroll
        for (int j = 0; j < 2; j++) {
            const int head = hp * 2 + j, bh = b_ * Hh + head;
            float acc2[2][4][4] = {};
#pragma unroll
            for (int ks = 0; ks < 4; ks++) {
                uint32_t a[2][4], bfr[2][4];
                ldsm4(a[0], Vt + (wm * 32) * 136 + j * 64 + ks * 16 + loA136);
                ldsm4(a[1], Vt + (wm * 32 + 16) * 136 + j * 64 + ks * 16 + loA136);
                ldsm4(bfr[0], WoS + (wn * 32) * 72 + ks * 16 + loB72);
                ldsm4(bfr[1], WoS + (wn * 32 + 16) * 72 + ks * 16 + loB72);
#pragma unroll
                for (int fm = 0; fm < 2; fm++) {
                    mma16f(acc2[fm][0], a[fm], bfr[0][0], bfr[0][1]);
                    mma16f(acc2[fm][1], a[fm], bfr[0][2], bfr[0][3]);
                    mma16f(acc2[fm][2], a[fm], bfr[1][0], bfr[1][1]);
                    mma16f(acc2[fm][3], a[fm], bfr[1][2], bfr[1][3]);
                }
            }
            uint16_t* dst = (uint16_t*)g_Vp + ((size_t)bh * Ss + s0) * DKk;
#pragma unroll
            for (int fm = 0; fm < 2; fm++) {
#pragma unroll
                for (int fn = 0; fn < 4; fn++) {
                    int col = wn * 32 + fn * 8 + 2 * tg;
                    int lr0 = wm * 32 + fm * 16 + g, lr1 = lr0 + 8;
                    *(uint32_t*)(dst + (size_t)lr0 * DKk + col) =
                        pack_hf2(acc2[fm][fn][0], acc2[fm][fn][1]);
                    *(uint32_t*)(dst + (size_t)lr1 * DKk + col) =
                        pack_hf2(acc2[fm][fn][2], acc2[fm][fn][3]);
                }
            }
        }
    }
}

// ---------------------------------------------------------------------------
// Flash attention v4 (unchanged from round 11, passing): fixed-max exp2
// softmax, register-resident P, 4-slot K/V ring (wait_group 2), 2 CTAs/SM.
// ---------------------------------------------------------------------------
#define KP 72
__global__ __launch_bounds__(256, 2) void attn_tc(const int* __restrict__ mask,
                                                  const float* __restrict__ bo,
                                                  float* __restrict__ out) {
    extern __shared__ char smraw[];
    uint16_t* Kb = (uint16_t*)smraw;                   // [4][64][72]  36864 B
    uint16_t* Vb = (uint16_t*)(smraw + 36864);         // [4][64][72]  36864 B
    uint16_t* Qs = (uint16_t*)(smraw + 73728);         // [128][72]    18432 B
    int* ms = (int*)(smraw + 92160);                   // [4][64]       1024 B

    int bh = blockIdx.y, q0 = blockIdx.x * 128;
    const uint16_t* Qg = (const uint16_t*)g_Qb + ((size_t)bh * Ss + q0) * DKk;
    const uint16_t* Kg = (const uint16_t*)g_Kb + (size_t)bh * Ss * DKk;
    const uint16_t* Vg = (const uint16_t*)g_Vp + (size_t)bh * Ss * DKk;

    int tid = threadIdx.x, w = tid >> 5, lane = tid & 31, g = lane >> 2, tg = lane & 3;
    const int loA72 = ((lane & 7) + ((lane >> 3) & 1) * 8) * KP + ((lane >> 4) & 1) * 8;
    const int loB72 = ((lane & 7) + ((lane >> 4) & 1) * 8) * KP + ((lane >> 3) & 1) * 8;
    const int loBT72 = ((lane & 7) + ((lane >> 3) & 1) * 8) * KP + ((lane >> 4) & 1) * 8;

#pragma unroll
    for (int j = 0; j < 4; j++) {
        int idx = tid + j * 256; int r = idx >> 3, c = (idx & 7) * 8;
        *(uint4*)(Qs + r * KP + c) = *(const uint4*)(Qg + (size_t)r * DKk + c);
    }
    __syncthreads();
    uint32_t qa[4][4];
#pragma unroll
    for (int ks = 0; ks < 4; ks++)
        ldsm4(qa[ks], Qs + w * 16 * KP + ks * 16 + loA72);

#define AFILL(KT, BUF)                                                                  \
    do {                                                                                \
        const uint16_t* kg = Kg + (size_t)(KT) * 64 * DKk;                              \
        const uint16_t* vg = Vg + (size_t)(KT) * 64 * DKk;                              \
        _Pragma("unroll")                                                               \
        for (int j = 0; j < 2; j++) {                                                   \
            int idx = tid + j * 256; int r = idx >> 3, c = (idx & 7) * 8;               \
            cp16(Kb + ((BUF) * 64 + r) * KP + c, kg + (size_t)r * DKk + c);             \
            cp16(Vb + ((BUF) * 64 + r) * KP + c, vg + (size_t)r * DKk + c);             \
        }                                                                               \
        if (tid < 16)                                                                   \
            cp16(ms + (BUF) * 64 + tid * 4, mask + (size_t)bh * Ss + (KT) * 64 + tid * 4); \
        asm volatile("cp.async.commit_group;");                                        \
    } while (0)

    float oacc[8][4] = {};
    float sumA = 0.f, sumB = 0.f;

    AFILL(0, 0);
    AFILL(1, 1);
    AFILL(2, 2);
    for (int kt = 0; kt < 16; kt++) {
        int buf = kt & 3;
        asm volatile("cp.async.wait_group 2;");
        __syncthreads();
        if (kt + 3 < 16) AFILL(kt + 3, (kt + 3) & 3);
        else asm volatile("cp.async.commit_group;");

        const uint16_t* Kt = Kb + buf * 64 * KP;
        const uint16_t* Vt = Vb + buf * 64 * KP;
        const int* mt = ms + buf * 64;

        float sacc[8][4] = {};
#pragma unroll
        for (int ks = 0; ks < 4; ks++) {
#pragma unroll
            for (int fnp = 0; fnp < 4; fnp++) {
                uint32_t b[4];
                ldsm4(b, Kt + fnp * 16 * KP + ks * 16 + loB72);
                mma16(sacc[2 * fnp],     qa[ks], b[0], b[1]);
                mma16(sacc[2 * fnp + 1], qa[ks], b[2], b[3]);
            }
        }
#pragma unroll
        for (int fn = 0; fn < 8; fn++) {
            int c0 = fn * 8 + 2 * tg;
            bool k0m = (mt[c0] == 0), k1m = (mt[c0 + 1] == 0);
            sacc[fn][0] = k0m ? 0.f : ex2f(sacc[fn][0]);
            sacc[fn][1] = k1m ? 0.f : ex2f(sacc[fn][1]);
            sacc[fn][2] = k0m ? 0.f : ex2f(sacc[fn][2]);
            sacc[fn][3] = k1m ? 0.f : ex2f(sacc[fn][3]);
            sumA += sacc[fn][0] + sacc[fn][1];
            sumB += sacc[fn][2] + sacc[fn][3];
        }
#pragma unroll
        for (int ks = 0; ks < 4; ks++) {
            uint32_t pa[4];
            pa[0] = pack_hf2(sacc[2 * ks][0],     sacc[2 * ks][1]);
            pa[1] = pack_hf2(sacc[2 * ks][2],     sacc[2 * ks][3]);
            pa[2] = pack_hf2(sacc[2 * ks + 1][0], sacc[2 * ks + 1][1]);
            pa[3] = pack_hf2(sacc[2 * ks + 1][2], sacc[2 * ks + 1][3]);
#pragma unroll
            for (int fnp = 0; fnp < 4; fnp++) {
                uint32_t b[4];
                ldsm4t(b, Vt + (ks * 16) * KP + fnp * 16 + loBT72);
                mma16f(oacc[2 * fnp],     pa, b[0], b[1]);
                mma16f(oacc[2 * fnp + 1], pa, b[2], b[3]);
            }
        }
    }
#undef AFILL

    sumA += __shfl_xor_sync(~0u, sumA, 1); sumA += __shfl_xor_sync(~0u, sumA, 2);
    sumB += __shfl_xor_sync(~0u, sumB, 1); sumB += __shfl_xor_sync(~0u, sumB, 2);
    float invA = 1.f / sumA, invB = 1.f / sumB;
    int b_ = bh >> 4, h = bh & 15;
#pragma unroll
    for (int fn = 0; fn < 8; fn++) {
        int col = fn * 8 + 2 * tg;
        float b0v = bo[col], b1v = bo[col + 1];
        int r0 = q0 + w * 16 + g, r1 = r0 + 8;
        *(float2*)(out + ((size_t)(b_ * Ss + r0)) * Dd + h * 64 + col) =
            make_float2(oacc[fn][0] * invA + b0v, oacc[fn][1] * invA + b1v);
        *(float2*)(out + ((size_t)(b_ * Ss + r1)) * Dd + h * 64 + col) =
            make_float2(oacc[fn][2] * invB + b0v, oacc[fn][3] * invB + b1v);
    }
}

// ---------------------------------------------------------------------------
extern "C" void kernel_launch(void* const* d_in, const int* in_sizes, int n_in,
                              void* d_out, int out_size) {
    const float* q   = (const float*)d_in[0];
    const float* k   = (const float*)d_in[1];
    const float* v   = (const float*)d_in[2];
    const int*   msk = (const int*)d_in[3];
    const float* Wq  = (const float*)d_in[4];
    const float* bq  = (const float*)d_in[5];
    const float* Wk  = (const float*)d_in[6];
    const float* bk  = (const float*)d_in[7];
    const float* Wv  = (const float*)d_in[8];
    const float* bv  = (const float*)d_in[9];
    const float* Wqf = (const float*)d_in[10];
    const float* bqf = (const float*)d_in[11];
    const float* Wkf = (const float*)d_in[12];
    const float* bkf = (const float*)d_in[13];
    const float* Wvf = (const float*)d_in[14];
    const float* bvf = (const float*)d_in[15];
    const float* Wo  = (const float*)d_in[16];
    const float* bo  = (const float*)d_in[17];
    float* out = (float*)d_out;

    const int proj_smem = 3 * 2 * 128 * BP * 2;  // 61440
    const int attn_smem = 93184;

    static int cfg = 0;
    if (!cfg) {
        cudaFuncSetAttribute(proj_all, cudaFuncAttributeMaxDynamicSharedMemorySize, proj_smem);
        cudaFuncSetAttribute(attn_tc, cudaFuncAttributeMaxDynamicSharedMemorySize, attn_smem);
        cfg = 1;
    }

    prologue<<<2819, 256>>>(q, k, v, Wq, Wqf, Wk, Wkf, Wv, Wvf,
                            bq, bqf, bk, bkf, bv, bvf);
    proj_all<<<dim3(8, 32, 3), 256, proj_smem>>>(Wo);
    attn_tc<<<dim3(8, 64), 256, attn_smem>>>(msk, bo, out);
}

// round 13
// speedup vs baseline: 5.6867x; 1.0061x over previous
#include <cuda_runtime.h>
#include <cuda_bf16.h>
#include <cuda_fp16.h>
#include <math.h>
#include <stdint.h>

#define Bb 4
#define Ss 1024
#define Dd 1024
#define Hh 16
#define DKk 64

#define QSCALE 0.18033688011112042f
#define MASKVAL -14426.950408889634f

// ---------------------------------------------------------------------------
// Device scratch
// ---------------------------------------------------------------------------
__device__ __nv_bfloat16 g_Xb[2][4096 * 1024];   // bf16 q,k inputs
__device__ __half        g_Xf[4096 * 1024];      // fp16 v input
__device__ __nv_bfloat16 g_Wcb[2][1024 * 1024];  // folded Wq,Wk (bf16)
__device__ __half        g_Wcf[1024 * 1024];     // folded Wv (fp16)
__device__ float         g_bc[3][1024];          // folded biases
__device__ __nv_bfloat16 g_Qb[64 * 1024 * 64];   // per-head Q (bf16, pre-scaled)
__device__ __nv_bfloat16 g_Kb[64 * 1024 * 64];   // per-head K (bf16)
__device__ __half        g_Vp[64 * 1024 * 64];   // V' = V @ Wo^T (fp16) [bh][s][d]

// ---------------------------------------------------------------------------
// helpers
// ---------------------------------------------------------------------------
__device__ __forceinline__ void mma16(float (&d)[4], const uint32_t (&a)[4],
                                      uint32_t b0, uint32_t b1) {
    asm volatile(
        "mma.sync.aligned.m16n8k16.row.col.f32.bf16.bf16.f32 "
        "{%0,%1,%2,%3},{%4,%5,%6,%7},{%8,%9},{%0,%1,%2,%3};"
        : "+f"(d[0]), "+f"(d[1]), "+f"(d[2]), "+f"(d[3])
        : "r"(a[0]), "r"(a[1]), "r"(a[2]), "r"(a[3]), "r"(b0), "r"(b1));
}
__device__ __forceinline__ void mma16f(float (&d)[4], const uint32_t (&a)[4],
                                       uint32_t b0, uint32_t b1) {
    asm volatile(
        "mma.sync.aligned.m16n8k16.row.col.f32.f16.f16.f32 "
        "{%0,%1,%2,%3},{%4,%5,%6,%7},{%8,%9},{%0,%1,%2,%3};"
        : "+f"(d[0]), "+f"(d[1]), "+f"(d[2]), "+f"(d[3])
        : "r"(a[0]), "r"(a[1]), "r"(a[2]), "r"(a[3]), "r"(b0), "r"(b1));
}
__device__ __forceinline__ void ldsm4(uint32_t (&r)[4], const uint16_t* p) {
    uint32_t a = (uint32_t)__cvta_generic_to_shared(p);
    asm volatile("ldmatrix.sync.aligned.m8n8.x4.shared.b16 {%0,%1,%2,%3},[%4];"
                 : "=r"(r[0]), "=r"(r[1]), "=r"(r[2]), "=r"(r[3]) : "r"(a));
}
__device__ __forceinline__ void ldsm4t(uint32_t (&r)[4], const uint16_t* p) {
    uint32_t a = (uint32_t)__cvta_generic_to_shared(p);
    asm volatile("ldmatrix.sync.aligned.m8n8.x4.trans.shared.b16 {%0,%1,%2,%3},[%4];"
                 : "=r"(r[0]), "=r"(r[1]), "=r"(r[2]), "=r"(r[3]) : "r"(a));
}
__device__ __forceinline__ void cp16(void* s, const void* g) {
    uint32_t sa = (uint32_t)__cvta_generic_to_shared(s);
    asm volatile("cp.async.cg.shared.global [%0], [%1], 16;" :: "r"(sa), "l"(g));
}
__device__ __forceinline__ uint32_t pack_bf2(float a, float b) {
    __nv_bfloat162 t = __float22bfloat162_rn(make_float2(a, b));
    return *reinterpret_cast<uint32_t*>(&t);
}
__device__ __forceinline__ uint32_t pack_hf2(float a, float b) {
    __half2 t = __floats2half2_rn(a, b);
    return *reinterpret_cast<uint32_t*>(&t);
}
__device__ __forceinline__ float ex2f(float x) {
    float y; asm("ex2.approx.f32 %0,%1;" : "=f"(y) : "f"(x)); return y;
}

// ---------------------------------------------------------------------------
// Merged prologue, longest-job-first ordering:
//   blocks [0, 768)     : fold      (long CTAs, start at t=0)
//   blocks [768, 2816)  : preround  (short streaming CTAs backfill)
//   blocks [2816, 2819) : bfold
// ---------------------------------------------------------------------------
__global__ __launch_bounds__(256) void prologue(
    const float* __restrict__ q, const float* __restrict__ k, const float* __restrict__ v,
    const float* __restrict__ Wq, const float* __restrict__ Wqf,
    const float* __restrict__ Wk, const float* __restrict__ Wkf,
    const float* __restrict__ Wv, const float* __restrict__ Wvf,
    const float* __restrict__ bq, const float* __restrict__ bqf,
    const float* __restrict__ bk, const float* __restrict__ bkf,
    const float* __restrict__ bv, const float* __restrict__ bvf) {
    int bid = blockIdx.x;
    int tid = threadIdx.x;

    if (bid < 768) {
        // ---- fold (long CTAs first) ------------------------------------------
        int t = bid >> 8, h = (bid >> 4) & 15, j0 = (bid & 15) * 64;
        const float* Wbig = (t == 0) ? Wq : (t == 1) ? Wk : Wv;
        const float* Wf   = (t == 0) ? Wqf : (t == 1) ? Wkf : Wvf;

        __shared__ float fs[64][65];
        __shared__ float bs[64][65];

        for (int idx = tid; idx < 64 * 16; idx += 256) {
            int r = idx >> 4, c4 = (idx & 15) * 4;
            float4 fv = *(const float4*)(Wf + r * 64 + c4);
            fs[r][c4] = fv.x; fs[r][c4 + 1] = fv.y; fs[r][c4 + 2] = fv.z; fs[r][c4 + 3] = fv.w;
            float4 bv2 = *(const float4*)(Wbig + (h * 64 + r) * Dd + j0 + c4);
            bs[r][c4] = bv2.x; bs[r][c4 + 1] = bv2.y; bs[r][c4 + 2] = bv2.z; bs[r][c4 + 3] = bv2.w;
        }
        __syncthreads();

        int ty = tid >> 4, tx = tid & 15;
        float acc[4][4] = {};
#pragma unroll 8
        for (int i = 0; i < 64; i++) {
            float a[4], b[4];
#pragma unroll
            for (int u = 0; u < 4; u++) { a[u] = fs[ty * 4 + u][i]; b[u] = bs[i][tx * 4 + u]; }
#pragma unroll
            for (int u = 0; u < 4; u++)
#pragma unroll
                for (int w = 0; w < 4; w++) acc[u][w] += a[u] * b[w];
        }
        if (t < 2) {
            uint32_t* dst = (uint32_t*)g_Wcb[t];
#pragma unroll
            for (int u = 0; u < 4; u++) {
                size_t row = (size_t)(h * 64 + ty * 4 + u) * Dd + j0 + tx * 4;
                dst[row / 2]     = pack_bf2(acc[u][0], acc[u][1]);
                dst[row / 2 + 1] = pack_bf2(acc[u][2], acc[u][3]);
            }
        } else {
            uint32_t* dst = (uint32_t*)g_Wcf;
#pragma unroll
            for (int u = 0; u < 4; u++) {
                size_t row = (size_t)(h * 64 + ty * 4 + u) * Dd + j0 + tx * 4;
                dst[row / 2]     = pack_hf2(acc[u][0], acc[u][1]);
                dst[row / 2 + 1] = pack_hf2(acc[u][2], acc[u][3]);
            }
        }
        return;
    }
    if (bid < 2816) {
        // ---- preround: 2 consecutive float4 per tensor per thread ------------
        size_t i = ((size_t)(bid - 768) * 256 + tid) * 2;  // float4 index (even)
        {
            float4 a0 = ((const float4*)q)[i], a1 = ((const float4*)q)[i + 1];
            uint4 o = {pack_bf2(a0.x, a0.y), pack_bf2(a0.z, a0.w),
                       pack_bf2(a1.x, a1.y), pack_bf2(a1.z, a1.w)};
            ((uint4*)g_Xb[0])[i / 2] = o;
        }
        {
            float4 a0 = ((const float4*)k)[i], a1 = ((const float4*)k)[i + 1];
            uint4 o = {pack_bf2(a0.x, a0.y), pack_bf2(a0.z, a0.w),
                       pack_bf2(a1.x, a1.y), pack_bf2(a1.z, a1.w)};
            ((uint4*)g_Xb[1])[i / 2] = o;
        }
        {
            float4 a0 = ((const float4*)v)[i], a1 = ((const float4*)v)[i + 1];
            uint4 o = {pack_hf2(a0.x, a0.y), pack_hf2(a0.z, a0.w),
                       pack_hf2(a1.x, a1.y), pack_hf2(a1.z, a1.w)};
            ((uint4*)g_Xf)[i / 2] = o;
        }
        return;
    }
    // ---- bfold (3 blocks, 4 outputs/thread) ---------------------------------
    {
        int t = bid - 2816;
        const float* b1 = (t == 0) ? bq : (t == 1) ? bk : bv;
        const float* b2 = (t == 0) ? bqf : (t == 1) ? bkf : bvf;
        const float* Wf = (t == 0) ? Wqf : (t == 1) ? Wkf : Wvf;
#pragma unroll
        for (int kk = 0; kk < 4; kk++) {
            int n = tid + kk * 256;
            int h = n >> 6, o = n & 63;
            float s = b2[o];
            for (int i = 0; i < 64; i++) s += Wf[o * 64 + i] * b1[h * 64 + i];
            g_bc[t][n] = s;
        }
    }
}

// ---------------------------------------------------------------------------
// Unified projection GEMM (flat 1-D grid, V-tensor CTAs FIRST; 2 CTAs/SM).
//   blocks [0, 256)   : t=2 (V + fused V' pass-2, longest CTAs)
//   blocks [256, 512) : t=0 (Q)
//   blocks [512, 768) : t=1 (K)
// ---------------------------------------------------------------------------
#define BP 40
__global__ __launch_bounds__(256, 2) void proj_all(const float* __restrict__ Wo) {
    extern __shared__ uint16_t sb[];

    int bid = blockIdx.x;
    const int t = (bid < 256) ? 2 : ((bid < 512) ? 0 : 1);
    const int r = (bid < 256) ? bid : ((bid < 512) ? bid - 256 : bid - 512);
    const int hp = r & 7;
    const int m0 = (r >> 3) * 128;

    const bool VM = (t == 2);
    const uint16_t* X = VM ? (const uint16_t*)g_Xf : (const uint16_t*)g_Xb[t];
    const uint16_t* W = VM ? (const uint16_t*)g_Wcf : (const uint16_t*)g_Wcb[t];
    const float* bias = g_bc[t];

    const int tid = threadIdx.x;
    const int w = tid >> 5, lane = tid & 31, g = lane >> 2, tg = lane & 3;
    const int wm = w & 3, wn = w >> 2;

    const int loA40 = ((lane & 7) + ((lane >> 3) & 1) * 8) * BP + ((lane >> 4) & 1) * 8;
    const int loB40 = ((lane & 7) + ((lane >> 4) & 1) * 8) * BP + ((lane >> 3) & 1) * 8;

    float acc[2][8][4] = {};

#define GLOAD(I, S)                                                                     \
    do {                                                                                \
        uint16_t* Xd = sb + (S) * 10240;                                                \
        uint16_t* Wd = Xd + 5120;                                                       \
        int k0_ = (I) * 32;                                                             \
        _Pragma("unroll")                                                               \
        for (int j = 0; j < 2; j++) {                                                   \
            int idx = tid + j * 256; int rr = idx >> 2, c = (idx & 3) * 8;              \
            cp16(Xd + rr * BP + c, X + (size_t)(m0 + rr) * Dd + k0_ + c);               \
        }                                                                               \
        _Pragma("unroll")                                                               \
        for (int j = 0; j < 2; j++) {                                                   \
            int idx = tid + j * 256; int rr = idx >> 2, c = (idx & 3) * 8;              \
            cp16(Wd + rr * BP + c, W + (size_t)(hp * 128 + rr) * Dd + k0_ + c);         \
        }                                                                               \
        asm volatile("cp.async.commit_group;");                                        \
    } while (0)

#define MAINLOOP(MMAOP)                                                                 \
    for (int i = 0; i < 32; i++) {                                                      \
        asm volatile("cp.async.wait_group 1;");                                         \
        __syncthreads();                                                                \
        if (i + 2 < 32) GLOAD(i + 2, (i + 2) % 3);                                      \
        else asm volatile("cp.async.commit_group;");                                    \
        const uint16_t* Xb_ = sb + (i % 3) * 10240;                                     \
        const uint16_t* Wb_ = Xb_ + 5120;                                               \
        _Pragma("unroll")                                                               \
        for (int ks = 0; ks < 2; ks++) {                                                \
            uint32_t a[2][4], b[4][4];                                                  \
            ldsm4(a[0], Xb_ + (wm * 32) * BP + ks * 16 + loA40);                        \
            ldsm4(a[1], Xb_ + (wm * 32 + 16) * BP + ks * 16 + loA40);                   \
            _Pragma("unroll")                                                           \
            for (int fnp = 0; fnp < 4; fnp++)                                           \
                ldsm4(b[fnp], Wb_ + (wn * 64 + fnp * 16) * BP + ks * 16 + loB40);       \
            _Pragma("unroll")                                                           \
            for (int fm = 0; fm < 2; fm++)                                              \
                _Pragma("unroll")                                                       \
                for (int fnp = 0; fnp < 4; fnp++) {                                     \
                    MMAOP(acc[fm][2 * fnp],     a[fm], b[fnp][0], b[fnp][1]);           \
                    MMAOP(acc[fm][2 * fnp + 1], a[fm], b[fnp][2], b[fnp][3]);           \
                }                                                                       \
        }                                                                               \
    }

    GLOAD(0, 0);
    GLOAD(1, 1);
    if (!VM) { MAINLOOP(mma16); }
    else     { MAINLOOP(mma16f); }
#undef MAINLOOP
#undef GLOAD

    const int b_ = m0 >> 10, s0 = m0 & 1023;
    if (!VM) {
        __nv_bfloat16* Y = (t == 0) ? g_Qb : g_Kb;
        const float sc = (t == 0) ? QSCALE : 1.0f;
        const int head = hp * 2 + wn;
        const float* bh_ = bias + head * 64;
#pragma unroll
        for (int fm = 0; fm < 2; fm++) {
#pragma unroll
            for (int fn = 0; fn < 8; fn++) {
                int col = fn * 8 + 2 * tg;
                float b0 = bh_[col], b1 = bh_[col + 1];
                int r0 = m0 + wm * 32 + fm * 16 + g, r1 = r0 + 8;
                uint32_t v0 = pack_bf2(fmaxf(acc[fm][fn][0] + b0, 0.f) * sc,
                                       fmaxf(acc[fm][fn][1] + b1, 0.f) * sc);
                uint32_t v1 = pack_bf2(fmaxf(acc[fm][fn][2] + b0, 0.f) * sc,
                                       fmaxf(acc[fm][fn][3] + b1, 0.f) * sc);
                {
                    int bb = r0 >> 10, s = r0 & 1023;
                    *(uint32_t*)((uint16_t*)Y + (((size_t)(bb * Hh + head)) * Ss + s) * DKk + col) = v0;
                }
                {
                    int bb = r1 >> 10, s = r1 & 1023;
                    *(uint32_t*)((uint16_t*)Y + (((size_t)(bb * Hh + head)) * Ss + s) * DKk + col) = v1;
                }
            }
        }
    } else {
        // ---- fused pass-2: V' = V @ Wo^T per head (fp16 mma) -----------------
        __syncthreads();
        uint16_t* Vt  = sb;                  // [128][136] fp16 (34816 B)
        uint16_t* WoS = sb + 128 * 136;      // [64][72]   fp16 ( 9216 B)

#pragma unroll
        for (int fm = 0; fm < 2; fm++) {
#pragma unroll
            for (int fn = 0; fn < 8; fn++) {
                int col = wn * 64 + fn * 8 + 2 * tg;
                float b0 = bias[hp * 128 + col], b1 = bias[hp * 128 + col + 1];
                int lr0 = wm * 32 + fm * 16 + g, lr1 = lr0 + 8;
                *(uint32_t*)(Vt + lr0 * 136 + col) = pack_hf2(fmaxf(acc[fm][fn][0] + b0, 0.f),
                                                              fmaxf(acc[fm][fn][1] + b1, 0.f));
                *(uint32_t*)(Vt + lr1 * 136 + col) = pack_hf2(fmaxf(acc[fm][fn][2] + b0, 0.f),
                                                              fmaxf(acc[fm][fn][3] + b1, 0.f));
            }
        }
#pragma unroll
        for (int j = 0; j < 4; j++) {
            int idx = tid + j * 256; int rr = idx >> 4, c = (idx & 15) * 4;
            float4 wv = *(const float4*)(Wo + rr * 64 + c);
            *(uint32_t*)(WoS + rr * 72 + c)     = pack_hf2(wv.x, wv.y);
            *(uint32_t*)(WoS + rr * 72 + c + 2) = pack_hf2(wv.z, wv.w);
        }
        __syncthreads();

        const int loA136 = ((lane & 7) + ((lane >> 3) & 1) * 8) * 136 + ((lane >> 4) & 1) * 8;
        const int loB72  = ((lane & 7) + ((lane >> 4) & 1) * 8) * 72 + ((lane >> 3) & 1) * 8;

#pragma unroll
        for (int j = 0; j < 2; j++) {
            const int head = hp * 2 + j, bh = b_ * Hh + head;
            float acc2[2][4][4] = {};
#pragma unroll
            for (int ks = 0; ks < 4; ks++) {
                uint32_t a[2][4], bfr[2][4];
                ldsm4(a[0], Vt + (wm * 32) * 136 + j * 64 + ks * 16 + loA136);
                ldsm4(a[1], Vt + (wm * 32 + 16) * 136 + j * 64 + ks * 16 + loA136);
                ldsm4(bfr[0], WoS + (wn * 32) * 72 + ks * 16 + loB72);
                ldsm4(bfr[1], WoS + (wn * 32 + 16) * 72 + ks * 16 + loB72);
#pragma unroll
                for (int fm = 0; fm < 2; fm++) {
                    mma16f(acc2[fm][0], a[fm], bfr[0][0], bfr[0][1]);
                    mma16f(acc2[fm][1], a[fm], bfr[0][2], bfr[0][3]);
                    mma16f(acc2[fm][2], a[fm], bfr[1][0], bfr[1][1]);
                    mma16f(acc2[fm][3], a[fm], bfr[1][2], bfr[1][3]);
                }
            }
            uint16_t* dst = (uint16_t*)g_Vp + ((size_t)bh * Ss + s0) * DKk;
#pragma unroll
            for (int fm = 0; fm < 2; fm++) {
#pragma unroll
                for (int fn = 0; fn < 4; fn++) {
                    int col = wn * 32 + fn * 8 + 2 * tg;
                    int lr0 = wm * 32 + fm * 16 + g, lr1 = lr0 + 8;
                    *(uint32_t*)(dst + (size_t)lr0 * DKk + col) =
                        pack_hf2(acc2[fm][fn][0], acc2[fm][fn][1]);
                    *(uint32_t*)(dst + (size_t)lr1 * DKk + col) =
                        pack_hf2(acc2[fm][fn][2], acc2[fm][fn][3]);
                }
            }
        }
    }
}

// ---------------------------------------------------------------------------
// Flash attention v4 (unchanged, passing; at mma.sync floor): fixed-max exp2
// softmax, register-resident P, 4-slot K/V ring (wait_group 2), 2 CTAs/SM.
// ---------------------------------------------------------------------------
#define KP 72
__global__ __launch_bounds__(256, 2) void attn_tc(const int* __restrict__ mask,
                                                  const float* __restrict__ bo,
                                                  float* __restrict__ out) {
    extern __shared__ char smraw[];
    uint16_t* Kb = (uint16_t*)smraw;                   // [4][64][72]  36864 B
    uint16_t* Vb = (uint16_t*)(smraw + 36864);         // [4][64][72]  36864 B
    uint16_t* Qs = (uint16_t*)(smraw + 73728);         // [128][72]    18432 B
    int* ms = (int*)(smraw + 92160);                   // [4][64]       1024 B

    int bh = blockIdx.y, q0 = blockIdx.x * 128;
    const uint16_t* Qg = (const uint16_t*)g_Qb + ((size_t)bh * Ss + q0) * DKk;
    const uint16_t* Kg = (const uint16_t*)g_Kb + (size_t)bh * Ss * DKk;
    const uint16_t* Vg = (const uint16_t*)g_Vp + (size_t)bh * Ss * DKk;

    int tid = threadIdx.x, w = tid >> 5, lane = tid & 31, g = lane >> 2, tg = lane & 3;
    const int loA72 = ((lane & 7) + ((lane >> 3) & 1) * 8) * KP + ((lane >> 4) & 1) * 8;
    const int loB72 = ((lane & 7) + ((lane >> 4) & 1) * 8) * KP + ((lane >> 3) & 1) * 8;
    const int loBT72 = ((lane & 7) + ((lane >> 3) & 1) * 8) * KP + ((lane >> 4) & 1) * 8;

#pragma unroll
    for (int j = 0; j < 4; j++) {
        int idx = tid + j * 256; int r = idx >> 3, c = (idx & 7) * 8;
        *(uint4*)(Qs + r * KP + c) = *(const uint4*)(Qg + (size_t)r * DKk + c);
    }
    __syncthreads();
    uint32_t qa[4][4];
#pragma unroll
    for (int ks = 0; ks < 4; ks++)
        ldsm4(qa[ks], Qs + w * 16 * KP + ks * 16 + loA72);

#define AFILL(KT, BUF)                                                                  \
    do {                                                                                \
        const uint16_t* kg = Kg + (size_t)(KT) * 64 * DKk;                              \
        const uint16_t* vg = Vg + (size_t)(KT) * 64 * DKk;                              \
        _Pragma("unroll")                                                               \
        for (int j = 0; j < 2; j++) {                                                   \
            int idx = tid + j * 256; int r = idx >> 3, c = (idx & 7) * 8;               \
            cp16(Kb + ((BUF) * 64 + r) * KP + c, kg + (size_t)r * DKk + c);             \
            cp16(Vb + ((BUF) * 64 + r) * KP + c, vg + (size_t)r * DKk + c);             \
        }                                                                               \
        if (tid < 16)                                                                   \
            cp16(ms + (BUF) * 64 + tid * 4, mask + (size_t)bh * Ss + (KT) * 64 + tid * 4); \
        asm volatile("cp.async.commit_group;");                                        \
    } while (0)

    float oacc[8][4] = {};
    float sumA = 0.f, sumB = 0.f;

    AFILL(0, 0);
    AFILL(1, 1);
    AFILL(2, 2);
    for (int kt = 0; kt < 16; kt++) {
        int buf = kt & 3;
        asm volatile("cp.async.wait_group 2;");
        __syncthreads();
        if (kt + 3 < 16) AFILL(kt + 3, (kt + 3) & 3);
        else asm volatile("cp.async.commit_group;");

        const uint16_t* Kt = Kb + buf * 64 * KP;
        const uint16_t* Vt = Vb + buf * 64 * KP;
        const int* mt = ms + buf * 64;

        float sacc[8][4] = {};
#pragma unroll
        for (int ks = 0; ks < 4; ks++) {
#pragma unroll
            for (int fnp = 0; fnp < 4; fnp++) {
                uint32_t b[4];
                ldsm4(b, Kt + fnp * 16 * KP + ks * 16 + loB72);
                mma16(sacc[2 * fnp],     qa[ks], b[0], b[1]);
                mma16(sacc[2 * fnp + 1], qa[ks], b[2], b[3]);
            }
        }
#pragma unroll
        for (int fn = 0; fn < 8; fn++) {
            int c0 = fn * 8 + 2 * tg;
            bool k0m = (mt[c0] == 0), k1m = (mt[c0 + 1] == 0);
            sacc[fn][0] = k0m ? 0.f : ex2f(sacc[fn][0]);
            sacc[fn][1] = k1m ? 0.f : ex2f(sacc[fn][1]);
            sacc[fn][2] = k0m ? 0.f : ex2f(sacc[fn][2]);
            sacc[fn][3] = k1m ? 0.f : ex2f(sacc[fn][3]);
            sumA += sacc[fn][0] + sacc[fn][1];
            sumB += sacc[fn][2] + sacc[fn][3];
        }
#pragma unroll
        for (int ks = 0; ks < 4; ks++) {
            uint32_t pa[4];
            pa[0] = pack_hf2(sacc[2 * ks][0],     sacc[2 * ks][1]);
            pa[1] = pack_hf2(sacc[2 * ks][2],     sacc[2 * ks][3]);
            pa[2] = pack_hf2(sacc[2 * ks + 1][0], sacc[2 * ks + 1][1]);
            pa[3] = pack_hf2(sacc[2 * ks + 1][2], sacc[2 * ks + 1][3]);
#pragma unroll
            for (int fnp = 0; fnp < 4; fnp++) {
                uint32_t b[4];
                ldsm4t(b, Vt + (ks * 16) * KP + fnp * 16 + loBT72);
                mma16f(oacc[2 * fnp],     pa, b[0], b[1]);
                mma16f(oacc[2 * fnp + 1], pa, b[2], b[3]);
            }
        }
    }
#undef AFILL

    sumA += __shfl_xor_sync(~0u, sumA, 1); sumA += __shfl_xor_sync(~0u, sumA, 2);
    sumB += __shfl_xor_sync(~0u, sumB, 1); sumB += __shfl_xor_sync(~0u, sumB, 2);
    float invA = 1.f / sumA, invB = 1.f / sumB;
    int b_ = bh >> 4, h = bh & 15;
#pragma unroll
    for (int fn = 0; fn < 8; fn++) {
        int col = fn * 8 + 2 * tg;
        float b0v = bo[col], b1v = bo[col + 1];
        int r0 = q0 + w * 16 + g, r1 = r0 + 8;
        *(float2*)(out + ((size_t)(b_ * Ss + r0)) * Dd + h * 64 + col) =
            make_float2(oacc[fn][0] * invA + b0v, oacc[fn][1] * invA + b1v);
        *(float2*)(out + ((size_t)(b_ * Ss + r1)) * Dd + h * 64 + col) =
            make_float2(oacc[fn][2] * invB + b0v, oacc[fn][3] * invB + b1v);
    }
}

// ---------------------------------------------------------------------------
extern "C" void kernel_launch(void* const* d_in, const int* in_sizes, int n_in,
                              void* d_out, int out_size) {
    const float* q   = (const float*)d_in[0];
    const float* k   = (const float*)d_in[1];
    const float* v   = (const float*)d_in[2];
    const int*   msk = (const int*)d_in[3];
    const float* Wq  = (const float*)d_in[4];
    const float* bq  = (const float*)d_in[5];
    const float* Wk  = (const float*)d_in[6];
    const float* bk  = (const float*)d_in[7];
    const float* Wv  = (const float*)d_in[8];
    const float* bv  = (const float*)d_in[9];
    const float* Wqf = (const float*)d_in[10];
    const float* bqf = (const float*)d_in[11];
    const float* Wkf = (const float*)d_in[12];
    const float* bkf = (const float*)d_in[13];
    const float* Wvf = (const float*)d_in[14];
    const float* bvf = (const float*)d_in[15];
    const float* Wo  = (const float*)d_in[16];
    const float* bo  = (const float*)d_in[17];
    float* out = (float*)d_out;

    const int proj_smem = 3 * 2 * 128 * BP * 2;  // 61440
    const int attn_smem = 93184;

    static int cfg = 0;
    if (!cfg) {
        cudaFuncSetAttribute(proj_all, cudaFuncAttributeMaxDynamicSharedMemorySize, proj_smem);
        cudaFuncSetAttribute(attn_tc, cudaFuncAttributeMaxDynamicSharedMemorySize, attn_smem);
        cfg = 1;
    }

    prologue<<<2819, 256>>>(q, k, v, Wq, Wqf, Wk, Wkf, Wv, Wvf,
                            bq, bqf, bk, bkf, bv, bvf);
    proj_all<<<768, 256, proj_smem>>>(Wo);
    attn_tc<<<dim3(8, 64), 256, attn_smem>>>(msk, bo, out);
}